// round 1
// baseline (speedup 1.0000x reference)
#include <cuda_runtime.h>
#include <math.h>

#define N 6000
#define E 192000
#define H 128
#define NHEADS 4
#define EN (E + N)
#define CATW (H * (NHEADS + 1))   // 640

// ---------------- device scratch (no allocation allowed) ----------------
__device__ int   g_deg[2][N];
__device__ int   g_off[2][N + 1];
__device__ int   g_cnt[2][N];
__device__ int   g_src[2][EN];
__device__ float g_nrm[2][EN];
__device__ float g_dinv[2][N];
__device__ float g_hw[N * H];
__device__ float g_ha[N * H];
__device__ float g_hb[N * H];
__device__ float g_xg[N * H];
__device__ float g_q[NHEADS][N * H];
__device__ float g_k[NHEADS][N * H];
__device__ float g_cat[N * CATW];
__device__ float g_d1[N * H];
__device__ float g_d2[N * H];

// ---------------- graph preprocessing ----------------
__global__ void k_deg_init(int* deg) {
    int i = blockIdx.x * blockDim.x + threadIdx.x;
    if (i < N) deg[i] = 1;                      // self loop
}
__global__ void k_deg_count(const int* __restrict__ col, int* deg) {
    int e = blockIdx.x * blockDim.x + threadIdx.x;
    if (e < E) atomicAdd(&deg[col[e]], 1);
}
__global__ void k_dinv(const int* __restrict__ deg, float* dinv) {
    int i = blockIdx.x * blockDim.x + threadIdx.x;
    if (i < N) dinv[i] = rsqrtf((float)deg[i]);
}
__global__ void k_zero_cnt(int* cnt) {
    int i = blockIdx.x * blockDim.x + threadIdx.x;
    if (i < N) cnt[i] = 0;
}
// single-block exclusive scan of deg[0..N) -> off[0..N]
__global__ void k_scan(const int* __restrict__ deg, int* __restrict__ off) {
    __shared__ int part[1024];
    int tid = threadIdx.x;
    const int C = (N + 1023) / 1024;            // 6
    int base = tid * C;
    int s = 0;
    for (int i = 0; i < C; i++) { int idx = base + i; if (idx < N) s += deg[idx]; }
    part[tid] = s;
    __syncthreads();
    for (int d = 1; d < 1024; d <<= 1) {
        int v = (tid >= d) ? part[tid - d] : 0;
        __syncthreads();
        part[tid] += v;
        __syncthreads();
    }
    int run = (tid == 0) ? 0 : part[tid - 1];
    for (int i = 0; i < C; i++) {
        int idx = base + i;
        if (idx < N) { off[idx] = run; run += deg[idx]; }
    }
    if (tid == 0) off[N] = part[1023];
}
__global__ void k_fill(const int* __restrict__ erow, const int* __restrict__ ecol,
                       const int* __restrict__ off, int* cnt,
                       const float* __restrict__ dinv,
                       int* __restrict__ src, float* __restrict__ nrm) {
    int e = blockIdx.x * blockDim.x + threadIdx.x;
    if (e >= EN) return;
    int r, c;
    if (e < E) { r = erow[e]; c = ecol[e]; }
    else       { r = c = e - E; }               // self loop
    int pos = off[c] + atomicAdd(&cnt[c], 1);
    src[pos] = r;
    nrm[pos] = dinv[r] * dinv[c];
}

// ---------------- GCN kernels ----------------
__global__ void k_gemm_in3(const float* __restrict__ x, const float* __restrict__ W,
                           float* __restrict__ out) {
    int v = blockIdx.x, t = threadIdx.x;
    float x0 = x[v * 3 + 0], x1 = x[v * 3 + 1], x2 = x[v * 3 + 2];
    out[v * H + t] = x0 * W[t] + x1 * W[H + t] + x2 * W[2 * H + t];
}
__global__ void k_aggregate(const float* __restrict__ hw, const int* __restrict__ off,
                            const int* __restrict__ src, const float* __restrict__ nrm,
                            const float* __restrict__ bias, float* __restrict__ out, int ldo) {
    __shared__ int   ssrc[128];
    __shared__ float snrm[128];
    int v = blockIdx.x, t = threadIdx.x;
    int s = off[v], e = off[v + 1];
    float acc = 0.f;
    for (int base = s; base < e; base += 128) {
        int i = base + t;
        if (i < e) { ssrc[t] = src[i]; snrm[t] = nrm[i]; }
        __syncthreads();
        int cnt = min(128, e - base);
        for (int j = 0; j < cnt; j++)
            acc += hw[ssrc[j] * H + t] * snrm[j];
        __syncthreads();
    }
    float r = acc + bias[t];
    out[v * ldo + t] = fmaxf(r, 0.f);
}

// ---------------- generic GEMM: out[n x 128] = A[n x K] @ W[K x 128] (+bias, relu) ----
__global__ __launch_bounds__(256)
void k_gemm(const float* __restrict__ A, int lda,
            const float* __restrict__ W, const float* __restrict__ bias,
            float* __restrict__ out, int ldo, int n, int K, int doRelu) {
    __shared__ float As[64 * 33];
    __shared__ float Ws[32 * 128];
    int tid = threadIdx.x;
    int tx = tid & 15, ty = tid >> 4;
    int r0 = blockIdx.x * 64;
    float acc[4][8];
#pragma unroll
    for (int r = 0; r < 4; r++)
#pragma unroll
        for (int c = 0; c < 8; c++) acc[r][c] = 0.f;

    for (int kc = 0; kc < K; kc += 32) {
        for (int i = tid; i < 32 * 128; i += 256) Ws[i] = W[kc * 128 + i];
        for (int idx = tid; idx < 64 * 32; idx += 256) {
            int i = idx >> 5, k = idx & 31;
            int row = r0 + i;
            As[i * 33 + k] = (row < n) ? A[(long)row * lda + kc + k] : 0.f;
        }
        __syncthreads();
#pragma unroll 8
        for (int k = 0; k < 32; k++) {
            float a[4], w[8];
#pragma unroll
            for (int r = 0; r < 4; r++) a[r] = As[(ty * 4 + r) * 33 + k];
#pragma unroll
            for (int c = 0; c < 8; c++) w[c] = Ws[k * 128 + c * 16 + tx];
#pragma unroll
            for (int r = 0; r < 4; r++)
#pragma unroll
                for (int c = 0; c < 8; c++) acc[r][c] += a[r] * w[c];
        }
        __syncthreads();
    }
#pragma unroll
    for (int r = 0; r < 4; r++) {
        int row = r0 + ty * 4 + r;
        if (row < n) {
#pragma unroll
            for (int c = 0; c < 8; c++) {
                int col = c * 16 + tx;
                float v = acc[r][c] + (bias ? bias[col] : 0.f);
                if (doRelu) v = fmaxf(v, 0.f);
                out[(long)row * ldo + col] = v;
            }
        }
    }
}

// ---------------- flash attention (fp32) ----------------
#define QS_ST 129
#define PS_ST 65
__global__ __launch_bounds__(256)
void k_flash(const float* __restrict__ Qall, const float* __restrict__ Kall,
             const float* __restrict__ V, float* __restrict__ catbase) {
    extern __shared__ float sm[];
    float* Qs = sm;                       // 64 x 129
    float* Ks = Qs + 64 * QS_ST;          // 64 x 129
    float* Vs = Ks + 64 * QS_ST;          // 64 x 128
    float* Ps = Vs + 64 * H;              // 64 x 65

    int tid = threadIdx.x;
    int tx = tid & 15, ty = tid >> 4;
    int r0 = blockIdx.x * 64;
    int head = blockIdx.y;
    const float* Q = Qall + (size_t)head * N * H;
    const float* K = Kall + (size_t)head * N * H;

    for (int idx = tid; idx < 64 * H; idx += 256) {
        int i = idx >> 7, k = idx & 127;
        int row = r0 + i;
        Qs[i * QS_ST + k] = (row < N) ? Q[row * H + k] : 0.f;
    }

    float m[4], l[4], o[4][8];
#pragma unroll
    for (int r = 0; r < 4; r++) {
        m[r] = -1e30f; l[r] = 0.f;
#pragma unroll
        for (int c = 0; c < 8; c++) o[r][c] = 0.f;
    }

    int nt = gridDim.x;
    for (int t = 0; t < nt; t++) {
        int c0 = t * 64;
        __syncthreads();   // previous PV done before overwriting Ks/Vs
        for (int idx = tid; idx < 64 * H; idx += 256) {
            int i = idx >> 7, k = idx & 127;
            int cr = c0 + i;
            bool ok = cr < N;
            Ks[i * QS_ST + k] = ok ? K[cr * H + k] : 0.f;
            Vs[i * H + k]     = ok ? V[cr * H + k] : 0.f;
        }
        __syncthreads();

        float s[4][4];
#pragma unroll
        for (int r = 0; r < 4; r++)
#pragma unroll
            for (int c = 0; c < 4; c++) s[r][c] = 0.f;
#pragma unroll 8
        for (int k = 0; k < H; k++) {
            float a[4], b[4];
#pragma unroll
            for (int r = 0; r < 4; r++) a[r] = Qs[(ty * 4 + r) * QS_ST + k];
#pragma unroll
            for (int c = 0; c < 4; c++) b[c] = Ks[(c * 16 + tx) * QS_ST + k];
#pragma unroll
            for (int r = 0; r < 4; r++)
#pragma unroll
                for (int c = 0; c < 4; c++) s[r][c] += a[r] * b[c];
        }
        if (c0 + 64 > N) {
#pragma unroll
            for (int c = 0; c < 4; c++)
                if (c0 + c * 16 + tx >= N)
#pragma unroll
                    for (int r = 0; r < 4; r++) s[r][c] = -1e30f;
        }
#pragma unroll
        for (int r = 0; r < 4; r++) {
            float rm = fmaxf(fmaxf(s[r][0], s[r][1]), fmaxf(s[r][2], s[r][3]));
#pragma unroll
            for (int w = 1; w < 16; w <<= 1)
                rm = fmaxf(rm, __shfl_xor_sync(0xffffffffu, rm, w));
            float mn = fmaxf(m[r], rm);
            float corr = __expf(m[r] - mn);
            float rs = 0.f;
#pragma unroll
            for (int c = 0; c < 4; c++) {
                float p = __expf(s[r][c] - mn);
                Ps[(ty * 4 + r) * PS_ST + c * 16 + tx] = p;
                rs += p;
            }
#pragma unroll
            for (int w = 1; w < 16; w <<= 1)
                rs += __shfl_xor_sync(0xffffffffu, rs, w);
            l[r] = l[r] * corr + rs;
            m[r] = mn;
#pragma unroll
            for (int c = 0; c < 8; c++) o[r][c] *= corr;
        }
        __syncthreads();   // Ps visible to all
#pragma unroll 4
        for (int j = 0; j < 64; j++) {
            float p[4], vv[8];
#pragma unroll
            for (int r = 0; r < 4; r++) p[r] = Ps[(ty * 4 + r) * PS_ST + j];
#pragma unroll
            for (int c = 0; c < 8; c++) vv[c] = Vs[j * H + c * 16 + tx];
#pragma unroll
            for (int r = 0; r < 4; r++)
#pragma unroll
                for (int c = 0; c < 8; c++) o[r][c] += p[r] * vv[c];
        }
    }
    float* outp = catbase + H + head * H;
#pragma unroll
    for (int r = 0; r < 4; r++) {
        int row = r0 + ty * 4 + r;
        if (row < N) {
            float inv = 1.f / l[r];
#pragma unroll
            for (int c = 0; c < 8; c++)
                outp[(long)row * CATW + c * 16 + tx] = o[r][c] * inv;
        }
    }
}

// ---------------- output projection (128 -> 3) ----------------
__global__ void k_out3(const float* __restrict__ h, const float* __restrict__ W,
                       const float* __restrict__ b, float* __restrict__ out) {
    __shared__ float red[3][128];
    int v = blockIdx.x, t = threadIdx.x;
    float hv = h[v * H + t];
    red[0][t] = hv * W[t * 3 + 0];
    red[1][t] = hv * W[t * 3 + 1];
    red[2][t] = hv * W[t * 3 + 2];
    __syncthreads();
    for (int ofs = 64; ofs > 0; ofs >>= 1) {
        if (t < ofs) {
            red[0][t] += red[0][t + ofs];
            red[1][t] += red[1][t + ofs];
            red[2][t] += red[2][t + ofs];
        }
        __syncthreads();
    }
    if (t < 3) out[v * 3 + t] = red[t][0] + b[t];
}

// ---------------- host ----------------
static void* symAddr(const void* s) {
    void* p = nullptr;
    cudaGetSymbolAddress(&p, s);
    return p;
}

extern "C" void kernel_launch(void* const* d_in, const int* in_sizes, int n_in,
                              void* d_out, int out_size) {
    const float* x_resting = (const float*)d_in[0];
    const float* x_rigid   = (const float*)d_in[1];
    const int*   e_rest    = (const int*)d_in[2];
    const int*   e_rig     = (const int*)d_in[3];
    const float* Wr0 = (const float*)d_in[4];
    const float* br0 = (const float*)d_in[5];
    const float* Wr  = (const float*)d_in[6];
    const float* br  = (const float*)d_in[7];
    const float* Wg0 = (const float*)d_in[8];
    const float* bg0 = (const float*)d_in[9];
    const float* Wg  = (const float*)d_in[10];
    const float* bg  = (const float*)d_in[11];
    const float* Wa  = (const float*)d_in[12];
    const float* ba  = (const float*)d_in[13];
    const float* Wd0 = (const float*)d_in[14];
    const float* bd0 = (const float*)d_in[15];
    const float* Wd  = (const float*)d_in[16];
    const float* bd  = (const float*)d_in[17];
    const float* Wout= (const float*)d_in[18];
    const float* bout= (const float*)d_in[19];
    float* out = (float*)d_out;

    int*   degB = (int*)symAddr(g_deg);
    int*   offB = (int*)symAddr(g_off);
    int*   cntB = (int*)symAddr(g_cnt);
    int*   srcB = (int*)symAddr(g_src);
    float* nrmB = (float*)symAddr(g_nrm);
    float* dinvB= (float*)symAddr(g_dinv);
    float* hw   = (float*)symAddr(g_hw);
    float* ha   = (float*)symAddr(g_ha);
    float* hb   = (float*)symAddr(g_hb);
    float* xg   = (float*)symAddr(g_xg);
    float* qbuf = (float*)symAddr(g_q);
    float* kbuf = (float*)symAddr(g_k);
    float* cat  = (float*)symAddr(g_cat);
    float* d1   = (float*)symAddr(g_d1);
    float* d2   = (float*)symAddr(g_d2);

    const int TB = 256;
    const int GN  = (N + TB - 1) / TB;
    const int GE  = (E + TB - 1) / TB;
    const int GEN = (EN + TB - 1) / TB;
    const int GB  = (N + 63) / 64;    // 94

    // ------- two GCN encoders -------
    for (int ei = 0; ei < 2; ei++) {
        const int*   edges = ei == 0 ? e_rest : e_rig;
        const float* x     = ei == 0 ? x_resting : x_rigid;
        const float* W0    = ei == 0 ? Wr0 : Wg0;
        const float* b0    = ei == 0 ? br0 : bg0;
        const float* Ws    = ei == 0 ? Wr  : Wg;
        const float* bs    = ei == 0 ? br  : bg;
        float* fout = ei == 0 ? cat : xg;    // resting -> cat cols[0:128)
        int    fldo = ei == 0 ? CATW : H;

        int*   deg = degB + ei * N;
        int*   off = offB + ei * (N + 1);
        int*   cnt = cntB + ei * N;
        int*   src = srcB + ei * EN;
        float* nrm = nrmB + ei * EN;
        float* dinv= dinvB + ei * N;

        k_deg_init<<<GN, TB>>>(deg);
        k_deg_count<<<GE, TB>>>(edges + E, deg);
        k_dinv<<<GN, TB>>>(deg, dinv);
        k_scan<<<1, 1024>>>(deg, off);
        k_zero_cnt<<<GN, TB>>>(cnt);
        k_fill<<<GEN, TB>>>(edges, edges + E, off, cnt, dinv, src, nrm);

        k_gemm_in3<<<N, H>>>(x, W0, hw);
        k_aggregate<<<N, H>>>(hw, off, src, nrm, b0, ha, H);
        k_gemm<<<GB, 256>>>(ha, H, Ws, nullptr, hw, H, N, H, 0);
        k_aggregate<<<N, H>>>(hw, off, src, nrm, bs, hb, H);
        k_gemm<<<GB, 256>>>(hb, H, Ws + H * H, nullptr, hw, H, N, H, 0);
        k_aggregate<<<N, H>>>(hw, off, src, nrm, bs + H, fout, fldo);
    }

    // ------- attention projections (xr lives in cat cols 0:128, lda=640) -------
    for (int a = 0; a < NHEADS; a++) {
        k_gemm<<<GB, 256>>>(cat, CATW, Wa + a * H * H, ba + a * H,
                            qbuf + (size_t)a * N * H, H, N, H, 0);
        k_gemm<<<GB, 256>>>(xg, H, Wa + a * H * H, ba + a * H,
                            kbuf + (size_t)a * N * H, H, N, H, 0);
    }

    // ------- flash attention, writes pooled heads into cat cols [128,640) -------
    size_t fsm = (size_t)(64 * QS_ST * 2 + 64 * H + 64 * PS_ST) * sizeof(float);
    cudaFuncSetAttribute(k_flash, cudaFuncAttributeMaxDynamicSharedMemorySize, (int)fsm);
    dim3 fgrid(GB, NHEADS);
    k_flash<<<fgrid, 256, fsm>>>(qbuf, kbuf, xg, cat);

    // ------- decoder -------
    k_gemm<<<GB, 256>>>(cat, CATW, Wd0, bd0, d1, H, N, CATW, 1);
    k_gemm<<<GB, 256>>>(d1, H, Wd, bd, d2, H, N, H, 1);
    k_gemm<<<GB, 256>>>(d2, H, Wd + H * H, bd + H, d1, H, N, H, 1);
    k_out3<<<N, H>>>(d1, Wout, bout, out);
}

// round 7
// speedup vs baseline: 2.5977x; 2.5977x over previous
#include <cuda_runtime.h>
#include <cuda_bf16.h>
#include <math.h>
#include <stdint.h>

#define N 6000
#define NP 6016
#define E 192000
#define H 128
#define NHEADS 4
#define EN (E + N)
#define CATW (H * (NHEADS + 1))   // 640

// ---------------- device scratch ----------------
__device__ int   g_deg[2][N];
__device__ int   g_off[2][N + 1];
__device__ int   g_cnt[2][N];
__device__ int   g_src[2][EN];
__device__ float g_nrm[2][EN];
__device__ float g_dinv[2][N];
__device__ float g_hw[N * H];
__device__ float g_ha[N * H];
__device__ float g_hb[N * H];
__device__ float g_xg[N * H];
__device__ float g_q[NHEADS][N * H];
__device__ float g_k[NHEADS][N * H];
__device__ float g_cat[N * CATW];
__device__ float g_d1[N * H];
__device__ float g_d2[N * H];
// bf16 attention operands (padded to NP rows; pads stay zero)
__device__ __align__(16) __nv_bfloat16 g_qhi[NHEADS * NP * H];
__device__ __align__(16) __nv_bfloat16 g_qlo[NHEADS * NP * H];
__device__ __align__(16) __nv_bfloat16 g_khi[NHEADS * NP * H];
__device__ __align__(16) __nv_bfloat16 g_klo[NHEADS * NP * H];
__device__ __align__(16) __nv_bfloat16 g_vbf[NP * H];

// ---------------- small helpers ----------------
__device__ __forceinline__ uint32_t smem_u32(const void* p) {
    uint32_t a;
    asm("{ .reg .u64 t; cvta.to.shared.u64 t, %1; cvt.u32.u64 %0, t; }" : "=r"(a) : "l"(p));
    return a;
}
__device__ __forceinline__ void mma16816(float* c, const uint32_t* a, uint32_t b0, uint32_t b1) {
    asm volatile(
        "mma.sync.aligned.m16n8k16.row.col.f32.bf16.bf16.f32 "
        "{%0,%1,%2,%3}, {%4,%5,%6,%7}, {%8,%9}, {%0,%1,%2,%3};"
        : "+f"(c[0]), "+f"(c[1]), "+f"(c[2]), "+f"(c[3])
        : "r"(a[0]), "r"(a[1]), "r"(a[2]), "r"(a[3]), "r"(b0), "r"(b1));
}
__device__ __forceinline__ void ldm_x4(uint32_t& r0, uint32_t& r1, uint32_t& r2, uint32_t& r3,
                                       uint32_t addr) {
    asm volatile("ldmatrix.sync.aligned.m8n8.x4.shared.b16 {%0,%1,%2,%3}, [%4];"
                 : "=r"(r0), "=r"(r1), "=r"(r2), "=r"(r3) : "r"(addr));
}
__device__ __forceinline__ void ldm_x4t(uint32_t& r0, uint32_t& r1, uint32_t& r2, uint32_t& r3,
                                        uint32_t addr) {
    asm volatile("ldmatrix.sync.aligned.m8n8.x4.trans.shared.b16 {%0,%1,%2,%3}, [%4];"
                 : "=r"(r0), "=r"(r1), "=r"(r2), "=r"(r3) : "r"(addr));
}
__device__ __forceinline__ void cp16(uint32_t dst, const void* src, uint32_t sz) {
    asm volatile("cp.async.cg.shared.global [%0], [%1], 16, %2;"
                 :: "r"(dst), "l"(src), "r"(sz) : "memory");
}
__device__ __forceinline__ uint32_t packbf(float a, float b) {
    __nv_bfloat162 v = __floats2bfloat162_rn(a, b);
    return *reinterpret_cast<uint32_t*>(&v);
}

// ---------------- graph preprocessing ----------------
__global__ void k_deg_init(int* deg) {
    int i = blockIdx.x * blockDim.x + threadIdx.x;
    if (i < N) deg[i] = 1;
}
__global__ void k_deg_count(const int* __restrict__ col, int* deg) {
    int e = blockIdx.x * blockDim.x + threadIdx.x;
    if (e < E) atomicAdd(&deg[col[e]], 1);
}
__global__ void k_dinv(const int* __restrict__ deg, float* dinv) {
    int i = blockIdx.x * blockDim.x + threadIdx.x;
    if (i < N) dinv[i] = rsqrtf((float)deg[i]);
}
__global__ void k_zero_cnt(int* cnt) {
    int i = blockIdx.x * blockDim.x + threadIdx.x;
    if (i < N) cnt[i] = 0;
}
__global__ void k_scan(const int* __restrict__ deg, int* __restrict__ off) {
    __shared__ int part[1024];
    int tid = threadIdx.x;
    const int C = (N + 1023) / 1024;
    int base = tid * C;
    int s = 0;
    for (int i = 0; i < C; i++) { int idx = base + i; if (idx < N) s += deg[idx]; }
    part[tid] = s;
    __syncthreads();
    for (int d = 1; d < 1024; d <<= 1) {
        int v = (tid >= d) ? part[tid - d] : 0;
        __syncthreads();
        part[tid] += v;
        __syncthreads();
    }
    int run = (tid == 0) ? 0 : part[tid - 1];
    for (int i = 0; i < C; i++) {
        int idx = base + i;
        if (idx < N) { off[idx] = run; run += deg[idx]; }
    }
    if (tid == 0) off[N] = part[1023];
}
__global__ void k_fill(const int* __restrict__ erow, const int* __restrict__ ecol,
                       const int* __restrict__ off, int* cnt,
                       const float* __restrict__ dinv,
                       int* __restrict__ src, float* __restrict__ nrm) {
    int e = blockIdx.x * blockDim.x + threadIdx.x;
    if (e >= EN) return;
    int r, c;
    if (e < E) { r = erow[e]; c = ecol[e]; }
    else       { r = c = e - E; }
    int pos = off[c] + atomicAdd(&cnt[c], 1);
    src[pos] = r;
    nrm[pos] = dinv[r] * dinv[c];
}

// ---------------- GCN kernels ----------------
__global__ void k_gemm_in3(const float* __restrict__ x, const float* __restrict__ W,
                           float* __restrict__ out) {
    int v = blockIdx.x, t = threadIdx.x;
    float x0 = x[v * 3 + 0], x1 = x[v * 3 + 1], x2 = x[v * 3 + 2];
    out[v * H + t] = x0 * W[t] + x1 * W[H + t] + x2 * W[2 * H + t];
}
__global__ void k_aggregate(const float* __restrict__ hw, const int* __restrict__ off,
                            const int* __restrict__ src, const float* __restrict__ nrm,
                            const float* __restrict__ bias, float* __restrict__ out, int ldo) {
    __shared__ int   ssrc[128];
    __shared__ float snrm[128];
    int v = blockIdx.x, t = threadIdx.x;
    int s = off[v], e = off[v + 1];
    float acc = 0.f;
    for (int base = s; base < e; base += 128) {
        int i = base + t;
        if (i < e) { ssrc[t] = src[i]; snrm[t] = nrm[i]; }
        __syncthreads();
        int cnt = min(128, e - base);
        for (int j = 0; j < cnt; j++)
            acc += hw[ssrc[j] * H + t] * snrm[j];
        __syncthreads();
    }
    float r = acc + bias[t];
    out[v * ldo + t] = fmaxf(r, 0.f);
}

// ---------------- generic fp32 GEMM ----------------
__global__ __launch_bounds__(256)
void k_gemm(const float* __restrict__ A, int lda,
            const float* __restrict__ W, const float* __restrict__ bias,
            float* __restrict__ out, int ldo, int n, int K, int doRelu) {
    __shared__ float As[64 * 33];
    __shared__ float Ws[32 * 128];
    int tid = threadIdx.x;
    int tx = tid & 15, ty = tid >> 4;
    int r0 = blockIdx.x * 64;
    float acc[4][8];
#pragma unroll
    for (int r = 0; r < 4; r++)
#pragma unroll
        for (int c = 0; c < 8; c++) acc[r][c] = 0.f;

    for (int kc = 0; kc < K; kc += 32) {
        for (int i = tid; i < 32 * 128; i += 256) Ws[i] = W[kc * 128 + i];
        for (int idx = tid; idx < 64 * 32; idx += 256) {
            int i = idx >> 5, k = idx & 31;
            int row = r0 + i;
            As[i * 33 + k] = (row < n) ? A[(long)row * lda + kc + k] : 0.f;
        }
        __syncthreads();
#pragma unroll 8
        for (int k = 0; k < 32; k++) {
            float a[4], w[8];
#pragma unroll
            for (int r = 0; r < 4; r++) a[r] = As[(ty * 4 + r) * 33 + k];
#pragma unroll
            for (int c = 0; c < 8; c++) w[c] = Ws[k * 128 + c * 16 + tx];
#pragma unroll
            for (int r = 0; r < 4; r++)
#pragma unroll
                for (int c = 0; c < 8; c++) acc[r][c] += a[r] * w[c];
        }
        __syncthreads();
    }
#pragma unroll
    for (int r = 0; r < 4; r++) {
        int row = r0 + ty * 4 + r;
        if (row < n) {
#pragma unroll
            for (int c = 0; c < 8; c++) {
                int col = c * 16 + tx;
                float v = acc[r][c] + (bias ? bias[col] : 0.f);
                if (doRelu) v = fmaxf(v, 0.f);
                out[(long)row * ldo + col] = v;
            }
        }
    }
}

// ---------------- attention operand prep ----------------
__global__ void k_split(const float* __restrict__ q, const float* __restrict__ k,
                        __nv_bfloat16* __restrict__ qh, __nv_bfloat16* __restrict__ ql,
                        __nv_bfloat16* __restrict__ kh, __nv_bfloat16* __restrict__ kl) {
    int idx = blockIdx.x * blockDim.x + threadIdx.x;
    if (idx >= NHEADS * N * H) return;
    int a = idx / (N * H), r = idx - a * (N * H);
    int d = a * NP * H + r;
    float qv = q[idx];
    __nv_bfloat16 h1 = __float2bfloat16(qv);
    qh[d] = h1;
    ql[d] = __float2bfloat16(qv - __bfloat162float(h1));
    float kv = k[idx];
    __nv_bfloat16 h2 = __float2bfloat16(kv);
    kh[d] = h2;
    kl[d] = __float2bfloat16(kv - __bfloat162float(h2));
}
__global__ void k_v2bf(const float* __restrict__ xg, __nv_bfloat16* __restrict__ vb) {
    int i = blockIdx.x * blockDim.x + threadIdx.x;
    if (i < N * H) vb[i] = __float2bfloat16(xg[i]);
}

// ---------------- mma.sync flash attention ----------------
#define QT  128
#define KVT 64
#define RS  136                   // smem row stride (bf16 elements) = 272B
#define BUFB (192 * RS * 2)       // bytes per buffer: khi(64) + klo(64) + v(64) rows
#define SMEM_FA (2 * BUFB)

__global__ void __launch_bounds__(256, 1)
k_flash_mma(const __nv_bfloat16* __restrict__ Qhi, const __nv_bfloat16* __restrict__ Qlo,
            const __nv_bfloat16* __restrict__ Khi, const __nv_bfloat16* __restrict__ Klo,
            const __nv_bfloat16* __restrict__ Vb, float* __restrict__ catb) {
    extern __shared__ __nv_bfloat16 smfa[];
    const uint32_t sbase = smem_u32(smfa);
    const int tid = threadIdx.x;
    const int w = tid >> 5, lane = tid & 31;
    const int g = lane >> 2, t4 = lane & 3;
    const int head = blockIdx.y;
    const int r0 = blockIdx.x * QT;

    const __nv_bfloat16* qhi = Qhi + (size_t)head * NP * H;
    const __nv_bfloat16* qlo = Qlo + (size_t)head * NP * H;
    const __nv_bfloat16* khi = Khi + (size_t)head * NP * H;
    const __nv_bfloat16* klo = Klo + (size_t)head * NP * H;

    const int row_g = r0 + w * 16 + g;
    const int row_h = row_g + 8;

    // --- Q fragments (persist across all tiles) ---
    uint32_t qh[8][4], ql[8][4];
#pragma unroll
    for (int kc = 0; kc < 8; kc++) {
        int c0 = kc * 16 + 2 * t4;
        qh[kc][0] = *(const uint32_t*)(qhi + (size_t)row_g * H + c0);
        qh[kc][1] = *(const uint32_t*)(qhi + (size_t)row_h * H + c0);
        qh[kc][2] = *(const uint32_t*)(qhi + (size_t)row_g * H + c0 + 8);
        qh[kc][3] = *(const uint32_t*)(qhi + (size_t)row_h * H + c0 + 8);
        ql[kc][0] = *(const uint32_t*)(qlo + (size_t)row_g * H + c0);
        ql[kc][1] = *(const uint32_t*)(qlo + (size_t)row_h * H + c0);
        ql[kc][2] = *(const uint32_t*)(qlo + (size_t)row_g * H + c0 + 8);
        ql[kc][3] = *(const uint32_t*)(qlo + (size_t)row_h * H + c0 + 8);
    }

    float o[16][4];
#pragma unroll
    for (int i = 0; i < 16; i++)
#pragma unroll
        for (int j = 0; j < 4; j++) o[i][j] = 0.f;
    float m0 = -1e30f, m1 = -1e30f, l0 = 0.f, l1 = 0.f;

    const int NT = (N + KVT - 1) / KVT;    // 94

    // tile loader: 64 rows x 16 segs x 3 arrays via cp.async (zfill OOB)
    auto issue_load = [&](int tile, int b) {
        int c0 = tile * KVT;
        uint32_t dbase = sbase + (uint32_t)b * BUFB;
#pragma unroll 4
        for (int i = tid; i < 64 * 16; i += 256) {
            int r = i >> 4, s = i & 15;
            int gr = c0 + r;
            uint32_t sz = (gr < N) ? 16u : 0u;
            int grc = (gr < N) ? gr : (N - 1);
            uint32_t d0 = dbase + (uint32_t)(r * RS * 2 + s * 16);
            cp16(d0,                    khi + (size_t)grc * H + s * 8, sz);
            cp16(d0 + 64 * RS * 2,      klo + (size_t)grc * H + s * 8, sz);
            cp16(d0 + 128 * RS * 2,     Vb  + (size_t)grc * H + s * 8, sz);
        }
        asm volatile("cp.async.commit_group;" ::: "memory");
    };

    issue_load(0, 0);

    for (int t = 0; t < NT; t++) {
        int b = t & 1;
        if (t + 1 < NT) {
            issue_load(t + 1, b ^ 1);
            asm volatile("cp.async.wait_group 1;" ::: "memory");
        } else {
            asm volatile("cp.async.wait_group 0;" ::: "memory");
        }
        __syncthreads();

        uint32_t kb = sbase + (uint32_t)b * BUFB;
        // ---- S = Qhi*Khi + Qlo*Khi + Qhi*Klo ----
        float c[8][4];
#pragma unroll
        for (int i = 0; i < 8; i++)
#pragma unroll
            for (int j = 0; j < 4; j++) c[i][j] = 0.f;

        const int jj = lane >> 3, rr = lane & 7;
#pragma unroll
        for (int nb2 = 0; nb2 < 4; nb2++) {
#pragma unroll
            for (int kc = 0; kc < 8; kc++) {
                uint32_t addr = kb + (uint32_t)(((nb2 * 16 + ((jj >> 1) << 3) + rr) * RS +
                                                kc * 16 + ((jj & 1) << 3)) * 2);
                uint32_t h0, h1, h2, h3, e0, e1, e2, e3;
                ldm_x4(h0, h1, h2, h3, addr);
                ldm_x4(e0, e1, e2, e3, addr + 64 * RS * 2);
                mma16816(c[2 * nb2],     qh[kc], h0, h1);
                mma16816(c[2 * nb2 + 1], qh[kc], h2, h3);
                mma16816(c[2 * nb2],     ql[kc], h0, h1);
                mma16816(c[2 * nb2 + 1], ql[kc], h2, h3);
                mma16816(c[2 * nb2],     qh[kc], e0, e1);
                mma16816(c[2 * nb2 + 1], qh[kc], e2, e3);
            }
        }

        // ---- online softmax ----
        float tm0 = -1e30f, tm1 = -1e30f;
#pragma unroll
        for (int nb = 0; nb < 8; nb++) {
            tm0 = fmaxf(tm0, fmaxf(c[nb][0], c[nb][1]));
            tm1 = fmaxf(tm1, fmaxf(c[nb][2], c[nb][3]));
        }
        tm0 = fmaxf(tm0, __shfl_xor_sync(0xffffffffu, tm0, 1));
        tm0 = fmaxf(tm0, __shfl_xor_sync(0xffffffffu, tm0, 2));
        tm1 = fmaxf(tm1, __shfl_xor_sync(0xffffffffu, tm1, 1));
        tm1 = fmaxf(tm1, __shfl_xor_sync(0xffffffffu, tm1, 2));
        float mn0 = fmaxf(m0, tm0), mn1 = fmaxf(m1, tm1);
        float sc0 = __expf(m0 - mn0), sc1 = __expf(m1 - mn1);
        m0 = mn0; m1 = mn1;

        uint32_t pa[4][4];
        float rs0 = 0.f, rs1 = 0.f;
        const bool tail = (t == NT - 1);
        const int cc0 = t * KVT;
#pragma unroll
        for (int kc2 = 0; kc2 < 4; kc2++) {
            int nA = 2 * kc2, nB = nA + 1;
            float pA0 = __expf(c[nA][0] - mn0), pA1 = __expf(c[nA][1] - mn0);
            float pA2 = __expf(c[nA][2] - mn1), pA3 = __expf(c[nA][3] - mn1);
            float pB0 = __expf(c[nB][0] - mn0), pB1 = __expf(c[nB][1] - mn0);
            float pB2 = __expf(c[nB][2] - mn1), pB3 = __expf(c[nB][3] - mn1);
            if (tail) {
                int jA = cc0 + nA * 8 + 2 * t4, jB = cc0 + nB * 8 + 2 * t4;
                if (jA     >= N) { pA0 = 0.f; pA2 = 0.f; }
                if (jA + 1 >= N) { pA1 = 0.f; pA3 = 0.f; }
                if (jB     >= N) { pB0 = 0.f; pB2 = 0.f; }
                if (jB + 1 >= N) { pB1 = 0.f; pB3 = 0.f; }
            }
            rs0 += pA0 + pA1 + pB0 + pB1;
            rs1 += pA2 + pA3 + pB2 + pB3;
            pa[kc2][0] = packbf(pA0, pA1);
            pa[kc2][1] = packbf(pA2, pA3);
            pa[kc2][2] = packbf(pB0, pB1);
            pa[kc2][3] = packbf(pB2, pB3);
        }
        l0 = l0 * sc0 + rs0;
        l1 = l1 * sc1 + rs1;
#pragma unroll
        for (int i = 0; i < 16; i++) {
            o[i][0] *= sc0; o[i][1] *= sc0;
            o[i][2] *= sc1; o[i][3] *= sc1;
        }

        // ---- O += P @ V ----
        uint32_t vbb = kb + 128 * RS * 2;
#pragma unroll
        for (int nb2 = 0; nb2 < 8; nb2++) {
#pragma unroll
            for (int kc2 = 0; kc2 < 4; kc2++) {
                uint32_t addr = vbb + (uint32_t)(((kc2 * 16 + ((jj & 1) << 3) + rr) * RS +
                                                 nb2 * 16 + ((jj >> 1) << 3)) * 2);
                uint32_t v0, v1, v2, v3;
                ldm_x4t(v0, v1, v2, v3, addr);
                mma16816(o[2 * nb2],     pa[kc2], v0, v1);
                mma16816(o[2 * nb2 + 1], pa[kc2], v2, v3);
            }
        }
        __syncthreads();
    }

    // ---- finalize ----
    l0 += __shfl_xor_sync(0xffffffffu, l0, 1);
    l0 += __shfl_xor_sync(0xffffffffu, l0, 2);
    l1 += __shfl_xor_sync(0xffffffffu, l1, 1);
    l1 += __shfl_xor_sync(0xffffffffu, l1, 2);
    float li0 = 1.f / l0, li1 = 1.f / l1;

    float* obase = catb + H + head * H;
    if (row_g < N) {
        float* p = obase + (size_t)row_g * CATW;
#pragma unroll
        for (int nb = 0; nb < 16; nb++) {
            float2 v = make_float2(o[nb][0] * li0, o[nb][1] * li0);
            *(float2*)(p + nb * 8 + 2 * t4) = v;
        }
    }
    if (row_h < N) {
        float* p = obase + (size_t)row_h * CATW;
#pragma unroll
        for (int nb = 0; nb < 16; nb++) {
            float2 v = make_float2(o[nb][2] * li1, o[nb][3] * li1);
            *(float2*)(p + nb * 8 + 2 * t4) = v;
        }
    }
}

// ---------------- output projection (128 -> 3) ----------------
__global__ void k_out3(const float* __restrict__ h, const float* __restrict__ W,
                       const float* __restrict__ b, float* __restrict__ out) {
    __shared__ float red[3][128];
    int v = blockIdx.x, t = threadIdx.x;
    float hv = h[v * H + t];
    red[0][t] = hv * W[t * 3 + 0];
    red[1][t] = hv * W[t * 3 + 1];
    red[2][t] = hv * W[t * 3 + 2];
    __syncthreads();
    for (int ofs = 64; ofs > 0; ofs >>= 1) {
        if (t < ofs) {
            red[0][t] += red[0][t + ofs];
            red[1][t] += red[1][t + ofs];
            red[2][t] += red[2][t + ofs];
        }
        __syncthreads();
    }
    if (t < 3) out[v * 3 + t] = red[t][0] + b[t];
}

// ---------------- host ----------------
static void* symAddr(const void* s) {
    void* p = nullptr;
    cudaGetSymbolAddress(&p, s);
    return p;
}

extern "C" void kernel_launch(void* const* d_in, const int* in_sizes, int n_in,
                              void* d_out, int out_size) {
    const float* x_resting = (const float*)d_in[0];
    const float* x_rigid   = (const float*)d_in[1];
    const int*   e_rest    = (const int*)d_in[2];
    const int*   e_rig     = (const int*)d_in[3];
    const float* Wr0 = (const float*)d_in[4];
    const float* br0 = (const float*)d_in[5];
    const float* Wr  = (const float*)d_in[6];
    const float* br  = (const float*)d_in[7];
    const float* Wg0 = (const float*)d_in[8];
    const float* bg0 = (const float*)d_in[9];
    const float* Wg  = (const float*)d_in[10];
    const float* bg  = (const float*)d_in[11];
    const float* Wa  = (const float*)d_in[12];
    const float* ba  = (const float*)d_in[13];
    const float* Wd0 = (const float*)d_in[14];
    const float* bd0 = (const float*)d_in[15];
    const float* Wd  = (const float*)d_in[16];
    const float* bd  = (const float*)d_in[17];
    const float* Wout= (const float*)d_in[18];
    const float* bout= (const float*)d_in[19];
    float* out = (float*)d_out;

    int*   degB = (int*)symAddr(g_deg);
    int*   offB = (int*)symAddr(g_off);
    int*   cntB = (int*)symAddr(g_cnt);
    int*   srcB = (int*)symAddr(g_src);
    float* nrmB = (float*)symAddr(g_nrm);
    float* dinvB= (float*)symAddr(g_dinv);
    float* hw   = (float*)symAddr(g_hw);
    float* ha   = (float*)symAddr(g_ha);
    float* hb   = (float*)symAddr(g_hb);
    float* xg   = (float*)symAddr(g_xg);
    float* qbuf = (float*)symAddr(g_q);
    float* kbuf = (float*)symAddr(g_k);
    float* cat  = (float*)symAddr(g_cat);
    float* d1   = (float*)symAddr(g_d1);
    float* d2   = (float*)symAddr(g_d2);
    __nv_bfloat16* qhi = (__nv_bfloat16*)symAddr(g_qhi);
    __nv_bfloat16* qlo = (__nv_bfloat16*)symAddr(g_qlo);
    __nv_bfloat16* khi = (__nv_bfloat16*)symAddr(g_khi);
    __nv_bfloat16* klo = (__nv_bfloat16*)symAddr(g_klo);
    __nv_bfloat16* vbf = (__nv_bfloat16*)symAddr(g_vbf);

    const int TB = 256;
    const int GN  = (N + TB - 1) / TB;
    const int GE  = (E + TB - 1) / TB;
    const int GEN = (EN + TB - 1) / TB;
    const int GB  = (N + 63) / 64;

    // ------- two GCN encoders -------
    for (int ei = 0; ei < 2; ei++) {
        const int*   edges = ei == 0 ? e_rest : e_rig;
        const float* x     = ei == 0 ? x_resting : x_rigid;
        const float* W0    = ei == 0 ? Wr0 : Wg0;
        const float* b0    = ei == 0 ? br0 : bg0;
        const float* Ws    = ei == 0 ? Wr  : Wg;
        const float* bs    = ei == 0 ? br  : bg;
        float* fout = ei == 0 ? cat : xg;
        int    fldo = ei == 0 ? CATW : H;

        int*   deg = degB + ei * N;
        int*   off = offB + ei * (N + 1);
        int*   cnt = cntB + ei * N;
        int*   src = srcB + ei * EN;
        float* nrm = nrmB + ei * EN;
        float* dinv= dinvB + ei * N;

        k_deg_init<<<GN, TB>>>(deg);
        k_deg_count<<<GE, TB>>>(edges + E, deg);
        k_dinv<<<GN, TB>>>(deg, dinv);
        k_scan<<<1, 1024>>>(deg, off);
        k_zero_cnt<<<GN, TB>>>(cnt);
        k_fill<<<GEN, TB>>>(edges, edges + E, off, cnt, dinv, src, nrm);

        k_gemm_in3<<<N, H>>>(x, W0, hw);
        k_aggregate<<<N, H>>>(hw, off, src, nrm, b0, ha, H);
        k_gemm<<<GB, 256>>>(ha, H, Ws, nullptr, hw, H, N, H, 0);
        k_aggregate<<<N, H>>>(hw, off, src, nrm, bs, hb, H);
        k_gemm<<<GB, 256>>>(hb, H, Ws + H * H, nullptr, hw, H, N, H, 0);
        k_aggregate<<<N, H>>>(hw, off, src, nrm, bs + H, fout, fldo);
    }

    // ------- attention projections -------
    for (int a = 0; a < NHEADS; a++) {
        k_gemm<<<GB, 256>>>(cat, CATW, Wa + a * H * H, ba + a * H,
                            qbuf + (size_t)a * N * H, H, N, H, 0);
        k_gemm<<<GB, 256>>>(xg, H, Wa + a * H * H, ba + a * H,
                            kbuf + (size_t)a * N * H, H, N, H, 0);
    }

    // ------- bf16 operand prep -------
    k_split<<<(NHEADS * N * H + 255) / 256, 256>>>(qbuf, kbuf, qhi, qlo, khi, klo);
    k_v2bf<<<(N * H + 255) / 256, 256>>>(xg, vbf);

    // ------- mma.sync flash attention -------
    cudaFuncSetAttribute(k_flash_mma, cudaFuncAttributeMaxDynamicSharedMemorySize, SMEM_FA);
    k_flash_mma<<<dim3((N + QT - 1) / QT, NHEADS), 256, SMEM_FA>>>(qhi, qlo, khi, klo, vbf, cat);

    // ------- decoder -------
    k_gemm<<<GB, 256>>>(cat, CATW, Wd0, bd0, d1, H, N, CATW, 1);
    k_gemm<<<GB, 256>>>(d1, H, Wd, bd, d2, H, N, H, 1);
    k_gemm<<<GB, 256>>>(d2, H, Wd + H * H, bd + H, d1, H, N, H, 1);
    k_out3<<<N, H>>>(d1, Wout, bout, out);
}

// round 8
// speedup vs baseline: 3.6812x; 1.4171x over previous
#include <cuda_runtime.h>
#include <cuda_bf16.h>
#include <math.h>
#include <stdint.h>

#define N 6000
#define NP 6016
#define E 192000
#define H 128
#define NHEADS 4
#define EN (E + N)
#define CATW (H * (NHEADS + 1))   // 640
#define NSPLIT 3

// ---------------- device scratch ----------------
__device__ int   g_deg[2][N];
__device__ int   g_off[2][N + 1];
__device__ int   g_cnt[2][N];
__device__ int   g_src[2][EN];
__device__ float g_nrm[2][EN];
__device__ float g_dinv[2][N];
__device__ float g_hw[2][N * H];
__device__ float g_ha[2][N * H];
__device__ float g_hb[2][N * H];
__device__ float g_xg[N * H];
__device__ float g_cat[N * CATW];
__device__ float g_d1[N * H];
__device__ float g_d2[N * H];
// bf16 attention operands (padded to NP rows; pads stay zero)
__device__ __align__(16) __nv_bfloat16 g_qhi[NHEADS * NP * H];
__device__ __align__(16) __nv_bfloat16 g_qlo[NHEADS * NP * H];
__device__ __align__(16) __nv_bfloat16 g_khi[NHEADS * NP * H];
__device__ __align__(16) __nv_bfloat16 g_klo[NHEADS * NP * H];
__device__ __align__(16) __nv_bfloat16 g_vbf[NP * H];
// flash partials (KV-split)
__device__ float g_po[NSPLIT * NHEADS * NP * H];
__device__ float g_pm[NSPLIT * NHEADS * NP];
__device__ float g_pl[NSPLIT * NHEADS * NP];

// ---------------- small helpers ----------------
__device__ __forceinline__ uint32_t smem_u32(const void* p) {
    uint32_t a;
    asm("{ .reg .u64 t; cvta.to.shared.u64 t, %1; cvt.u32.u64 %0, t; }" : "=r"(a) : "l"(p));
    return a;
}
__device__ __forceinline__ void mma16816(float* c, const uint32_t* a, uint32_t b0, uint32_t b1) {
    asm volatile(
        "mma.sync.aligned.m16n8k16.row.col.f32.bf16.bf16.f32 "
        "{%0,%1,%2,%3}, {%4,%5,%6,%7}, {%8,%9}, {%0,%1,%2,%3};"
        : "+f"(c[0]), "+f"(c[1]), "+f"(c[2]), "+f"(c[3])
        : "r"(a[0]), "r"(a[1]), "r"(a[2]), "r"(a[3]), "r"(b0), "r"(b1));
}
__device__ __forceinline__ void ldm_x4(uint32_t& r0, uint32_t& r1, uint32_t& r2, uint32_t& r3,
                                       uint32_t addr) {
    asm volatile("ldmatrix.sync.aligned.m8n8.x4.shared.b16 {%0,%1,%2,%3}, [%4];"
                 : "=r"(r0), "=r"(r1), "=r"(r2), "=r"(r3) : "r"(addr));
}
__device__ __forceinline__ void ldm_x4t(uint32_t& r0, uint32_t& r1, uint32_t& r2, uint32_t& r3,
                                        uint32_t addr) {
    asm volatile("ldmatrix.sync.aligned.m8n8.x4.trans.shared.b16 {%0,%1,%2,%3}, [%4];"
                 : "=r"(r0), "=r"(r1), "=r"(r2), "=r"(r3) : "r"(addr));
}
__device__ __forceinline__ void cp16(uint32_t dst, const void* src, uint32_t sz) {
    asm volatile("cp.async.cg.shared.global [%0], [%1], 16, %2;"
                 :: "r"(dst), "l"(src), "r"(sz) : "memory");
}
__device__ __forceinline__ uint32_t packbf(float a, float b) {
    __nv_bfloat162 v = __floats2bfloat162_rn(a, b);
    return *reinterpret_cast<uint32_t*>(&v);
}

// ---------------- graph preprocessing (both encoders merged) ----------------
__global__ void k_deg_init(int* deg) {
    int i = blockIdx.x * blockDim.x + threadIdx.x;
    if (i < 2 * N) deg[i] = 1;
}
__global__ void k_deg_count2(const int* __restrict__ col0, const int* __restrict__ col1,
                             int* deg) {
    int e = blockIdx.x * blockDim.x + threadIdx.x;
    int ei = blockIdx.y;
    const int* col = ei ? col1 : col0;
    if (e < E) atomicAdd(&deg[ei * N + col[e]], 1);
}
__global__ void k_dinv(const int* __restrict__ deg, float* dinv) {
    int i = blockIdx.x * blockDim.x + threadIdx.x;
    if (i < 2 * N) dinv[i] = rsqrtf((float)deg[i]);
}
__global__ void k_zero_cnt(int* cnt) {
    int i = blockIdx.x * blockDim.x + threadIdx.x;
    if (i < 2 * N) cnt[i] = 0;
}
// two blocks: one exclusive scan per encoder, warp-shuffle based
__global__ void k_scan2(const int* __restrict__ degAll, int* __restrict__ offAll) {
    int ei = blockIdx.x;
    const int* deg = degAll + ei * N;
    int* off = offAll + ei * (N + 1);
    __shared__ int wsum[32];
    int tid = threadIdx.x, lane = tid & 31, wid = tid >> 5;
    const int C = (N + 1023) / 1024;          // 6
    int base = tid * C;
    int loc[C];
    int s = 0;
#pragma unroll
    for (int i = 0; i < C; i++) {
        int idx = base + i;
        loc[i] = (idx < N) ? deg[idx] : 0;
        s += loc[i];
    }
    int inc = s;
#pragma unroll
    for (int d = 1; d < 32; d <<= 1) {
        int v = __shfl_up_sync(0xffffffffu, inc, d);
        if (lane >= d) inc += v;
    }
    if (lane == 31) wsum[wid] = inc;
    __syncthreads();
    if (wid == 0) {
        int v = wsum[lane];
#pragma unroll
        for (int d = 1; d < 32; d <<= 1) {
            int u = __shfl_up_sync(0xffffffffu, v, d);
            if (lane >= d) v += u;
        }
        wsum[lane] = v;
    }
    __syncthreads();
    int run = inc - s + (wid > 0 ? wsum[wid - 1] : 0);
#pragma unroll
    for (int i = 0; i < C; i++) {
        int idx = base + i;
        if (idx < N) { off[idx] = run; run += loc[i]; }
    }
    if (tid == 1023) off[N] = run;
}
__global__ void k_fill2(const int* __restrict__ ed0, const int* __restrict__ ed1,
                        const int* __restrict__ offB, int* cntB,
                        const float* __restrict__ dinvB,
                        int* __restrict__ srcB, float* __restrict__ nrmB) {
    int e = blockIdx.x * blockDim.x + threadIdx.x;
    if (e >= EN) return;
    int ei = blockIdx.y;
    const int* edges = ei ? ed1 : ed0;
    const int* off  = offB + ei * (N + 1);
    int* cnt        = cntB + ei * N;
    const float* dinv = dinvB + ei * N;
    int* src        = srcB + (size_t)ei * EN;
    float* nrm      = nrmB + (size_t)ei * EN;
    int r, c;
    if (e < E) { r = edges[e]; c = edges[E + e]; }
    else       { r = c = e - E; }
    int pos = off[c] + atomicAdd(&cnt[c], 1);
    src[pos] = r;
    nrm[pos] = dinv[r] * dinv[c];
}

// ---------------- GCN kernels (both encoders merged via grid.y) ----------------
__global__ void k_in3_2(const float* __restrict__ x0, const float* __restrict__ x1,
                        const float* __restrict__ W0, const float* __restrict__ W1,
                        float* __restrict__ hwB) {
    int ei = blockIdx.y;
    const float* x = ei ? x1 : x0;
    const float* W = ei ? W1 : W0;
    int v = blockIdx.x, t = threadIdx.x;
    float a0 = x[v * 3 + 0], a1 = x[v * 3 + 1], a2 = x[v * 3 + 2];
    hwB[(size_t)ei * N * H + v * H + t] = a0 * W[t] + a1 * W[H + t] + a2 * W[2 * H + t];
}
__global__ void k_agg2(const float* __restrict__ hwB, const int* __restrict__ offB,
                       const int* __restrict__ srcB, const float* __restrict__ nrmB,
                       const float* __restrict__ bias0, const float* __restrict__ bias1,
                       float* out0, int ldo0, float* out1, int ldo1) {
    __shared__ int   ssrc[128];
    __shared__ float snrm[128];
    int ei = blockIdx.y;
    const float* hw  = hwB + (size_t)ei * N * H;
    const int*   off = offB + ei * (N + 1);
    const int*   src = srcB + (size_t)ei * EN;
    const float* nrm = nrmB + (size_t)ei * EN;
    const float* bias = ei ? bias1 : bias0;
    float* out = ei ? out1 : out0;
    int ldo = ei ? ldo1 : ldo0;

    int v = blockIdx.x, t = threadIdx.x;
    int s = off[v], e = off[v + 1];
    float acc = 0.f;
    for (int base = s; base < e; base += 128) {
        int i = base + t;
        if (i < e) { ssrc[t] = src[i]; snrm[t] = nrm[i]; }
        __syncthreads();
        int cnt = min(128, e - base);
        for (int j = 0; j < cnt; j++)
            acc += hw[ssrc[j] * H + t] * snrm[j];
        __syncthreads();
    }
    float r = acc + bias[t];
    out[(size_t)v * ldo + t] = fmaxf(r, 0.f);
}

// ---------------- shared GEMM body ----------------
// MODE 0: fp32 store (+optional relu). MODE 1: bf16 hi/lo split store (ldo=H).
template<int MODE>
__device__ __forceinline__ void gemm_body(
    const float* __restrict__ A, int lda,
    const float* __restrict__ W, const float* __restrict__ bias,
    int n, int K, int doRelu, int r0,
    float* out, int ldo, __nv_bfloat16* oh, __nv_bfloat16* ol) {
    __shared__ float As[64 * 33];
    __shared__ float Ws[32 * 128];
    int tid = threadIdx.x;
    int tx = tid & 15, ty = tid >> 4;
    float acc[4][8];
#pragma unroll
    for (int r = 0; r < 4; r++)
#pragma unroll
        for (int c = 0; c < 8; c++) acc[r][c] = 0.f;

    for (int kc = 0; kc < K; kc += 32) {
        for (int i = tid; i < 32 * 128; i += 256) Ws[i] = W[kc * 128 + i];
        for (int idx = tid; idx < 64 * 32; idx += 256) {
            int i = idx >> 5, k = idx & 31;
            int row = r0 + i;
            As[i * 33 + k] = (row < n) ? A[(long)row * lda + kc + k] : 0.f;
        }
        __syncthreads();
#pragma unroll 8
        for (int k = 0; k < 32; k++) {
            float a[4], w[8];
#pragma unroll
            for (int r = 0; r < 4; r++) a[r] = As[(ty * 4 + r) * 33 + k];
#pragma unroll
            for (int c = 0; c < 8; c++) w[c] = Ws[k * 128 + c * 16 + tx];
#pragma unroll
            for (int r = 0; r < 4; r++)
#pragma unroll
                for (int c = 0; c < 8; c++) acc[r][c] += a[r] * w[c];
        }
        __syncthreads();
    }
#pragma unroll
    for (int r = 0; r < 4; r++) {
        int row = r0 + ty * 4 + r;
        if (row < n) {
#pragma unroll
            for (int c = 0; c < 8; c++) {
                int col = c * 16 + tx;
                float v = acc[r][c] + (bias ? bias[col] : 0.f);
                if (MODE == 0) {
                    if (doRelu) v = fmaxf(v, 0.f);
                    out[(long)row * ldo + col] = v;
                } else {
                    __nv_bfloat16 hi = __float2bfloat16(v);
                    oh[(size_t)row * H + col] = hi;
                    ol[(size_t)row * H + col] = __float2bfloat16(v - __bfloat162float(hi));
                }
            }
        }
    }
}

__global__ __launch_bounds__(256)
void k_gemm(const float* __restrict__ A, int lda,
            const float* __restrict__ W, const float* __restrict__ bias,
            float* __restrict__ out, int ldo, int n, int K, int doRelu) {
    gemm_body<0>(A, lda, W, bias, n, K, doRelu, blockIdx.x * 64, out, ldo, nullptr, nullptr);
}
__global__ __launch_bounds__(256)
void k_gcn_gemm(const float* __restrict__ Abase,
                const float* __restrict__ W0, const float* __restrict__ W1,
                float* __restrict__ outbase) {
    int ei = blockIdx.y;
    gemm_body<0>(Abase + (size_t)ei * N * H, H, ei ? W1 : W0, nullptr, N, H, 0,
                 blockIdx.x * 64, outbase + (size_t)ei * N * H, H, nullptr, nullptr);
}
// 8 projection GEMMs in one launch; epilogue writes bf16 hi/lo directly
__global__ __launch_bounds__(256)
void k_proj(const float* __restrict__ catb, const float* __restrict__ xg,
            const float* __restrict__ Wa, const float* __restrict__ ba,
            __nv_bfloat16* qh, __nv_bfloat16* ql,
            __nv_bfloat16* kh, __nv_bfloat16* kl) {
    int head = blockIdx.y & 3, isK = blockIdx.y >> 2;
    const float* A = isK ? xg : catb;
    int lda = isK ? H : CATW;
    __nv_bfloat16* oh = (isK ? kh : qh) + (size_t)head * NP * H;
    __nv_bfloat16* ol = (isK ? kl : ql) + (size_t)head * NP * H;
    gemm_body<1>(A, lda, Wa + head * H * H, ba + head * H, N, H, 0,
                 blockIdx.x * 64, nullptr, 0, oh, ol);
}

__global__ void k_v2bf(const float* __restrict__ xg, __nv_bfloat16* __restrict__ vb) {
    int i = blockIdx.x * blockDim.x + threadIdx.x;
    if (i < N * H) vb[i] = __float2bfloat16(xg[i]);
}

// ---------------- mma.sync flash attention (KV-split) ----------------
#define QT  128
#define KVT 64
#define RS  136                   // smem row stride (bf16 elements) = 272B
#define BUFB (192 * RS * 2)       // bytes per buffer: khi(64) + klo(64) + v(64) rows
#define SMEM_FA (2 * BUFB)

__global__ void __launch_bounds__(256, 1)
k_flash_mma(const __nv_bfloat16* __restrict__ Qhi, const __nv_bfloat16* __restrict__ Qlo,
            const __nv_bfloat16* __restrict__ Khi, const __nv_bfloat16* __restrict__ Klo,
            const __nv_bfloat16* __restrict__ Vb) {
    extern __shared__ __nv_bfloat16 smfa[];
    const uint32_t sbase = smem_u32(smfa);
    const int tid = threadIdx.x;
    const int w = tid >> 5, lane = tid & 31;
    const int g = lane >> 2, t4 = lane & 3;
    const int head = blockIdx.y;
    const int split = blockIdx.z;
    const int r0 = blockIdx.x * QT;

    const __nv_bfloat16* qhi = Qhi + (size_t)head * NP * H;
    const __nv_bfloat16* qlo = Qlo + (size_t)head * NP * H;
    const __nv_bfloat16* khi = Khi + (size_t)head * NP * H;
    const __nv_bfloat16* klo = Klo + (size_t)head * NP * H;

    const int row_g = r0 + w * 16 + g;
    const int row_h = row_g + 8;

    // --- Q fragments (persist across all tiles) ---
    uint32_t qh[8][4], ql[8][4];
#pragma unroll
    for (int kc = 0; kc < 8; kc++) {
        int c0 = kc * 16 + 2 * t4;
        qh[kc][0] = *(const uint32_t*)(qhi + (size_t)row_g * H + c0);
        qh[kc][1] = *(const uint32_t*)(qhi + (size_t)row_h * H + c0);
        qh[kc][2] = *(const uint32_t*)(qhi + (size_t)row_g * H + c0 + 8);
        qh[kc][3] = *(const uint32_t*)(qhi + (size_t)row_h * H + c0 + 8);
        ql[kc][0] = *(const uint32_t*)(qlo + (size_t)row_g * H + c0);
        ql[kc][1] = *(const uint32_t*)(qlo + (size_t)row_h * H + c0);
        ql[kc][2] = *(const uint32_t*)(qlo + (size_t)row_g * H + c0 + 8);
        ql[kc][3] = *(const uint32_t*)(qlo + (size_t)row_h * H + c0 + 8);
    }

    float o[16][4];
#pragma unroll
    for (int i = 0; i < 16; i++)
#pragma unroll
        for (int j = 0; j < 4; j++) o[i][j] = 0.f;
    float m0 = -1e30f, m1 = -1e30f, l0 = 0.f, l1 = 0.f;

    const int NT = (N + KVT - 1) / KVT;                       // 94
    const int t_lo = (split == 0) ? 0 : (split == 1 ? 31 : 62);
    const int t_hi = (split == 0) ? 31 : (split == 1 ? 62 : NT);

    auto issue_load = [&](int tile, int b) {
        int c0 = tile * KVT;
        uint32_t dbase = sbase + (uint32_t)b * BUFB;
#pragma unroll 4
        for (int i = tid; i < 64 * 16; i += 256) {
            int r = i >> 4, s = i & 15;
            int gr = c0 + r;
            uint32_t sz = (gr < N) ? 16u : 0u;
            int grc = (gr < N) ? gr : (N - 1);
            uint32_t d0 = dbase + (uint32_t)(r * RS * 2 + s * 16);
            cp16(d0,                    khi + (size_t)grc * H + s * 8, sz);
            cp16(d0 + 64 * RS * 2,      klo + (size_t)grc * H + s * 8, sz);
            cp16(d0 + 128 * RS * 2,     Vb  + (size_t)grc * H + s * 8, sz);
        }
        asm volatile("cp.async.commit_group;" ::: "memory");
    };

    issue_load(t_lo, 0);

    for (int t = t_lo; t < t_hi; t++) {
        int b = (t - t_lo) & 1;
        if (t + 1 < t_hi) {
            issue_load(t + 1, b ^ 1);
            asm volatile("cp.async.wait_group 1;" ::: "memory");
        } else {
            asm volatile("cp.async.wait_group 0;" ::: "memory");
        }
        __syncthreads();

        uint32_t kb = sbase + (uint32_t)b * BUFB;
        float c[8][4];
#pragma unroll
        for (int i = 0; i < 8; i++)
#pragma unroll
            for (int j = 0; j < 4; j++) c[i][j] = 0.f;

        const int jj = lane >> 3, rr = lane & 7;
#pragma unroll
        for (int nb2 = 0; nb2 < 4; nb2++) {
#pragma unroll
            for (int kc = 0; kc < 8; kc++) {
                uint32_t addr = kb + (uint32_t)(((nb2 * 16 + ((jj >> 1) << 3) + rr) * RS +
                                                kc * 16 + ((jj & 1) << 3)) * 2);
                uint32_t h0, h1, h2, h3, e0, e1, e2, e3;
                ldm_x4(h0, h1, h2, h3, addr);
                ldm_x4(e0, e1, e2, e3, addr + 64 * RS * 2);
                mma16816(c[2 * nb2],     qh[kc], h0, h1);
                mma16816(c[2 * nb2 + 1], qh[kc], h2, h3);
                mma16816(c[2 * nb2],     ql[kc], h0, h1);
                mma16816(c[2 * nb2 + 1], ql[kc], h2, h3);
                mma16816(c[2 * nb2],     qh[kc], e0, e1);
                mma16816(c[2 * nb2 + 1], qh[kc], e2, e3);
            }
        }

        // ---- online softmax ----
        float tm0 = -1e30f, tm1 = -1e30f;
#pragma unroll
        for (int nb = 0; nb < 8; nb++) {
            tm0 = fmaxf(tm0, fmaxf(c[nb][0], c[nb][1]));
            tm1 = fmaxf(tm1, fmaxf(c[nb][2], c[nb][3]));
        }
        tm0 = fmaxf(tm0, __shfl_xor_sync(0xffffffffu, tm0, 1));
        tm0 = fmaxf(tm0, __shfl_xor_sync(0xffffffffu, tm0, 2));
        tm1 = fmaxf(tm1, __shfl_xor_sync(0xffffffffu, tm1, 1));
        tm1 = fmaxf(tm1, __shfl_xor_sync(0xffffffffu, tm1, 2));
        float mn0 = fmaxf(m0, tm0), mn1 = fmaxf(m1, tm1);
        float sc0 = __expf(m0 - mn0), sc1 = __expf(m1 - mn1);
        m0 = mn0; m1 = mn1;

        uint32_t pa[4][4];
        float rs0 = 0.f, rs1 = 0.f;
        const bool tail = (t == NT - 1);
        const int cc0 = t * KVT;
#pragma unroll
        for (int kc2 = 0; kc2 < 4; kc2++) {
            int nA = 2 * kc2, nB = nA + 1;
            float pA0 = __expf(c[nA][0] - mn0), pA1 = __expf(c[nA][1] - mn0);
            float pA2 = __expf(c[nA][2] - mn1), pA3 = __expf(c[nA][3] - mn1);
            float pB0 = __expf(c[nB][0] - mn0), pB1 = __expf(c[nB][1] - mn0);
            float pB2 = __expf(c[nB][2] - mn1), pB3 = __expf(c[nB][3] - mn1);
            if (tail) {
                int jA = cc0 + nA * 8 + 2 * t4, jB = cc0 + nB * 8 + 2 * t4;
                if (jA     >= N) { pA0 = 0.f; pA2 = 0.f; }
                if (jA + 1 >= N) { pA1 = 0.f; pA3 = 0.f; }
                if (jB     >= N) { pB0 = 0.f; pB2 = 0.f; }
                if (jB + 1 >= N) { pB1 = 0.f; pB3 = 0.f; }
            }
            rs0 += pA0 + pA1 + pB0 + pB1;
            rs1 += pA2 + pA3 + pB2 + pB3;
            pa[kc2][0] = packbf(pA0, pA1);
            pa[kc2][1] = packbf(pA2, pA3);
            pa[kc2][2] = packbf(pB0, pB1);
            pa[kc2][3] = packbf(pB2, pB3);
        }
        l0 = l0 * sc0 + rs0;
        l1 = l1 * sc1 + rs1;
#pragma unroll
        for (int i = 0; i < 16; i++) {
            o[i][0] *= sc0; o[i][1] *= sc0;
            o[i][2] *= sc1; o[i][3] *= sc1;
        }

        // ---- O += P @ V ----
        uint32_t vbb = kb + 128 * RS * 2;
#pragma unroll
        for (int nb2 = 0; nb2 < 8; nb2++) {
#pragma unroll
            for (int kc2 = 0; kc2 < 4; kc2++) {
                uint32_t addr = vbb + (uint32_t)(((kc2 * 16 + ((jj & 1) << 3) + rr) * RS +
                                                 nb2 * 16 + ((jj >> 1) << 3)) * 2);
                uint32_t v0, v1, v2, v3;
                ldm_x4t(v0, v1, v2, v3, addr);
                mma16816(o[2 * nb2],     pa[kc2], v0, v1);
                mma16816(o[2 * nb2 + 1], pa[kc2], v2, v3);
            }
        }
        __syncthreads();
    }

    // ---- write raw partials (no normalization) ----
    l0 += __shfl_xor_sync(0xffffffffu, l0, 1);
    l0 += __shfl_xor_sync(0xffffffffu, l0, 2);
    l1 += __shfl_xor_sync(0xffffffffu, l1, 1);
    l1 += __shfl_xor_sync(0xffffffffu, l1, 2);

    size_t pbase = (size_t)(split * NHEADS + head) * NP;
    if (row_g < N) {
        float* p = g_po + (pbase + row_g) * H;
#pragma unroll
        for (int nb = 0; nb < 16; nb++)
            *(float2*)(p + nb * 8 + 2 * t4) = make_float2(o[nb][0], o[nb][1]);
        if (t4 == 0) { g_pm[pbase + row_g] = m0; g_pl[pbase + row_g] = l0; }
    }
    if (row_h < N) {
        float* p = g_po + (pbase + row_h) * H;
#pragma unroll
        for (int nb = 0; nb < 16; nb++)
            *(float2*)(p + nb * 8 + 2 * t4) = make_float2(o[nb][2], o[nb][3]);
        if (t4 == 0) { g_pm[pbase + row_h] = m1; g_pl[pbase + row_h] = l1; }
    }
}

// merge KV-split partials into cat
__global__ void k_combine(float* __restrict__ catb) {
    int row = blockIdx.x, head = blockIdx.y, t = threadIdx.x;
    size_t i0 = (size_t)(0 * NHEADS + head) * NP + row;
    size_t i1 = (size_t)(1 * NHEADS + head) * NP + row;
    size_t i2 = (size_t)(2 * NHEADS + head) * NP + row;
    float m0 = g_pm[i0], m1 = g_pm[i1], m2 = g_pm[i2];
    float mm = fmaxf(m0, fmaxf(m1, m2));
    float w0 = __expf(m0 - mm), w1 = __expf(m1 - mm), w2 = __expf(m2 - mm);
    float L = g_pl[i0] * w0 + g_pl[i1] * w1 + g_pl[i2] * w2;
    float v = (g_po[i0 * H + t] * w0 + g_po[i1 * H + t] * w1 + g_po[i2 * H + t] * w2) / L;
    catb[(size_t)row * CATW + H + head * H + t] = v;
}

// ---------------- output projection (128 -> 3) ----------------
__global__ void k_out3(const float* __restrict__ h, const float* __restrict__ W,
                       const float* __restrict__ b, float* __restrict__ out) {
    __shared__ float red[3][128];
    int v = blockIdx.x, t = threadIdx.x;
    float hv = h[v * H + t];
    red[0][t] = hv * W[t * 3 + 0];
    red[1][t] = hv * W[t * 3 + 1];
    red[2][t] = hv * W[t * 3 + 2];
    __syncthreads();
    for (int ofs = 64; ofs > 0; ofs >>= 1) {
        if (t < ofs) {
            red[0][t] += red[0][t + ofs];
            red[1][t] += red[1][t + ofs];
            red[2][t] += red[2][t + ofs];
        }
        __syncthreads();
    }
    if (t < 3) out[v * 3 + t] = red[t][0] + b[t];
}

// ---------------- host ----------------
static void* symAddr(const void* s) {
    void* p = nullptr;
    cudaGetSymbolAddress(&p, s);
    return p;
}

extern "C" void kernel_launch(void* const* d_in, const int* in_sizes, int n_in,
                              void* d_out, int out_size) {
    const float* x_resting = (const float*)d_in[0];
    const float* x_rigid   = (const float*)d_in[1];
    const int*   e_rest    = (const int*)d_in[2];
    const int*   e_rig     = (const int*)d_in[3];
    const float* Wr0 = (const float*)d_in[4];
    const float* br0 = (const float*)d_in[5];
    const float* Wr  = (const float*)d_in[6];
    const float* br  = (const float*)d_in[7];
    const float* Wg0 = (const float*)d_in[8];
    const float* bg0 = (const float*)d_in[9];
    const float* Wg  = (const float*)d_in[10];
    const float* bg  = (const float*)d_in[11];
    const float* Wa  = (const float*)d_in[12];
    const float* ba  = (const float*)d_in[13];
    const float* Wd0 = (const float*)d_in[14];
    const float* bd0 = (const float*)d_in[15];
    const float* Wd  = (const float*)d_in[16];
    const float* bd  = (const float*)d_in[17];
    const float* Wout= (const float*)d_in[18];
    const float* bout= (const float*)d_in[19];
    float* out = (float*)d_out;

    int*   degB = (int*)symAddr(g_deg);
    int*   offB = (int*)symAddr(g_off);
    int*   cntB = (int*)symAddr(g_cnt);
    int*   srcB = (int*)symAddr(g_src);
    float* nrmB = (float*)symAddr(g_nrm);
    float* dinvB= (float*)symAddr(g_dinv);
    float* hw   = (float*)symAddr(g_hw);
    float* ha   = (float*)symAddr(g_ha);
    float* hb   = (float*)symAddr(g_hb);
    float* xg   = (float*)symAddr(g_xg);
    float* cat  = (float*)symAddr(g_cat);
    float* d1   = (float*)symAddr(g_d1);
    float* d2   = (float*)symAddr(g_d2);
    __nv_bfloat16* qhi = (__nv_bfloat16*)symAddr(g_qhi);
    __nv_bfloat16* qlo = (__nv_bfloat16*)symAddr(g_qlo);
    __nv_bfloat16* khi = (__nv_bfloat16*)symAddr(g_khi);
    __nv_bfloat16* klo = (__nv_bfloat16*)symAddr(g_klo);
    __nv_bfloat16* vbf = (__nv_bfloat16*)symAddr(g_vbf);

    const int TB = 256;
    const int GN2 = (2 * N + TB - 1) / TB;
    const int GE  = (E + TB - 1) / TB;
    const int GEN = (EN + TB - 1) / TB;
    const int GB  = (N + 63) / 64;    // 94

    // ------- graph prep, both encoders in each launch -------
    k_deg_init<<<GN2, TB>>>(degB);
    k_deg_count2<<<dim3(GE, 2), TB>>>(e_rest + E, e_rig + E, degB);
    k_dinv<<<GN2, TB>>>(degB, dinvB);
    k_scan2<<<2, 1024>>>(degB, offB);
    k_zero_cnt<<<GN2, TB>>>(cntB);
    k_fill2<<<dim3(GEN, 2), TB>>>(e_rest, e_rig, offB, cntB, dinvB, srcB, nrmB);

    // ------- GCN encoders, merged -------
    k_in3_2<<<dim3(N, 2), H>>>(x_resting, x_rigid, Wr0, Wg0, hw);
    k_agg2<<<dim3(N, 2), H>>>(hw, offB, srcB, nrmB, br0, bg0, ha, H, ha + N * H, H);
    k_gcn_gemm<<<dim3(GB, 2), 256>>>(ha, Wr, Wg, hw);
    k_agg2<<<dim3(N, 2), H>>>(hw, offB, srcB, nrmB, br, bg, hb, H, hb + N * H, H);
    k_gcn_gemm<<<dim3(GB, 2), 256>>>(hb, Wr + H * H, Wg + H * H, hw);
    k_agg2<<<dim3(N, 2), H>>>(hw, offB, srcB, nrmB, br + H, bg + H, cat, CATW, xg, H);

    // ------- attention projections (8 GEMMs, one launch, bf16 hi/lo epilogue) -------
    k_proj<<<dim3(GB, 8), 256>>>(cat, xg, Wa, ba, qhi, qlo, khi, klo);
    k_v2bf<<<(N * H + 255) / 256, 256>>>(xg, vbf);

    // ------- flash attention, 3-way KV split + combine -------
    cudaFuncSetAttribute(k_flash_mma, cudaFuncAttributeMaxDynamicSharedMemorySize, SMEM_FA);
    k_flash_mma<<<dim3((N + QT - 1) / QT, NHEADS, NSPLIT), 256, SMEM_FA>>>(qhi, qlo, khi, klo, vbf);
    k_combine<<<dim3(N, NHEADS), H>>>(cat);

    // ------- decoder -------
    k_gemm<<<GB, 256>>>(cat, CATW, Wd0, bd0, d1, H, N, CATW, 1);
    k_gemm<<<GB, 256>>>(d1, H, Wd, bd, d2, H, N, H, 1);
    k_gemm<<<GB, 256>>>(d2, H, Wd + H * H, bd + H, d1, H, N, H, 1);
    k_out3<<<N, H>>>(d1, Wout, bout, out);
}

// round 11
// speedup vs baseline: 4.3968x; 1.1944x over previous
#include <cuda_runtime.h>
#include <cuda_bf16.h>
#include <math.h>
#include <stdint.h>

#define N 6000
#define NP 6016
#define E 192000
#define H 128
#define NHEADS 4
#define EN (E + N)
#define CATW (H * (NHEADS + 1))   // 640
#define NSPLIT 3

// ---------------- device scratch ----------------
__device__ int   g_deg[2][N];
__device__ int   g_off[2][N + 1];
__device__ int   g_cnt[2][N];
__device__ int   g_src[2][EN];
__device__ float g_nrm[2][EN];
__device__ float g_dinv[2][N];
__device__ __align__(16) float g_hw[2][N * H];
__device__ __align__(16) float g_ha[2][N * H];
__device__ __align__(16) float g_hb[2][N * H];
__device__ __align__(16) float g_xg[N * H];
__device__ __align__(16) float g_cat[N * CATW];
__device__ __align__(16) float g_d1[N * H];
__device__ __align__(16) float g_d2[N * H];
// bf16 attention operands (padded to NP rows; pads stay zero)
__device__ __align__(16) __nv_bfloat16 g_qhi[NHEADS * NP * H];
__device__ __align__(16) __nv_bfloat16 g_qlo[NHEADS * NP * H];
__device__ __align__(16) __nv_bfloat16 g_khi[NHEADS * NP * H];
__device__ __align__(16) __nv_bfloat16 g_klo[NHEADS * NP * H];
__device__ __align__(16) __nv_bfloat16 g_vbf[NP * H];
// flash partials (KV-split)
__device__ __align__(16) float g_po[NSPLIT * NHEADS * NP * H];
__device__ float g_pm[NSPLIT * NHEADS * NP];
__device__ float g_pl[NSPLIT * NHEADS * NP];

// ---------------- small helpers ----------------
__device__ __forceinline__ uint32_t smem_u32(const void* p) {
    uint32_t a;
    asm("{ .reg .u64 t; cvta.to.shared.u64 t, %1; cvt.u32.u64 %0, t; }" : "=r"(a) : "l"(p));
    return a;
}
__device__ __forceinline__ void mma16816(float* c, const uint32_t* a, uint32_t b0, uint32_t b1) {
    asm volatile(
        "mma.sync.aligned.m16n8k16.row.col.f32.bf16.bf16.f32 "
        "{%0,%1,%2,%3}, {%4,%5,%6,%7}, {%8,%9}, {%0,%1,%2,%3};"
        : "+f"(c[0]), "+f"(c[1]), "+f"(c[2]), "+f"(c[3])
        : "r"(a[0]), "r"(a[1]), "r"(a[2]), "r"(a[3]), "r"(b0), "r"(b1));
}
__device__ __forceinline__ void ldm_x4(uint32_t& r0, uint32_t& r1, uint32_t& r2, uint32_t& r3,
                                       uint32_t addr) {
    asm volatile("ldmatrix.sync.aligned.m8n8.x4.shared.b16 {%0,%1,%2,%3}, [%4];"
                 : "=r"(r0), "=r"(r1), "=r"(r2), "=r"(r3) : "r"(addr));
}
__device__ __forceinline__ void ldm_x4t(uint32_t& r0, uint32_t& r1, uint32_t& r2, uint32_t& r3,
                                        uint32_t addr) {
    asm volatile("ldmatrix.sync.aligned.m8n8.x4.trans.shared.b16 {%0,%1,%2,%3}, [%4];"
                 : "=r"(r0), "=r"(r1), "=r"(r2), "=r"(r3) : "r"(addr));
}
__device__ __forceinline__ void cp16(uint32_t dst, const void* src, uint32_t sz) {
    asm volatile("cp.async.cg.shared.global [%0], [%1], 16, %2;"
                 :: "r"(dst), "l"(src), "r"(sz) : "memory");
}
__device__ __forceinline__ uint32_t packbf(float a, float b) {
    __nv_bfloat162 v = __floats2bfloat162_rn(a, b);
    return *reinterpret_cast<uint32_t*>(&v);
}
__device__ __forceinline__ void split2(float2 v, uint32_t& hi, uint32_t& lo) {
    __nv_bfloat16 hx = __float2bfloat16(v.x), hy = __float2bfloat16(v.y);
    __nv_bfloat162 h2 = __nv_bfloat162(hx, hy);
    hi = *reinterpret_cast<uint32_t*>(&h2);
    lo = packbf(v.x - __bfloat162float(hx), v.y - __bfloat162float(hy));
}

// ---------------- graph preprocessing (both encoders merged) ----------------
__global__ void k_deg_init(int* deg) {
    int i = blockIdx.x * blockDim.x + threadIdx.x;
    if (i < 2 * N) deg[i] = 1;
}
__global__ void k_deg_count2(const int* __restrict__ col0, const int* __restrict__ col1,
                             int* deg) {
    int e = blockIdx.x * blockDim.x + threadIdx.x;
    int ei = blockIdx.y;
    const int* col = ei ? col1 : col0;
    if (e < E) atomicAdd(&deg[ei * N + col[e]], 1);
}
__global__ void k_dinv(const int* __restrict__ deg, float* dinv) {
    int i = blockIdx.x * blockDim.x + threadIdx.x;
    if (i < 2 * N) dinv[i] = rsqrtf((float)deg[i]);
}
__global__ void k_zero_cnt(int* cnt) {
    int i = blockIdx.x * blockDim.x + threadIdx.x;
    if (i < 2 * N) cnt[i] = 0;
}
__global__ void k_scan2(const int* __restrict__ degAll, int* __restrict__ offAll) {
    int ei = blockIdx.x;
    const int* deg = degAll + ei * N;
    int* off = offAll + ei * (N + 1);
    __shared__ int wsum[32];
    int tid = threadIdx.x, lane = tid & 31, wid = tid >> 5;
    const int C = (N + 1023) / 1024;          // 6
    int base = tid * C;
    int loc[C];
    int s = 0;
#pragma unroll
    for (int i = 0; i < C; i++) {
        int idx = base + i;
        loc[i] = (idx < N) ? deg[idx] : 0;
        s += loc[i];
    }
    int inc = s;
#pragma unroll
    for (int d = 1; d < 32; d <<= 1) {
        int v = __shfl_up_sync(0xffffffffu, inc, d);
        if (lane >= d) inc += v;
    }
    if (lane == 31) wsum[wid] = inc;
    __syncthreads();
    if (wid == 0) {
        int v = wsum[lane];
#pragma unroll
        for (int d = 1; d < 32; d <<= 1) {
            int u = __shfl_up_sync(0xffffffffu, v, d);
            if (lane >= d) v += u;
        }
        wsum[lane] = v;
    }
    __syncthreads();
    int run = inc - s + (wid > 0 ? wsum[wid - 1] : 0);
#pragma unroll
    for (int i = 0; i < C; i++) {
        int idx = base + i;
        if (idx < N) { off[idx] = run; run += loc[i]; }
    }
    if (tid == 1023) off[N] = run;
}
__global__ void k_fill2(const int* __restrict__ ed0, const int* __restrict__ ed1,
                        const int* __restrict__ offB, int* cntB,
                        const float* __restrict__ dinvB,
                        int* __restrict__ srcB, float* __restrict__ nrmB) {
    int e = blockIdx.x * blockDim.x + threadIdx.x;
    if (e >= EN) return;
    int ei = blockIdx.y;
    const int* edges = ei ? ed1 : ed0;
    const int* off  = offB + ei * (N + 1);
    int* cnt        = cntB + ei * N;
    const float* dinv = dinvB + ei * N;
    int* src        = srcB + (size_t)ei * EN;
    float* nrm      = nrmB + (size_t)ei * EN;
    int r, c;
    if (e < E) { r = edges[e]; c = edges[E + e]; }
    else       { r = c = e - E; }
    int pos = off[c] + atomicAdd(&cnt[c], 1);
    src[pos] = r;
    nrm[pos] = dinv[r] * dinv[c];
}

// ---------------- GCN input + aggregation ----------------
__global__ void k_in3_2(const float* __restrict__ x0, const float* __restrict__ x1,
                        const float* __restrict__ W0, const float* __restrict__ W1,
                        float* __restrict__ hwB) {
    int ei = blockIdx.y;
    const float* x = ei ? x1 : x0;
    const float* W = ei ? W1 : W0;
    int v = blockIdx.x, t = threadIdx.x;
    float a0 = x[v * 3 + 0], a1 = x[v * 3 + 1], a2 = x[v * 3 + 2];
    hwB[(size_t)ei * N * H + v * H + t] = a0 * W[t] + a1 * W[H + t] + a2 * W[2 * H + t];
}
// vectorized aggregate: 4 warps over neighbors, float4 per thread, smem reduce
__global__ void k_agg2v(const float* __restrict__ hwB, const int* __restrict__ offB,
                        const int* __restrict__ srcB, const float* __restrict__ nrmB,
                        const float* __restrict__ bias0, const float* __restrict__ bias1,
                        float* out0, int ldo0, float* out1, int ldo1,
                        __nv_bfloat16* vb1) {
    __shared__ float4 part[4][32];
    int ei = blockIdx.y;
    const float4* hw4 = (const float4*)(hwB + (size_t)ei * N * H);
    const int*   off = offB + ei * (N + 1);
    const int*   src = srcB + (size_t)ei * EN;
    const float* nrm = nrmB + (size_t)ei * EN;
    int v = blockIdx.x, tid = threadIdx.x, w = tid >> 5, lane = tid & 31;
    int s = off[v], e = off[v + 1];
    float4 acc = make_float4(0.f, 0.f, 0.f, 0.f);
    for (int j = s + w; j < e; j += 4) {
        int   sj = __ldg(&src[j]);
        float nj = __ldg(&nrm[j]);
        float4 x = hw4[(size_t)sj * 32 + lane];
        acc.x += x.x * nj; acc.y += x.y * nj; acc.z += x.z * nj; acc.w += x.w * nj;
    }
    part[w][lane] = acc;
    __syncthreads();
    if (w == 0) {
        float4 a = part[0][lane], b = part[1][lane], c = part[2][lane], d = part[3][lane];
        const float* bias = ei ? bias1 : bias0;
        float4 bb = *(const float4*)(bias + lane * 4);
        float r0 = fmaxf(a.x + b.x + c.x + d.x + bb.x, 0.f);
        float r1 = fmaxf(a.y + b.y + c.y + d.y + bb.y, 0.f);
        float r2 = fmaxf(a.z + b.z + c.z + d.z + bb.z, 0.f);
        float r3 = fmaxf(a.w + b.w + c.w + d.w + bb.w, 0.f);
        float* out = ei ? out1 : out0;
        int ldo = ei ? ldo1 : ldo0;
        *(float4*)(out + (size_t)v * ldo + lane * 4) = make_float4(r0, r1, r2, r3);
        if (ei == 1 && vb1) {
            uint2 p = make_uint2(packbf(r0, r1), packbf(r2, r3));
            *(uint2*)((char*)vb1 + ((size_t)v * H + lane * 4) * 2) = p;
        }
    }
}

// ---------------- tensor-core GEMM (bf16 hi/lo, fp32-accurate) ----------------
// out[n x 128] = A[n x K] @ W[K x 128]; per CTA: 128 rows, all 128 cols.
#define RS2 136
#define WLOFF (128 * RS2 * 2)     // byte offset of Wl within smem
#define SMEM_TG (2 * 128 * RS2 * 2)   // 69632 B

// MODE 0: fp32 store (+optional relu). MODE 1: bf16 hi/lo split store (ld H).
template<int MODE>
__device__ __forceinline__ void tgemm_body(
    char* sm, const float* __restrict__ A, int lda,
    const float* __restrict__ W, const float* __restrict__ bias,
    int doRelu, int r0, float* out, int ldo,
    __nv_bfloat16* oh, __nv_bfloat16* ol, int K) {
    const uint32_t sb = smem_u32(sm);
    const int tid = threadIdx.x;
    const int w = tid >> 5, lane = tid & 31;
    const int g = lane >> 2, t4 = lane & 3;
    const int jj = lane >> 3, rr = lane & 7;
    const int row_g = r0 + w * 16 + g;
    const int row_h = row_g + 8;
    const int rg = (row_g < N) ? row_g : (N - 1);
    const int rh = (row_h < N) ? row_h : (N - 1);

    float o[16][4];
#pragma unroll
    for (int i = 0; i < 16; i++)
#pragma unroll
        for (int j = 0; j < 4; j++) o[i][j] = 0.f;

    for (int kc0 = 0; kc0 < K; kc0 += 128) {
        if (kc0 > 0) __syncthreads();
        // stage W chunk [kc0..kc0+128) x 128 as bf16 hi/lo
        const float4* W4 = (const float4*)(W + (size_t)kc0 * 128);
        for (int i = tid; i < 128 * 32; i += 256) {
            int k = i >> 5, c4 = (i & 31) << 2;
            float4 wv = W4[i];
            uint32_t h0, l0, h1, l1;
            split2(make_float2(wv.x, wv.y), h0, l0);
            split2(make_float2(wv.z, wv.w), h1, l1);
            uint32_t off = (uint32_t)(k * RS2 + c4) * 2;
            *(uint2*)(sm + off)         = make_uint2(h0, h1);
            *(uint2*)(sm + WLOFF + off) = make_uint2(l0, l1);
        }
        __syncthreads();

        // A fragments for this chunk (hi/lo, direct from gmem fp32)
        uint32_t ah[8][4], al[8][4];
#pragma unroll
        for (int kc = 0; kc < 8; kc++) {
            int c0 = kc0 + kc * 16 + 2 * t4;
            split2(*(const float2*)(A + (size_t)rg * lda + c0),     ah[kc][0], al[kc][0]);
            split2(*(const float2*)(A + (size_t)rh * lda + c0),     ah[kc][1], al[kc][1]);
            split2(*(const float2*)(A + (size_t)rg * lda + c0 + 8), ah[kc][2], al[kc][2]);
            split2(*(const float2*)(A + (size_t)rh * lda + c0 + 8), ah[kc][3], al[kc][3]);
        }

#pragma unroll
        for (int nb2 = 0; nb2 < 8; nb2++) {
#pragma unroll
            for (int kc = 0; kc < 8; kc++) {
                uint32_t addr = sb + (uint32_t)(((kc * 16 + ((jj & 1) << 3) + rr) * RS2 +
                                                nb2 * 16 + ((jj >> 1) << 3)) * 2);
                uint32_t b0, b1, b2, b3, d0, d1, d2, d3;
                ldm_x4t(b0, b1, b2, b3, addr);
                ldm_x4t(d0, d1, d2, d3, addr + WLOFF);
                mma16816(o[2 * nb2],     ah[kc], b0, b1);
                mma16816(o[2 * nb2 + 1], ah[kc], b2, b3);
                mma16816(o[2 * nb2],     al[kc], b0, b1);
                mma16816(o[2 * nb2 + 1], al[kc], b2, b3);
                mma16816(o[2 * nb2],     ah[kc], d0, d1);
                mma16816(o[2 * nb2 + 1], ah[kc], d2, d3);
            }
        }
    }

#pragma unroll
    for (int nb = 0; nb < 16; nb++) {
        int col = nb * 8 + 2 * t4;
        float2 bz = bias ? *(const float2*)(bias + col) : make_float2(0.f, 0.f);
        float v0 = o[nb][0] + bz.x, v1 = o[nb][1] + bz.y;
        float v2 = o[nb][2] + bz.x, v3 = o[nb][3] + bz.y;
        if (MODE == 0) {
            if (doRelu) {
                v0 = fmaxf(v0, 0.f); v1 = fmaxf(v1, 0.f);
                v2 = fmaxf(v2, 0.f); v3 = fmaxf(v3, 0.f);
            }
            if (row_g < N) *(float2*)(out + (size_t)row_g * ldo + col) = make_float2(v0, v1);
            if (row_h < N) *(float2*)(out + (size_t)row_h * ldo + col) = make_float2(v2, v3);
        } else {
            if (row_g < N) {
                uint32_t hi, lo;
                split2(make_float2(v0, v1), hi, lo);
                *(uint32_t*)((char*)oh + ((size_t)row_g * H + col) * 2) = hi;
                *(uint32_t*)((char*)ol + ((size_t)row_g * H + col) * 2) = lo;
            }
            if (row_h < N) {
                uint32_t hi, lo;
                split2(make_float2(v2, v3), hi, lo);
                *(uint32_t*)((char*)oh + ((size_t)row_h * H + col) * 2) = hi;
                *(uint32_t*)((char*)ol + ((size_t)row_h * H + col) * 2) = lo;
            }
        }
    }
}

__global__ __launch_bounds__(256)
void k_tg_gcn(const float* __restrict__ Abase,
              const float* __restrict__ W0, const float* __restrict__ W1,
              float* __restrict__ outbase) {
    extern __shared__ char sm[];
    int ei = blockIdx.y;
    tgemm_body<0>(sm, Abase + (size_t)ei * N * H, H, ei ? W1 : W0, nullptr, 0,
                  blockIdx.x * 128, outbase + (size_t)ei * N * H, H, nullptr, nullptr, H);
}
__global__ __launch_bounds__(256)
void k_tg_proj(const float* __restrict__ catb, const float* __restrict__ xg,
               const float* __restrict__ Wa, const float* __restrict__ ba,
               __nv_bfloat16* qh, __nv_bfloat16* ql,
               __nv_bfloat16* kh, __nv_bfloat16* kl) {
    extern __shared__ char sm[];
    int head = blockIdx.y & 3, isK = blockIdx.y >> 2;
    tgemm_body<1>(sm, isK ? xg : catb, isK ? H : CATW, Wa + head * H * H, ba + head * H, 0,
                  blockIdx.x * 128, nullptr, 0,
                  (isK ? kh : qh) + (size_t)head * NP * H,
                  (isK ? kl : ql) + (size_t)head * NP * H, H);
}
__global__ __launch_bounds__(256)
void k_tg(const float* __restrict__ A, int lda,
          const float* __restrict__ W, const float* __restrict__ bias,
          float* __restrict__ out, int K, int doRelu) {
    extern __shared__ char sm[];
    tgemm_body<0>(sm, A, lda, W, bias, doRelu, blockIdx.x * 128, out, H, nullptr, nullptr, K);
}

// ---------------- mma.sync flash attention (KV-split) ----------------
#define QT  128
#define KVT 64
#define RS  136                   // smem row stride (bf16 elements) = 272B
#define BUFB (192 * RS * 2)       // bytes per buffer: khi(64) + klo(64) + v(64) rows
#define SMEM_FA (2 * BUFB)

__global__ void __launch_bounds__(256, 1)
k_flash_mma(const __nv_bfloat16* __restrict__ Qhi, const __nv_bfloat16* __restrict__ Qlo,
            const __nv_bfloat16* __restrict__ Khi, const __nv_bfloat16* __restrict__ Klo,
            const __nv_bfloat16* __restrict__ Vb) {
    extern __shared__ __nv_bfloat16 smfa[];
    const uint32_t sbase = smem_u32(smfa);
    const int tid = threadIdx.x;
    const int w = tid >> 5, lane = tid & 31;
    const int g = lane >> 2, t4 = lane & 3;
    const int head = blockIdx.y;
    const int split = blockIdx.z;
    const int r0 = blockIdx.x * QT;

    const __nv_bfloat16* qhi = Qhi + (size_t)head * NP * H;
    const __nv_bfloat16* qlo = Qlo + (size_t)head * NP * H;
    const __nv_bfloat16* khi = Khi + (size_t)head * NP * H;
    const __nv_bfloat16* klo = Klo + (size_t)head * NP * H;

    const int row_g = r0 + w * 16 + g;
    const int row_h = row_g + 8;

    uint32_t qh[8][4], ql[8][4];
#pragma unroll
    for (int kc = 0; kc < 8; kc++) {
        int c0 = kc * 16 + 2 * t4;
        qh[kc][0] = *(const uint32_t*)(qhi + (size_t)row_g * H + c0);
        qh[kc][1] = *(const uint32_t*)(qhi + (size_t)row_h * H + c0);
        qh[kc][2] = *(const uint32_t*)(qhi + (size_t)row_g * H + c0 + 8);
        qh[kc][3] = *(const uint32_t*)(qhi + (size_t)row_h * H + c0 + 8);
        ql[kc][0] = *(const uint32_t*)(qlo + (size_t)row_g * H + c0);
        ql[kc][1] = *(const uint32_t*)(qlo + (size_t)row_h * H + c0);
        ql[kc][2] = *(const uint32_t*)(qlo + (size_t)row_g * H + c0 + 8);
        ql[kc][3] = *(const uint32_t*)(qlo + (size_t)row_h * H + c0 + 8);
    }

    float o[16][4];
#pragma unroll
    for (int i = 0; i < 16; i++)
#pragma unroll
        for (int j = 0; j < 4; j++) o[i][j] = 0.f;
    float m0 = -1e30f, m1 = -1e30f, l0 = 0.f, l1 = 0.f;

    const int NT = (N + KVT - 1) / KVT;                       // 94
    const int t_lo = (split == 0) ? 0 : (split == 1 ? 31 : 62);
    const int t_hi = (split == 0) ? 31 : (split == 1 ? 62 : NT);

    auto issue_load = [&](int tile, int b) {
        int c0 = tile * KVT;
        uint32_t dbase = sbase + (uint32_t)b * BUFB;
#pragma unroll 4
        for (int i = tid; i < 64 * 16; i += 256) {
            int r = i >> 4, s = i & 15;
            int gr = c0 + r;
            uint32_t sz = (gr < N) ? 16u : 0u;
            int grc = (gr < N) ? gr : (N - 1);
            uint32_t d0 = dbase + (uint32_t)(r * RS * 2 + s * 16);
            cp16(d0,                    khi + (size_t)grc * H + s * 8, sz);
            cp16(d0 + 64 * RS * 2,      klo + (size_t)grc * H + s * 8, sz);
            cp16(d0 + 128 * RS * 2,     Vb  + (size_t)grc * H + s * 8, sz);
        }
        asm volatile("cp.async.commit_group;" ::: "memory");
    };

    issue_load(t_lo, 0);

    for (int t = t_lo; t < t_hi; t++) {
        int b = (t - t_lo) & 1;
        if (t + 1 < t_hi) {
            issue_load(t + 1, b ^ 1);
            asm volatile("cp.async.wait_group 1;" ::: "memory");
        } else {
            asm volatile("cp.async.wait_group 0;" ::: "memory");
        }
        __syncthreads();

        uint32_t kb = sbase + (uint32_t)b * BUFB;
        float c[8][4];
#pragma unroll
        for (int i = 0; i < 8; i++)
#pragma unroll
            for (int j = 0; j < 4; j++) c[i][j] = 0.f;

        const int jj = lane >> 3, rr = lane & 7;
#pragma unroll
        for (int nb2 = 0; nb2 < 4; nb2++) {
#pragma unroll
            for (int kc = 0; kc < 8; kc++) {
                uint32_t addr = kb + (uint32_t)(((nb2 * 16 + ((jj >> 1) << 3) + rr) * RS +
                                                kc * 16 + ((jj & 1) << 3)) * 2);
                uint32_t h0, h1, h2, h3, e0, e1, e2, e3;
                ldm_x4(h0, h1, h2, h3, addr);
                ldm_x4(e0, e1, e2, e3, addr + 64 * RS * 2);
                mma16816(c[2 * nb2],     qh[kc], h0, h1);
                mma16816(c[2 * nb2 + 1], qh[kc], h2, h3);
                mma16816(c[2 * nb2],     ql[kc], h0, h1);
                mma16816(c[2 * nb2 + 1], ql[kc], h2, h3);
                mma16816(c[2 * nb2],     qh[kc], e0, e1);
                mma16816(c[2 * nb2 + 1], qh[kc], e2, e3);
            }
        }

        float tm0 = -1e30f, tm1 = -1e30f;
#pragma unroll
        for (int nb = 0; nb < 8; nb++) {
            tm0 = fmaxf(tm0, fmaxf(c[nb][0], c[nb][1]));
            tm1 = fmaxf(tm1, fmaxf(c[nb][2], c[nb][3]));
        }
        tm0 = fmaxf(tm0, __shfl_xor_sync(0xffffffffu, tm0, 1));
        tm0 = fmaxf(tm0, __shfl_xor_sync(0xffffffffu, tm0, 2));
        tm1 = fmaxf(tm1, __shfl_xor_sync(0xffffffffu, tm1, 1));
        tm1 = fmaxf(tm1, __shfl_xor_sync(0xffffffffu, tm1, 2));
        float mn0 = fmaxf(m0, tm0), mn1 = fmaxf(m1, tm1);
        float sc0 = __expf(m0 - mn0), sc1 = __expf(m1 - mn1);
        m0 = mn0; m1 = mn1;

        uint32_t pa[4][4];
        float rs0 = 0.f, rs1 = 0.f;
        const bool tail = (t == NT - 1);
        const int cc0 = t * KVT;
#pragma unroll
        for (int kc2 = 0; kc2 < 4; kc2++) {
            int nA = 2 * kc2, nB = nA + 1;
            float pA0 = __expf(c[nA][0] - mn0), pA1 = __expf(c[nA][1] - mn0);
            float pA2 = __expf(c[nA][2] - mn1), pA3 = __expf(c[nA][3] - mn1);
            float pB0 = __expf(c[nB][0] - mn0), pB1 = __expf(c[nB][1] - mn0);
            float pB2 = __expf(c[nB][2] - mn1), pB3 = __expf(c[nB][3] - mn1);
            if (tail) {
                int jA = cc0 + nA * 8 + 2 * t4, jB = cc0 + nB * 8 + 2 * t4;
                if (jA     >= N) { pA0 = 0.f; pA2 = 0.f; }
                if (jA + 1 >= N) { pA1 = 0.f; pA3 = 0.f; }
                if (jB     >= N) { pB0 = 0.f; pB2 = 0.f; }
                if (jB + 1 >= N) { pB1 = 0.f; pB3 = 0.f; }
            }
            rs0 += pA0 + pA1 + pB0 + pB1;
            rs1 += pA2 + pA3 + pB2 + pB3;
            pa[kc2][0] = packbf(pA0, pA1);
            pa[kc2][1] = packbf(pA2, pA3);
            pa[kc2][2] = packbf(pB0, pB1);
            pa[kc2][3] = packbf(pB2, pB3);
        }
        l0 = l0 * sc0 + rs0;
        l1 = l1 * sc1 + rs1;
#pragma unroll
        for (int i = 0; i < 16; i++) {
            o[i][0] *= sc0; o[i][1] *= sc0;
            o[i][2] *= sc1; o[i][3] *= sc1;
        }

        uint32_t vbb = kb + 128 * RS * 2;
#pragma unroll
        for (int nb2 = 0; nb2 < 8; nb2++) {
#pragma unroll
            for (int kc2 = 0; kc2 < 4; kc2++) {
                uint32_t addr = vbb + (uint32_t)(((kc2 * 16 + ((jj & 1) << 3) + rr) * RS +
                                                 nb2 * 16 + ((jj >> 1) << 3)) * 2);
                uint32_t v0, v1, v2, v3;
                ldm_x4t(v0, v1, v2, v3, addr);
                mma16816(o[2 * nb2],     pa[kc2], v0, v1);
                mma16816(o[2 * nb2 + 1], pa[kc2], v2, v3);
            }
        }
        __syncthreads();
    }

    l0 += __shfl_xor_sync(0xffffffffu, l0, 1);
    l0 += __shfl_xor_sync(0xffffffffu, l0, 2);
    l1 += __shfl_xor_sync(0xffffffffu, l1, 1);
    l1 += __shfl_xor_sync(0xffffffffu, l1, 2);

    size_t pbase = (size_t)(split * NHEADS + head) * NP;
    if (row_g < N) {
        float* p = g_po + (pbase + row_g) * H;
#pragma unroll
        for (int nb = 0; nb < 16; nb++)
            *(float2*)(p + nb * 8 + 2 * t4) = make_float2(o[nb][0], o[nb][1]);
        if (t4 == 0) { g_pm[pbase + row_g] = m0; g_pl[pbase + row_g] = l0; }
    }
    if (row_h < N) {
        float* p = g_po + (pbase + row_h) * H;
#pragma unroll
        for (int nb = 0; nb < 16; nb++)
            *(float2*)(p + nb * 8 + 2 * t4) = make_float2(o[nb][2], o[nb][3]);
        if (t4 == 0) { g_pm[pbase + row_h] = m1; g_pl[pbase + row_h] = l1; }
    }
}

// merge KV-split partials into cat
__global__ void k_combine(float* __restrict__ catb) {
    int row = blockIdx.x, head = blockIdx.y, t = threadIdx.x;
    size_t i0 = (size_t)(0 * NHEADS + head) * NP + row;
    size_t i1 = (size_t)(1 * NHEADS + head) * NP + row;
    size_t i2 = (size_t)(2 * NHEADS + head) * NP + row;
    float m0 = g_pm[i0], m1 = g_pm[i1], m2 = g_pm[i2];
    float mm = fmaxf(m0, fmaxf(m1, m2));
    float w0 = __expf(m0 - mm), w1 = __expf(m1 - mm), w2 = __expf(m2 - mm);
    float L = g_pl[i0] * w0 + g_pl[i1] * w1 + g_pl[i2] * w2;
    float v = (g_po[i0 * H + t] * w0 + g_po[i1 * H + t] * w1 + g_po[i2 * H + t] * w2) / L;
    catb[(size_t)row * CATW + H + head * H + t] = v;
}

// ---------------- output projection (128 -> 3) ----------------
__global__ void k_out3(const float* __restrict__ h, const float* __restrict__ W,
                       const float* __restrict__ b, float* __restrict__ out) {
    __shared__ float red[3][128];
    int v = blockIdx.x, t = threadIdx.x;
    float hv = h[v * H + t];
    red[0][t] = hv * W[t * 3 + 0];
    red[1][t] = hv * W[t * 3 + 1];
    red[2][t] = hv * W[t * 3 + 2];
    __syncthreads();
    for (int ofs = 64; ofs > 0; ofs >>= 1) {
        if (t < ofs) {
            red[0][t] += red[0][t + ofs];
            red[1][t] += red[1][t + ofs];
            red[2][t] += red[2][t + ofs];
        }
        __syncthreads();
    }
    if (t < 3) out[v * 3 + t] = red[t][0] + b[t];
}

// ---------------- host ----------------
static void* symAddr(const void* s) {
    void* p = nullptr;
    cudaGetSymbolAddress(&p, s);
    return p;
}

extern "C" void kernel_launch(void* const* d_in, const int* in_sizes, int n_in,
                              void* d_out, int out_size) {
    const float* x_resting = (const float*)d_in[0];
    const float* x_rigid   = (const float*)d_in[1];
    const int*   e_rest    = (const int*)d_in[2];
    const int*   e_rig     = (const int*)d_in[3];
    const float* Wr0 = (const float*)d_in[4];
    const float* br0 = (const float*)d_in[5];
    const float* Wr  = (const float*)d_in[6];
    const float* br  = (const float*)d_in[7];
    const float* Wg0 = (const float*)d_in[8];
    const float* bg0 = (const float*)d_in[9];
    const float* Wg  = (const float*)d_in[10];
    const float* bg  = (const float*)d_in[11];
    const float* Wa  = (const float*)d_in[12];
    const float* ba  = (const float*)d_in[13];
    const float* Wd0 = (const float*)d_in[14];
    const float* bd0 = (const float*)d_in[15];
    const float* Wd  = (const float*)d_in[16];
    const float* bd  = (const float*)d_in[17];
    const float* Wout= (const float*)d_in[18];
    const float* bout= (const float*)d_in[19];
    float* out = (float*)d_out;

    int*   degB = (int*)symAddr(g_deg);
    int*   offB = (int*)symAddr(g_off);
    int*   cntB = (int*)symAddr(g_cnt);
    int*   srcB = (int*)symAddr(g_src);
    float* nrmB = (float*)symAddr(g_nrm);
    float* dinvB= (float*)symAddr(g_dinv);
    float* hw   = (float*)symAddr(g_hw);
    float* ha   = (float*)symAddr(g_ha);
    float* hb   = (float*)symAddr(g_hb);
    float* xg   = (float*)symAddr(g_xg);
    float* cat  = (float*)symAddr(g_cat);
    float* d1   = (float*)symAddr(g_d1);
    float* d2   = (float*)symAddr(g_d2);
    __nv_bfloat16* qhi = (__nv_bfloat16*)symAddr(g_qhi);
    __nv_bfloat16* qlo = (__nv_bfloat16*)symAddr(g_qlo);
    __nv_bfloat16* khi = (__nv_bfloat16*)symAddr(g_khi);
    __nv_bfloat16* klo = (__nv_bfloat16*)symAddr(g_klo);
    __nv_bfloat16* vbf = (__nv_bfloat16*)symAddr(g_vbf);

    const int TB = 256;
    const int GN2 = (2 * N + TB - 1) / TB;
    const int GE  = (E + TB - 1) / TB;
    const int GEN = (EN + TB - 1) / TB;
    const int GT  = (N + 127) / 128;  // 47

    cudaFuncSetAttribute(k_tg_gcn,  cudaFuncAttributeMaxDynamicSharedMemorySize, SMEM_TG);
    cudaFuncSetAttribute(k_tg_proj, cudaFuncAttributeMaxDynamicSharedMemorySize, SMEM_TG);
    cudaFuncSetAttribute(k_tg,      cudaFuncAttributeMaxDynamicSharedMemorySize, SMEM_TG);
    cudaFuncSetAttribute(k_flash_mma, cudaFuncAttributeMaxDynamicSharedMemorySize, SMEM_FA);

    // ------- graph prep, both encoders merged -------
    k_deg_init<<<GN2, TB>>>(degB);
    k_deg_count2<<<dim3(GE, 2), TB>>>(e_rest + E, e_rig + E, degB);
    k_dinv<<<GN2, TB>>>(degB, dinvB);
    k_scan2<<<2, 1024>>>(degB, offB);
    k_zero_cnt<<<GN2, TB>>>(cntB);
    k_fill2<<<dim3(GEN, 2), TB>>>(e_rest, e_rig, offB, cntB, dinvB, srcB, nrmB);

    // ------- GCN encoders, merged -------
    k_in3_2<<<dim3(N, 2), H>>>(x_resting, x_rigid, Wr0, Wg0, hw);
    k_agg2v<<<dim3(N, 2), 128>>>(hw, offB, srcB, nrmB, br0, bg0, ha, H, ha + N * H, H, nullptr);
    k_tg_gcn<<<dim3(GT, 2), 256, SMEM_TG>>>(ha, Wr, Wg, hw);
    k_agg2v<<<dim3(N, 2), 128>>>(hw, offB, srcB, nrmB, br, bg, hb, H, hb + N * H, H, nullptr);
    k_tg_gcn<<<dim3(GT, 2), 256, SMEM_TG>>>(hb, Wr + H * H, Wg + H * H, hw);
    k_agg2v<<<dim3(N, 2), 128>>>(hw, offB, srcB, nrmB, br + H, bg + H, cat, CATW, xg, H, vbf);

    // ------- attention projections (8 tensor GEMMs, one launch, bf16 hi/lo epilogue) -------
    k_tg_proj<<<dim3(GT, 8), 256, SMEM_TG>>>(cat, xg, Wa, ba, qhi, qlo, khi, klo);

    // ------- flash attention, 3-way KV split + combine -------
    k_flash_mma<<<dim3((N + QT - 1) / QT, NHEADS, NSPLIT), 256, SMEM_FA>>>(qhi, qlo, khi, klo, vbf);
    k_combine<<<dim3(N, NHEADS), H>>>(cat);

    // ------- decoder (tensor GEMMs) -------
    k_tg<<<GT, 256, SMEM_TG>>>(cat, CATW, Wd0, bd0, d1, CATW, 1);
    k_tg<<<GT, 256, SMEM_TG>>>(d1, H, Wd, bd, d2, H, 1);
    k_tg<<<GT, 256, SMEM_TG>>>(d2, H, Wd + H * H, bd + H, d1, H, 1);
    k_out3<<<N, H>>>(d1, Wout, bout, out);
}

// round 12
// speedup vs baseline: 4.4887x; 1.0209x over previous
#include <cuda_runtime.h>
#include <cuda_bf16.h>
#include <math.h>
#include <stdint.h>

#define N 6000
#define NP 6016
#define E 192000
#define H 128
#define NHEADS 4
#define EN (E + N)
#define CATW (H * (NHEADS + 1))   // 640
#define NSPLIT 3
#define LOG2E 1.4426950408889634f

// ---------------- device scratch ----------------
__device__ int   g_deg[2][N];
__device__ int   g_off[2][N + 1];
__device__ int   g_cnt[2][N];
__device__ int   g_src[2][EN];
__device__ float g_nrm[2][EN];
__device__ float g_dinv[2][N];
__device__ __align__(16) float g_hw[2][N * H];
__device__ __align__(16) float g_ha[2][N * H];
__device__ __align__(16) float g_hb[2][N * H];
__device__ __align__(16) float g_xg[N * H];
__device__ __align__(16) float g_cat[N * CATW];
__device__ __align__(16) float g_d1[N * H];
__device__ __align__(16) float g_d2[N * H];
// bf16 attention operands (padded to NP rows; pads stay zero)
__device__ __align__(16) __nv_bfloat16 g_qhi[NHEADS * NP * H];
__device__ __align__(16) __nv_bfloat16 g_qlo[NHEADS * NP * H];
__device__ __align__(16) __nv_bfloat16 g_khi[NHEADS * NP * H];
__device__ __align__(16) __nv_bfloat16 g_klo[NHEADS * NP * H];
__device__ __align__(16) __nv_bfloat16 g_vbf[NP * H];
// flash partials (KV-split)
__device__ __align__(16) float g_po[NSPLIT * NHEADS * NP * H];
__device__ float g_pm[NSPLIT * NHEADS * NP];
__device__ float g_pl[NSPLIT * NHEADS * NP];

// ---------------- small helpers ----------------
__device__ __forceinline__ uint32_t smem_u32(const void* p) {
    uint32_t a;
    asm("{ .reg .u64 t; cvta.to.shared.u64 t, %1; cvt.u32.u64 %0, t; }" : "=r"(a) : "l"(p));
    return a;
}
__device__ __forceinline__ float ex2(float x) {
    float y;
    asm("ex2.approx.f32 %0, %1;" : "=f"(y) : "f"(x));
    return y;
}
__device__ __forceinline__ void mma16816(float* c, const uint32_t* a, uint32_t b0, uint32_t b1) {
    asm volatile(
        "mma.sync.aligned.m16n8k16.row.col.f32.bf16.bf16.f32 "
        "{%0,%1,%2,%3}, {%4,%5,%6,%7}, {%8,%9}, {%0,%1,%2,%3};"
        : "+f"(c[0]), "+f"(c[1]), "+f"(c[2]), "+f"(c[3])
        : "r"(a[0]), "r"(a[1]), "r"(a[2]), "r"(a[3]), "r"(b0), "r"(b1));
}
__device__ __forceinline__ void ldm_x4(uint32_t& r0, uint32_t& r1, uint32_t& r2, uint32_t& r3,
                                       uint32_t addr) {
    asm volatile("ldmatrix.sync.aligned.m8n8.x4.shared.b16 {%0,%1,%2,%3}, [%4];"
                 : "=r"(r0), "=r"(r1), "=r"(r2), "=r"(r3) : "r"(addr));
}
__device__ __forceinline__ void ldm_x4t(uint32_t& r0, uint32_t& r1, uint32_t& r2, uint32_t& r3,
                                        uint32_t addr) {
    asm volatile("ldmatrix.sync.aligned.m8n8.x4.trans.shared.b16 {%0,%1,%2,%3}, [%4];"
                 : "=r"(r0), "=r"(r1), "=r"(r2), "=r"(r3) : "r"(addr));
}
__device__ __forceinline__ void cp16(uint32_t dst, const void* src, uint32_t sz) {
    asm volatile("cp.async.cg.shared.global [%0], [%1], 16, %2;"
                 :: "r"(dst), "l"(src), "r"(sz) : "memory");
}
__device__ __forceinline__ uint32_t packbf(float a, float b) {
    __nv_bfloat162 v = __floats2bfloat162_rn(a, b);
    return *reinterpret_cast<uint32_t*>(&v);
}
__device__ __forceinline__ void split2(float2 v, uint32_t& hi, uint32_t& lo) {
    __nv_bfloat16 hx = __float2bfloat16(v.x), hy = __float2bfloat16(v.y);
    __nv_bfloat162 h2 = __nv_bfloat162(hx, hy);
    hi = *reinterpret_cast<uint32_t*>(&h2);
    lo = packbf(v.x - __bfloat162float(hx), v.y - __bfloat162float(hy));
}

// ---------------- graph preprocessing (both encoders merged) ----------------
__global__ void k_deg_init(int* deg, int* cnt) {
    int i = blockIdx.x * blockDim.x + threadIdx.x;
    if (i < 2 * N) { deg[i] = 1; cnt[i] = 0; }
}
__global__ void k_deg_count2(const int* __restrict__ col0, const int* __restrict__ col1,
                             int* deg) {
    int e = blockIdx.x * blockDim.x + threadIdx.x;
    int ei = blockIdx.y;
    const int* col = ei ? col1 : col0;
    if (e < E) atomicAdd(&deg[ei * N + col[e]], 1);
}
// scan + dinv fused; one block per encoder
__global__ void k_scan2(const int* __restrict__ degAll, int* __restrict__ offAll,
                        float* __restrict__ dinvAll) {
    int ei = blockIdx.x;
    const int* deg = degAll + ei * N;
    int* off = offAll + ei * (N + 1);
    float* dinv = dinvAll + ei * N;
    __shared__ int wsum[32];
    int tid = threadIdx.x, lane = tid & 31, wid = tid >> 5;
    const int C = (N + 1023) / 1024;          // 6
    int base = tid * C;
    int loc[C];
    int s = 0;
#pragma unroll
    for (int i = 0; i < C; i++) {
        int idx = base + i;
        loc[i] = (idx < N) ? deg[idx] : 0;
        if (idx < N) dinv[idx] = rsqrtf((float)loc[i]);
        s += loc[i];
    }
    int inc = s;
#pragma unroll
    for (int d = 1; d < 32; d <<= 1) {
        int v = __shfl_up_sync(0xffffffffu, inc, d);
        if (lane >= d) inc += v;
    }
    if (lane == 31) wsum[wid] = inc;
    __syncthreads();
    if (wid == 0) {
        int v = wsum[lane];
#pragma unroll
        for (int d = 1; d < 32; d <<= 1) {
            int u = __shfl_up_sync(0xffffffffu, v, d);
            if (lane >= d) v += u;
        }
        wsum[lane] = v;
    }
    __syncthreads();
    int run = inc - s + (wid > 0 ? wsum[wid - 1] : 0);
#pragma unroll
    for (int i = 0; i < C; i++) {
        int idx = base + i;
        if (idx < N) { off[idx] = run; run += loc[i]; }
    }
    if (tid == 1023) off[N] = run;
}
__global__ void k_fill2(const int* __restrict__ ed0, const int* __restrict__ ed1,
                        const int* __restrict__ offB, int* cntB,
                        const float* __restrict__ dinvB,
                        int* __restrict__ srcB, float* __restrict__ nrmB) {
    int e = blockIdx.x * blockDim.x + threadIdx.x;
    if (e >= EN) return;
    int ei = blockIdx.y;
    const int* edges = ei ? ed1 : ed0;
    const int* off  = offB + ei * (N + 1);
    int* cnt        = cntB + ei * N;
    const float* dinv = dinvB + ei * N;
    int* src        = srcB + (size_t)ei * EN;
    float* nrm      = nrmB + (size_t)ei * EN;
    int r, c;
    if (e < E) { r = edges[e]; c = edges[E + e]; }
    else       { r = c = e - E; }
    int pos = off[c] + atomicAdd(&cnt[c], 1);
    src[pos] = r;
    nrm[pos] = dinv[r] * dinv[c];
}

// ---------------- GCN input + aggregation ----------------
__global__ void k_in3_2(const float* __restrict__ x0, const float* __restrict__ x1,
                        const float* __restrict__ W0, const float* __restrict__ W1,
                        float* __restrict__ hwB) {
    int ei = blockIdx.y;
    const float* x = ei ? x1 : x0;
    const float* W = ei ? W1 : W0;
    int v = blockIdx.x, t = threadIdx.x;
    float a0 = x[v * 3 + 0], a1 = x[v * 3 + 1], a2 = x[v * 3 + 2];
    hwB[(size_t)ei * N * H + v * H + t] = a0 * W[t] + a1 * W[H + t] + a2 * W[2 * H + t];
}
// vectorized aggregate: 4 warps over neighbors, float4 per thread, smem reduce
__global__ void k_agg2v(const float* __restrict__ hwB, const int* __restrict__ offB,
                        const int* __restrict__ srcB, const float* __restrict__ nrmB,
                        const float* __restrict__ bias0, const float* __restrict__ bias1,
                        float* out0, int ldo0, float* out1, int ldo1,
                        __nv_bfloat16* vb1) {
    __shared__ float4 part[4][32];
    int ei = blockIdx.y;
    const float4* hw4 = (const float4*)(hwB + (size_t)ei * N * H);
    const int*   off = offB + ei * (N + 1);
    const int*   src = srcB + (size_t)ei * EN;
    const float* nrm = nrmB + (size_t)ei * EN;
    int v = blockIdx.x, tid = threadIdx.x, w = tid >> 5, lane = tid & 31;
    int s = off[v], e = off[v + 1];
    float4 acc = make_float4(0.f, 0.f, 0.f, 0.f);
    for (int j = s + w; j < e; j += 4) {
        int   sj = __ldg(&src[j]);
        float nj = __ldg(&nrm[j]);
        float4 x = hw4[(size_t)sj * 32 + lane];
        acc.x += x.x * nj; acc.y += x.y * nj; acc.z += x.z * nj; acc.w += x.w * nj;
    }
    part[w][lane] = acc;
    __syncthreads();
    if (w == 0) {
        float4 a = part[0][lane], b = part[1][lane], c = part[2][lane], d = part[3][lane];
        const float* bias = ei ? bias1 : bias0;
        float4 bb = *(const float4*)(bias + lane * 4);
        float r0 = fmaxf(a.x + b.x + c.x + d.x + bb.x, 0.f);
        float r1 = fmaxf(a.y + b.y + c.y + d.y + bb.y, 0.f);
        float r2 = fmaxf(a.z + b.z + c.z + d.z + bb.z, 0.f);
        float r3 = fmaxf(a.w + b.w + c.w + d.w + bb.w, 0.f);
        float* out = ei ? out1 : out0;
        int ldo = ei ? ldo1 : ldo0;
        *(float4*)(out + (size_t)v * ldo + lane * 4) = make_float4(r0, r1, r2, r3);
        if (ei == 1 && vb1) {
            uint2 p = make_uint2(packbf(r0, r1), packbf(r2, r3));
            *(uint2*)((char*)vb1 + ((size_t)v * H + lane * 4) * 2) = p;
        }
    }
}

// ---------------- tensor-core GEMM (bf16 hi/lo, fp32-accurate) ----------------
#define RS2 136
#define WLOFF (128 * RS2 * 2)     // byte offset of Wl within smem
#define SMEM_TG (2 * 128 * RS2 * 2)   // 69632 B

// MODE 0: fp32 store (+optional relu). MODE 1: bf16 hi/lo split store (ld H), scaled.
template<int MODE>
__device__ __forceinline__ void tgemm_body(
    char* sm, const float* __restrict__ A, int lda,
    const float* __restrict__ W, const float* __restrict__ bias,
    int doRelu, int r0, float* out, int ldo,
    __nv_bfloat16* oh, __nv_bfloat16* ol, int K, float oscale) {
    const uint32_t sb = smem_u32(sm);
    const int tid = threadIdx.x;
    const int w = tid >> 5, lane = tid & 31;
    const int g = lane >> 2, t4 = lane & 3;
    const int jj = lane >> 3, rr = lane & 7;
    const int row_g = r0 + w * 16 + g;
    const int row_h = row_g + 8;
    const int rg = (row_g < N) ? row_g : (N - 1);
    const int rh = (row_h < N) ? row_h : (N - 1);

    float o[16][4];
#pragma unroll
    for (int i = 0; i < 16; i++)
#pragma unroll
        for (int j = 0; j < 4; j++) o[i][j] = 0.f;

    for (int kc0 = 0; kc0 < K; kc0 += 128) {
        if (kc0 > 0) __syncthreads();
        const float4* W4 = (const float4*)(W + (size_t)kc0 * 128);
        for (int i = tid; i < 128 * 32; i += 256) {
            int k = i >> 5, c4 = (i & 31) << 2;
            float4 wv = W4[i];
            uint32_t h0, l0, h1, l1;
            split2(make_float2(wv.x, wv.y), h0, l0);
            split2(make_float2(wv.z, wv.w), h1, l1);
            uint32_t off = (uint32_t)(k * RS2 + c4) * 2;
            *(uint2*)(sm + off)         = make_uint2(h0, h1);
            *(uint2*)(sm + WLOFF + off) = make_uint2(l0, l1);
        }
        __syncthreads();

        uint32_t ah[8][4], al[8][4];
#pragma unroll
        for (int kc = 0; kc < 8; kc++) {
            int c0 = kc0 + kc * 16 + 2 * t4;
            split2(*(const float2*)(A + (size_t)rg * lda + c0),     ah[kc][0], al[kc][0]);
            split2(*(const float2*)(A + (size_t)rh * lda + c0),     ah[kc][1], al[kc][1]);
            split2(*(const float2*)(A + (size_t)rg * lda + c0 + 8), ah[kc][2], al[kc][2]);
            split2(*(const float2*)(A + (size_t)rh * lda + c0 + 8), ah[kc][3], al[kc][3]);
        }

#pragma unroll
        for (int nb2 = 0; nb2 < 8; nb2++) {
#pragma unroll
            for (int kc = 0; kc < 8; kc++) {
                uint32_t addr = sb + (uint32_t)(((kc * 16 + ((jj & 1) << 3) + rr) * RS2 +
                                                nb2 * 16 + ((jj >> 1) << 3)) * 2);
                uint32_t b0, b1, b2, b3, d0, d1, d2, d3;
                ldm_x4t(b0, b1, b2, b3, addr);
                ldm_x4t(d0, d1, d2, d3, addr + WLOFF);
                mma16816(o[2 * nb2],     ah[kc], b0, b1);
                mma16816(o[2 * nb2 + 1], ah[kc], b2, b3);
                mma16816(o[2 * nb2],     al[kc], b0, b1);
                mma16816(o[2 * nb2 + 1], al[kc], b2, b3);
                mma16816(o[2 * nb2],     ah[kc], d0, d1);
                mma16816(o[2 * nb2 + 1], ah[kc], d2, d3);
            }
        }
    }

#pragma unroll
    for (int nb = 0; nb < 16; nb++) {
        int col = nb * 8 + 2 * t4;
        float2 bz = bias ? *(const float2*)(bias + col) : make_float2(0.f, 0.f);
        float v0 = o[nb][0] + bz.x, v1 = o[nb][1] + bz.y;
        float v2 = o[nb][2] + bz.x, v3 = o[nb][3] + bz.y;
        if (MODE == 0) {
            if (doRelu) {
                v0 = fmaxf(v0, 0.f); v1 = fmaxf(v1, 0.f);
                v2 = fmaxf(v2, 0.f); v3 = fmaxf(v3, 0.f);
            }
            if (row_g < N) *(float2*)(out + (size_t)row_g * ldo + col) = make_float2(v0, v1);
            if (row_h < N) *(float2*)(out + (size_t)row_h * ldo + col) = make_float2(v2, v3);
        } else {
            v0 *= oscale; v1 *= oscale; v2 *= oscale; v3 *= oscale;
            if (row_g < N) {
                uint32_t hi, lo;
                split2(make_float2(v0, v1), hi, lo);
                *(uint32_t*)((char*)oh + ((size_t)row_g * H + col) * 2) = hi;
                *(uint32_t*)((char*)ol + ((size_t)row_g * H + col) * 2) = lo;
            }
            if (row_h < N) {
                uint32_t hi, lo;
                split2(make_float2(v2, v3), hi, lo);
                *(uint32_t*)((char*)oh + ((size_t)row_h * H + col) * 2) = hi;
                *(uint32_t*)((char*)ol + ((size_t)row_h * H + col) * 2) = lo;
            }
        }
    }
}

__global__ __launch_bounds__(256)
void k_tg_gcn(const float* __restrict__ Abase,
              const float* __restrict__ W0, const float* __restrict__ W1,
              float* __restrict__ outbase) {
    extern __shared__ char sm[];
    int ei = blockIdx.y;
    tgemm_body<0>(sm, Abase + (size_t)ei * N * H, H, ei ? W1 : W0, nullptr, 0,
                  blockIdx.x * 128, outbase + (size_t)ei * N * H, H, nullptr, nullptr, H, 1.f);
}
__global__ __launch_bounds__(256)
void k_tg_proj(const float* __restrict__ catb, const float* __restrict__ xg,
               const float* __restrict__ Wa, const float* __restrict__ ba,
               __nv_bfloat16* qh, __nv_bfloat16* ql,
               __nv_bfloat16* kh, __nv_bfloat16* kl) {
    extern __shared__ char sm[];
    int head = blockIdx.y & 3, isK = blockIdx.y >> 2;
    tgemm_body<1>(sm, isK ? xg : catb, isK ? H : CATW, Wa + head * H * H, ba + head * H, 0,
                  blockIdx.x * 128, nullptr, 0,
                  (isK ? kh : qh) + (size_t)head * NP * H,
                  (isK ? kl : ql) + (size_t)head * NP * H, H,
                  isK ? 1.f : LOG2E);
}
__global__ __launch_bounds__(256)
void k_tg(const float* __restrict__ A, int lda,
          const float* __restrict__ W, const float* __restrict__ bias,
          float* __restrict__ out, int K, int doRelu) {
    extern __shared__ char sm[];
    tgemm_body<0>(sm, A, lda, W, bias, doRelu, blockIdx.x * 128, out, H, nullptr, nullptr, K, 1.f);
}

// ---------------- mma.sync flash attention (KV-split, KVT=128) ----------------
#define QT  128
#define KVT 128
#define RS  136                   // smem row stride (bf16 elements) = 272B
#define BUFB (384 * RS * 2)       // khi(128)+klo(128)+v(128) rows = 104448 B
#define SMEM_FA (2 * BUFB)        // 208896 B

__global__ void __launch_bounds__(256, 1)
k_flash_mma(const __nv_bfloat16* __restrict__ Qhi, const __nv_bfloat16* __restrict__ Qlo,
            const __nv_bfloat16* __restrict__ Khi, const __nv_bfloat16* __restrict__ Klo,
            const __nv_bfloat16* __restrict__ Vb) {
    extern __shared__ __nv_bfloat16 smfa[];
    const uint32_t sbase = smem_u32(smfa);
    const int tid = threadIdx.x;
    const int w = tid >> 5, lane = tid & 31;
    const int g = lane >> 2, t4 = lane & 3;
    const int head = blockIdx.y;
    const int split = blockIdx.z;
    const int r0 = blockIdx.x * QT;

    const __nv_bfloat16* qhi = Qhi + (size_t)head * NP * H;
    const __nv_bfloat16* qlo = Qlo + (size_t)head * NP * H;
    const __nv_bfloat16* khi = Khi + (size_t)head * NP * H;
    const __nv_bfloat16* klo = Klo + (size_t)head * NP * H;

    const int row_g = r0 + w * 16 + g;
    const int row_h = row_g + 8;

    uint32_t qh[8][4], ql[8][4];
#pragma unroll
    for (int kc = 0; kc < 8; kc++) {
        int c0 = kc * 16 + 2 * t4;
        qh[kc][0] = *(const uint32_t*)(qhi + (size_t)row_g * H + c0);
        qh[kc][1] = *(const uint32_t*)(qhi + (size_t)row_h * H + c0);
        qh[kc][2] = *(const uint32_t*)(qhi + (size_t)row_g * H + c0 + 8);
        qh[kc][3] = *(const uint32_t*)(qhi + (size_t)row_h * H + c0 + 8);
        ql[kc][0] = *(const uint32_t*)(qlo + (size_t)row_g * H + c0);
        ql[kc][1] = *(const uint32_t*)(qlo + (size_t)row_h * H + c0);
        ql[kc][2] = *(const uint32_t*)(qlo + (size_t)row_g * H + c0 + 8);
        ql[kc][3] = *(const uint32_t*)(qlo + (size_t)row_h * H + c0 + 8);
    }

    float o[16][4];
#pragma unroll
    for (int i = 0; i < 16; i++)
#pragma unroll
        for (int j = 0; j < 4; j++) o[i][j] = 0.f;
    float m0 = -1e30f, m1 = -1e30f, l0 = 0.f, l1 = 0.f;

    const int NT = (N + KVT - 1) / KVT;                       // 47
    const int t_lo = (split == 0) ? 0 : (split == 1 ? 16 : 32);
    const int t_hi = (split == 0) ? 16 : (split == 1 ? 32 : NT);

    auto issue_load = [&](int tile, int b) {
        int c0 = tile * KVT;
        uint32_t dbase = sbase + (uint32_t)b * BUFB;
#pragma unroll 4
        for (int i = tid; i < 128 * 16; i += 256) {
            int r = i >> 4, s = i & 15;
            int gr = c0 + r;
            uint32_t sz = (gr < N) ? 16u : 0u;
            int grc = (gr < N) ? gr : (N - 1);
            uint32_t d0 = dbase + (uint32_t)(r * RS * 2 + s * 16);
            cp16(d0,                    khi + (size_t)grc * H + s * 8, sz);
            cp16(d0 + 128 * RS * 2,     klo + (size_t)grc * H + s * 8, sz);
            cp16(d0 + 256 * RS * 2,     Vb  + (size_t)grc * H + s * 8, sz);
        }
        asm volatile("cp.async.commit_group;" ::: "memory");
    };

    issue_load(t_lo, 0);

    for (int t = t_lo; t < t_hi; t++) {
        int b = (t - t_lo) & 1;
        if (t + 1 < t_hi) {
            issue_load(t + 1, b ^ 1);
            asm volatile("cp.async.wait_group 1;" ::: "memory");
        } else {
            asm volatile("cp.async.wait_group 0;" ::: "memory");
        }
        __syncthreads();

        uint32_t kb = sbase + (uint32_t)b * BUFB;
        float c[16][4];
#pragma unroll
        for (int i = 0; i < 16; i++)
#pragma unroll
            for (int j = 0; j < 4; j++) c[i][j] = 0.f;

        const int jj = lane >> 3, rr = lane & 7;
#pragma unroll
        for (int nb2 = 0; nb2 < 8; nb2++) {
#pragma unroll
            for (int kc = 0; kc < 8; kc++) {
                uint32_t addr = kb + (uint32_t)(((nb2 * 16 + ((jj >> 1) << 3) + rr) * RS +
                                                kc * 16 + ((jj & 1) << 3)) * 2);
                uint32_t h0, h1, h2, h3, e0, e1, e2, e3;
                ldm_x4(h0, h1, h2, h3, addr);
                ldm_x4(e0, e1, e2, e3, addr + 128 * RS * 2);
                mma16816(c[2 * nb2],     qh[kc], h0, h1);
                mma16816(c[2 * nb2 + 1], qh[kc], h2, h3);
                mma16816(c[2 * nb2],     ql[kc], h0, h1);
                mma16816(c[2 * nb2 + 1], ql[kc], h2, h3);
                mma16816(c[2 * nb2],     qh[kc], e0, e1);
                mma16816(c[2 * nb2 + 1], qh[kc], e2, e3);
            }
        }

        // ---- online softmax (base-2 logits) ----
        float tm0 = -1e30f, tm1 = -1e30f;
#pragma unroll
        for (int nb = 0; nb < 16; nb++) {
            tm0 = fmaxf(tm0, fmaxf(c[nb][0], c[nb][1]));
            tm1 = fmaxf(tm1, fmaxf(c[nb][2], c[nb][3]));
        }
        tm0 = fmaxf(tm0, __shfl_xor_sync(0xffffffffu, tm0, 1));
        tm0 = fmaxf(tm0, __shfl_xor_sync(0xffffffffu, tm0, 2));
        tm1 = fmaxf(tm1, __shfl_xor_sync(0xffffffffu, tm1, 1));
        tm1 = fmaxf(tm1, __shfl_xor_sync(0xffffffffu, tm1, 2));
        float mn0 = fmaxf(m0, tm0), mn1 = fmaxf(m1, tm1);
        float sc0 = ex2(m0 - mn0), sc1 = ex2(m1 - mn1);
        m0 = mn0; m1 = mn1;

        uint32_t pa[8][4];
        float rs0 = 0.f, rs1 = 0.f;
        const bool tail = (t == NT - 1);
        const int cc0 = t * KVT;
#pragma unroll
        for (int kc2 = 0; kc2 < 8; kc2++) {
            int nA = 2 * kc2, nB = nA + 1;
            float pA0 = ex2(c[nA][0] - mn0), pA1 = ex2(c[nA][1] - mn0);
            float pA2 = ex2(c[nA][2] - mn1), pA3 = ex2(c[nA][3] - mn1);
            float pB0 = ex2(c[nB][0] - mn0), pB1 = ex2(c[nB][1] - mn0);
            float pB2 = ex2(c[nB][2] - mn1), pB3 = ex2(c[nB][3] - mn1);
            if (tail) {
                int jA = cc0 + nA * 8 + 2 * t4, jB = cc0 + nB * 8 + 2 * t4;
                if (jA     >= N) { pA0 = 0.f; pA2 = 0.f; }
                if (jA + 1 >= N) { pA1 = 0.f; pA3 = 0.f; }
                if (jB     >= N) { pB0 = 0.f; pB2 = 0.f; }
                if (jB + 1 >= N) { pB1 = 0.f; pB3 = 0.f; }
            }
            rs0 += pA0 + pA1 + pB0 + pB1;
            rs1 += pA2 + pA3 + pB2 + pB3;
            pa[kc2][0] = packbf(pA0, pA1);
            pa[kc2][1] = packbf(pA2, pA3);
            pa[kc2][2] = packbf(pB0, pB1);
            pa[kc2][3] = packbf(pB2, pB3);
        }
        l0 = l0 * sc0 + rs0;
        l1 = l1 * sc1 + rs1;
#pragma unroll
        for (int i = 0; i < 16; i++) {
            o[i][0] *= sc0; o[i][1] *= sc0;
            o[i][2] *= sc1; o[i][3] *= sc1;
        }

        // ---- O += P @ V ----
        uint32_t vbb = kb + 256 * RS * 2;
#pragma unroll
        for (int nb2 = 0; nb2 < 8; nb2++) {
#pragma unroll
            for (int kc2 = 0; kc2 < 8; kc2++) {
                uint32_t addr = vbb + (uint32_t)(((kc2 * 16 + ((jj & 1) << 3) + rr) * RS +
                                                 nb2 * 16 + ((jj >> 1) << 3)) * 2);
                uint32_t v0, v1, v2, v3;
                ldm_x4t(v0, v1, v2, v3, addr);
                mma16816(o[2 * nb2],     pa[kc2], v0, v1);
                mma16816(o[2 * nb2 + 1], pa[kc2], v2, v3);
            }
        }
        __syncthreads();
    }

    l0 += __shfl_xor_sync(0xffffffffu, l0, 1);
    l0 += __shfl_xor_sync(0xffffffffu, l0, 2);
    l1 += __shfl_xor_sync(0xffffffffu, l1, 1);
    l1 += __shfl_xor_sync(0xffffffffu, l1, 2);

    size_t pbase = (size_t)(split * NHEADS + head) * NP;
    if (row_g < N) {
        float* p = g_po + (pbase + row_g) * H;
#pragma unroll
        for (int nb = 0; nb < 16; nb++)
            *(float2*)(p + nb * 8 + 2 * t4) = make_float2(o[nb][0], o[nb][1]);
        if (t4 == 0) { g_pm[pbase + row_g] = m0; g_pl[pbase + row_g] = l0; }
    }
    if (row_h < N) {
        float* p = g_po + (pbase + row_h) * H;
#pragma unroll
        for (int nb = 0; nb < 16; nb++)
            *(float2*)(p + nb * 8 + 2 * t4) = make_float2(o[nb][2], o[nb][3]);
        if (t4 == 0) { g_pm[pbase + row_h] = m1; g_pl[pbase + row_h] = l1; }
    }
}

// merge KV-split partials into cat (base-2 m values)
__global__ void k_combine(float* __restrict__ catb) {
    int row = blockIdx.x, head = blockIdx.y, t = threadIdx.x;
    size_t i0 = (size_t)(0 * NHEADS + head) * NP + row;
    size_t i1 = (size_t)(1 * NHEADS + head) * NP + row;
    size_t i2 = (size_t)(2 * NHEADS + head) * NP + row;
    float m0 = g_pm[i0], m1 = g_pm[i1], m2 = g_pm[i2];
    float mm = fmaxf(m0, fmaxf(m1, m2));
    float w0 = ex2(m0 - mm), w1 = ex2(m1 - mm), w2 = ex2(m2 - mm);
    float L = g_pl[i0] * w0 + g_pl[i1] * w1 + g_pl[i2] * w2;
    float v = (g_po[i0 * H + t] * w0 + g_po[i1 * H + t] * w1 + g_po[i2 * H + t] * w2) / L;
    catb[(size_t)row * CATW + H + head * H + t] = v;
}

// ---------------- output projection (128 -> 3) ----------------
__global__ void k_out3(const float* __restrict__ h, const float* __restrict__ W,
                       const float* __restrict__ b, float* __restrict__ out) {
    __shared__ float red[3][128];
    int v = blockIdx.x, t = threadIdx.x;
    float hv = h[v * H + t];
    red[0][t] = hv * W[t * 3 + 0];
    red[1][t] = hv * W[t * 3 + 1];
    red[2][t] = hv * W[t * 3 + 2];
    __syncthreads();
    for (int ofs = 64; ofs > 0; ofs >>= 1) {
        if (t < ofs) {
            red[0][t] += red[0][t + ofs];
            red[1][t] += red[1][t + ofs];
            red[2][t] += red[2][t + ofs];
        }
        __syncthreads();
    }
    if (t < 3) out[v * 3 + t] = red[t][0] + b[t];
}

// ---------------- host ----------------
static void* symAddr(const void* s) {
    void* p = nullptr;
    cudaGetSymbolAddress(&p, s);
    return p;
}

extern "C" void kernel_launch(void* const* d_in, const int* in_sizes, int n_in,
                              void* d_out, int out_size) {
    const float* x_resting = (const float*)d_in[0];
    const float* x_rigid   = (const float*)d_in[1];
    const int*   e_rest    = (const int*)d_in[2];
    const int*   e_rig     = (const int*)d_in[3];
    const float* Wr0 = (const float*)d_in[4];
    const float* br0 = (const float*)d_in[5];
    const float* Wr  = (const float*)d_in[6];
    const float* br  = (const float*)d_in[7];
    const float* Wg0 = (const float*)d_in[8];
    const float* bg0 = (const float*)d_in[9];
    const float* Wg  = (const float*)d_in[10];
    const float* bg  = (const float*)d_in[11];
    const float* Wa  = (const float*)d_in[12];
    const float* ba  = (const float*)d_in[13];
    const float* Wd0 = (const float*)d_in[14];
    const float* bd0 = (const float*)d_in[15];
    const float* Wd  = (const float*)d_in[16];
    const float* bd  = (const float*)d_in[17];
    const float* Wout= (const float*)d_in[18];
    const float* bout= (const float*)d_in[19];
    float* out = (float*)d_out;

    int*   degB = (int*)symAddr(g_deg);
    int*   offB = (int*)symAddr(g_off);
    int*   cntB = (int*)symAddr(g_cnt);
    int*   srcB = (int*)symAddr(g_src);
    float* nrmB = (float*)symAddr(g_nrm);
    float* dinvB= (float*)symAddr(g_dinv);
    float* hw   = (float*)symAddr(g_hw);
    float* ha   = (float*)symAddr(g_ha);
    float* hb   = (float*)symAddr(g_hb);
    float* xg   = (float*)symAddr(g_xg);
    float* cat  = (float*)symAddr(g_cat);
    float* d1   = (float*)symAddr(g_d1);
    float* d2   = (float*)symAddr(g_d2);
    __nv_bfloat16* qhi = (__nv_bfloat16*)symAddr(g_qhi);
    __nv_bfloat16* qlo = (__nv_bfloat16*)symAddr(g_qlo);
    __nv_bfloat16* khi = (__nv_bfloat16*)symAddr(g_khi);
    __nv_bfloat16* klo = (__nv_bfloat16*)symAddr(g_klo);
    __nv_bfloat16* vbf = (__nv_bfloat16*)symAddr(g_vbf);

    const int TB = 256;
    const int GN2 = (2 * N + TB - 1) / TB;
    const int GE  = (E + TB - 1) / TB;
    const int GEN = (EN + TB - 1) / TB;
    const int GT  = (N + 127) / 128;  // 47

    cudaFuncSetAttribute(k_tg_gcn,  cudaFuncAttributeMaxDynamicSharedMemorySize, SMEM_TG);
    cudaFuncSetAttribute(k_tg_proj, cudaFuncAttributeMaxDynamicSharedMemorySize, SMEM_TG);
    cudaFuncSetAttribute(k_tg,      cudaFuncAttributeMaxDynamicSharedMemorySize, SMEM_TG);
    cudaFuncSetAttribute(k_flash_mma, cudaFuncAttributeMaxDynamicSharedMemorySize, SMEM_FA);

    // ------- graph prep, both encoders merged -------
    k_deg_init<<<GN2, TB>>>(degB, cntB);
    k_deg_count2<<<dim3(GE, 2), TB>>>(e_rest + E, e_rig + E, degB);
    k_scan2<<<2, 1024>>>(degB, offB, dinvB);
    k_fill2<<<dim3(GEN, 2), TB>>>(e_rest, e_rig, offB, cntB, dinvB, srcB, nrmB);

    // ------- GCN encoders, merged -------
    k_in3_2<<<dim3(N, 2), H>>>(x_resting, x_rigid, Wr0, Wg0, hw);
    k_agg2v<<<dim3(N, 2), 128>>>(hw, offB, srcB, nrmB, br0, bg0, ha, H, ha + N * H, H, nullptr);
    k_tg_gcn<<<dim3(GT, 2), 256, SMEM_TG>>>(ha, Wr, Wg, hw);
    k_agg2v<<<dim3(N, 2), 128>>>(hw, offB, srcB, nrmB, br, bg, hb, H, hb + N * H, H, nullptr);
    k_tg_gcn<<<dim3(GT, 2), 256, SMEM_TG>>>(hb, Wr + H * H, Wg + H * H, hw);
    k_agg2v<<<dim3(N, 2), 128>>>(hw, offB, srcB, nrmB, br + H, bg + H, cat, CATW, xg, H, vbf);

    // ------- attention projections (8 tensor GEMMs, one launch, bf16 hi/lo epilogue) -------
    k_tg_proj<<<dim3(GT, 8), 256, SMEM_TG>>>(cat, xg, Wa, ba, qhi, qlo, khi, klo);

    // ------- flash attention, 3-way KV split + combine -------
    k_flash_mma<<<dim3((N + QT - 1) / QT, NHEADS, NSPLIT), 256, SMEM_FA>>>(qhi, qlo, khi, klo, vbf);
    k_combine<<<dim3(N, NHEADS), H>>>(cat);

    // ------- decoder (tensor GEMMs) -------
    k_tg<<<GT, 256, SMEM_TG>>>(cat, CATW, Wd0, bd0, d1, CATW, 1);
    k_tg<<<GT, 256, SMEM_TG>>>(d1, H, Wd, bd, d2, H, 1);
    k_tg<<<GT, 256, SMEM_TG>>>(d2, H, Wd + H * H, bd + H, d1, H, 1);
    k_out3<<<N, H>>>(d1, Wout, bout, out);
}

// round 14
// speedup vs baseline: 5.2617x; 1.1722x over previous
#include <cuda_runtime.h>
#include <cuda_bf16.h>
#include <cuda_fp16.h>
#include <math.h>
#include <stdint.h>

#define N 6000
#define NP 6016
#define E 192000
#define H 128
#define NHEADS 4
#define EN (E + N)
#define CATW (H * (NHEADS + 1))   // 640
#define NSPLIT 3
#define LOG2E 1.4426950408889634f

// ---------------- device scratch ----------------
__device__ int   g_deg[2][N];
__device__ int   g_off[2][N + 1];
__device__ int   g_cnt[2][N];
__device__ int   g_src[2][EN];
__device__ float g_nrm[2][EN];
__device__ float g_dinv[2][N];
__device__ __align__(16) float g_hw[2][N * H];
__device__ __align__(16) float g_ha[2][N * H];
__device__ __align__(16) float g_hb[2][N * H];
__device__ __align__(16) float g_xg[N * H];
__device__ __align__(16) float g_cat[N * CATW];
__device__ __align__(16) float g_d1[N * H];
__device__ __align__(16) float g_d2[N * H];
// fp16 attention operands (padded to NP rows; pads stay zero)
__device__ __align__(16) __half g_qhi[NHEADS * NP * H];
__device__ __align__(16) __half g_qlo[NHEADS * NP * H];
__device__ __align__(16) __half g_khf[NHEADS * NP * H];
__device__ __align__(16) __half g_vhf[NP * H];
// flash partials (KV-split)
__device__ __align__(16) float g_po[NSPLIT * NHEADS * NP * H];
__device__ float g_pm[NSPLIT * NHEADS * NP];
__device__ float g_pl[NSPLIT * NHEADS * NP];

// ---------------- small helpers ----------------
__device__ __forceinline__ uint32_t smem_u32(const void* p) {
    uint32_t a;
    asm("{ .reg .u64 t; cvta.to.shared.u64 t, %1; cvt.u32.u64 %0, t; }" : "=r"(a) : "l"(p));
    return a;
}
__device__ __forceinline__ float ex2(float x) {
    float y;
    asm("ex2.approx.f32 %0, %1;" : "=f"(y) : "f"(x));
    return y;
}
// fp16 MMA: D(f32) += A(f16) B(f16)
__device__ __forceinline__ void mma16816h(float* c, const uint32_t* a, uint32_t b0, uint32_t b1) {
    asm volatile(
        "mma.sync.aligned.m16n8k16.row.col.f32.f16.f16.f32 "
        "{%0,%1,%2,%3}, {%4,%5,%6,%7}, {%8,%9}, {%0,%1,%2,%3};"
        : "+f"(c[0]), "+f"(c[1]), "+f"(c[2]), "+f"(c[3])
        : "r"(a[0]), "r"(a[1]), "r"(a[2]), "r"(a[3]), "r"(b0), "r"(b1));
}
// bf16 MMA (kept for the hi/lo GEMMs)
__device__ __forceinline__ void mma16816(float* c, const uint32_t* a, uint32_t b0, uint32_t b1) {
    asm volatile(
        "mma.sync.aligned.m16n8k16.row.col.f32.bf16.bf16.f32 "
        "{%0,%1,%2,%3}, {%4,%5,%6,%7}, {%8,%9}, {%0,%1,%2,%3};"
        : "+f"(c[0]), "+f"(c[1]), "+f"(c[2]), "+f"(c[3])
        : "r"(a[0]), "r"(a[1]), "r"(a[2]), "r"(a[3]), "r"(b0), "r"(b1));
}
__device__ __forceinline__ void ldm_x4(uint32_t& r0, uint32_t& r1, uint32_t& r2, uint32_t& r3,
                                       uint32_t addr) {
    asm volatile("ldmatrix.sync.aligned.m8n8.x4.shared.b16 {%0,%1,%2,%3}, [%4];"
                 : "=r"(r0), "=r"(r1), "=r"(r2), "=r"(r3) : "r"(addr));
}
__device__ __forceinline__ void ldm_x4t(uint32_t& r0, uint32_t& r1, uint32_t& r2, uint32_t& r3,
                                        uint32_t addr) {
    asm volatile("ldmatrix.sync.aligned.m8n8.x4.trans.shared.b16 {%0,%1,%2,%3}, [%4];"
                 : "=r"(r0), "=r"(r1), "=r"(r2), "=r"(r3) : "r"(addr));
}
__device__ __forceinline__ void cp16(uint32_t dst, const void* src, uint32_t sz) {
    asm volatile("cp.async.cg.shared.global [%0], [%1], 16, %2;"
                 :: "r"(dst), "l"(src), "r"(sz) : "memory");
}
__device__ __forceinline__ uint32_t packbf(float a, float b) {
    __nv_bfloat162 v = __floats2bfloat162_rn(a, b);
    return *reinterpret_cast<uint32_t*>(&v);
}
__device__ __forceinline__ uint32_t packh(float a, float b) {
    __half2 v = __floats2half2_rn(a, b);
    return *reinterpret_cast<uint32_t*>(&v);
}
// bf16 hi/lo split (GEMM weights/activations)
__device__ __forceinline__ void split2(float2 v, uint32_t& hi, uint32_t& lo) {
    __nv_bfloat16 hx = __float2bfloat16(v.x), hy = __float2bfloat16(v.y);
    __nv_bfloat162 h2 = __nv_bfloat162(hx, hy);
    hi = *reinterpret_cast<uint32_t*>(&h2);
    lo = packbf(v.x - __bfloat162float(hx), v.y - __bfloat162float(hy));
}
// fp16 hi/lo split (attention operands)
__device__ __forceinline__ void split2h(float2 v, uint32_t& hi, uint32_t& lo) {
    __half hx = __float2half_rn(v.x), hy = __float2half_rn(v.y);
    __half2 h2 = __half2(hx, hy);
    hi = *reinterpret_cast<uint32_t*>(&h2);
    lo = packh(v.x - __half2float(hx), v.y - __half2float(hy));
}

// ---------------- graph preprocessing (both encoders merged) ----------------
__global__ void k_deg_init(int* deg, int* cnt) {
    int i = blockIdx.x * blockDim.x + threadIdx.x;
    if (i < 2 * N) { deg[i] = 1; cnt[i] = 0; }
}
__global__ void k_deg_count2(const int* __restrict__ col0, const int* __restrict__ col1,
                             int* deg) {
    int e = blockIdx.x * blockDim.x + threadIdx.x;
    int ei = blockIdx.y;
    const int* col = ei ? col1 : col0;
    if (e < E) atomicAdd(&deg[ei * N + col[e]], 1);
}
// scan + dinv fused; one block per encoder
__global__ void k_scan2(const int* __restrict__ degAll, int* __restrict__ offAll,
                        float* __restrict__ dinvAll) {
    int ei = blockIdx.x;
    const int* deg = degAll + ei * N;
    int* off = offAll + ei * (N + 1);
    float* dinv = dinvAll + ei * N;
    __shared__ int wsum[32];
    int tid = threadIdx.x, lane = tid & 31, wid = tid >> 5;
    const int C = (N + 1023) / 1024;          // 6
    int base = tid * C;
    int loc[C];
    int s = 0;
#pragma unroll
    for (int i = 0; i < C; i++) {
        int idx = base + i;
        loc[i] = (idx < N) ? deg[idx] : 0;
        if (idx < N) dinv[idx] = rsqrtf((float)loc[i]);
        s += loc[i];
    }
    int inc = s;
#pragma unroll
    for (int d = 1; d < 32; d <<= 1) {
        int v = __shfl_up_sync(0xffffffffu, inc, d);
        if (lane >= d) inc += v;
    }
    if (lane == 31) wsum[wid] = inc;
    __syncthreads();
    if (wid == 0) {
        int v = wsum[lane];
#pragma unroll
        for (int d = 1; d < 32; d <<= 1) {
            int u = __shfl_up_sync(0xffffffffu, v, d);
            if (lane >= d) v += u;
        }
        wsum[lane] = v;
    }
    __syncthreads();
    int run = inc - s + (wid > 0 ? wsum[wid - 1] : 0);
#pragma unroll
    for (int i = 0; i < C; i++) {
        int idx = base + i;
        if (idx < N) { off[idx] = run; run += loc[i]; }
    }
    if (tid == 1023) off[N] = run;
}
__global__ void k_fill2(const int* __restrict__ ed0, const int* __restrict__ ed1,
                        const int* __restrict__ offB, int* cntB,
                        const float* __restrict__ dinvB,
                        int* __restrict__ srcB, float* __restrict__ nrmB) {
    int e = blockIdx.x * blockDim.x + threadIdx.x;
    if (e >= EN) return;
    int ei = blockIdx.y;
    const int* edges = ei ? ed1 : ed0;
    const int* off  = offB + ei * (N + 1);
    int* cnt        = cntB + ei * N;
    const float* dinv = dinvB + ei * N;
    int* src        = srcB + (size_t)ei * EN;
    float* nrm      = nrmB + (size_t)ei * EN;
    int r, c;
    if (e < E) { r = edges[e]; c = edges[E + e]; }
    else       { r = c = e - E; }
    int pos = off[c] + atomicAdd(&cnt[c], 1);
    src[pos] = r;
    nrm[pos] = dinv[r] * dinv[c];
}

// ---------------- GCN input + aggregation ----------------
__global__ void k_in3_2(const float* __restrict__ x0, const float* __restrict__ x1,
                        const float* __restrict__ W0, const float* __restrict__ W1,
                        float* __restrict__ hwB) {
    int ei = blockIdx.y;
    const float* x = ei ? x1 : x0;
    const float* W = ei ? W1 : W0;
    int v = blockIdx.x, t = threadIdx.x;
    float a0 = x[v * 3 + 0], a1 = x[v * 3 + 1], a2 = x[v * 3 + 2];
    hwB[(size_t)ei * N * H + v * H + t] = a0 * W[t] + a1 * W[H + t] + a2 * W[2 * H + t];
}
// vectorized aggregate: 4 warps over neighbors, float4 per thread, smem reduce
__global__ void k_agg2v(const float* __restrict__ hwB, const int* __restrict__ offB,
                        const int* __restrict__ srcB, const float* __restrict__ nrmB,
                        const float* __restrict__ bias0, const float* __restrict__ bias1,
                        float* out0, int ldo0, float* out1, int ldo1,
                        __half* vb1) {
    __shared__ float4 part[4][32];
    int ei = blockIdx.y;
    const float4* hw4 = (const float4*)(hwB + (size_t)ei * N * H);
    const int*   off = offB + ei * (N + 1);
    const int*   src = srcB + (size_t)ei * EN;
    const float* nrm = nrmB + (size_t)ei * EN;
    int v = blockIdx.x, tid = threadIdx.x, w = tid >> 5, lane = tid & 31;
    int s = off[v], e = off[v + 1];
    float4 acc = make_float4(0.f, 0.f, 0.f, 0.f);
    for (int j = s + w; j < e; j += 4) {
        int   sj = __ldg(&src[j]);
        float nj = __ldg(&nrm[j]);
        float4 x = hw4[(size_t)sj * 32 + lane];
        acc.x += x.x * nj; acc.y += x.y * nj; acc.z += x.z * nj; acc.w += x.w * nj;
    }
    part[w][lane] = acc;
    __syncthreads();
    if (w == 0) {
        float4 a = part[0][lane], b = part[1][lane], c = part[2][lane], d = part[3][lane];
        const float* bias = ei ? bias1 : bias0;
        float4 bb = *(const float4*)(bias + lane * 4);
        float r0 = fmaxf(a.x + b.x + c.x + d.x + bb.x, 0.f);
        float r1 = fmaxf(a.y + b.y + c.y + d.y + bb.y, 0.f);
        float r2 = fmaxf(a.z + b.z + c.z + d.z + bb.z, 0.f);
        float r3 = fmaxf(a.w + b.w + c.w + d.w + bb.w, 0.f);
        float* out = ei ? out1 : out0;
        int ldo = ei ? ldo1 : ldo0;
        *(float4*)(out + (size_t)v * ldo + lane * 4) = make_float4(r0, r1, r2, r3);
        if (ei == 1 && vb1) {
            uint2 p = make_uint2(packh(r0, r1), packh(r2, r3));
            *(uint2*)((char*)vb1 + ((size_t)v * H + lane * 4) * 2) = p;
        }
    }
}

// ---------------- tensor-core GEMM (bf16 hi/lo, fp32-accurate) ----------------
#define RS2 136
#define WLOFF (128 * RS2 * 2)     // byte offset of Wl within smem
#define SMEM_TG (2 * 128 * RS2 * 2)   // 69632 B

// MODE 0: fp32 store (+optional relu). MODE 1: fp16 hi/lo split store (ld H), scaled.
template<int MODE>
__device__ __forceinline__ void tgemm_body(
    char* sm, const float* __restrict__ A, int lda,
    const float* __restrict__ W, const float* __restrict__ bias,
    int doRelu, int r0, float* out, int ldo,
    __half* oh, __half* ol, int K, float oscale) {
    const uint32_t sb = smem_u32(sm);
    const int tid = threadIdx.x;
    const int w = tid >> 5, lane = tid & 31;
    const int g = lane >> 2, t4 = lane & 3;
    const int jj = lane >> 3, rr = lane & 7;
    const int row_g = r0 + w * 16 + g;
    const int row_h = row_g + 8;
    const int rg = (row_g < N) ? row_g : (N - 1);
    const int rh = (row_h < N) ? row_h : (N - 1);

    float o[16][4];
#pragma unroll
    for (int i = 0; i < 16; i++)
#pragma unroll
        for (int j = 0; j < 4; j++) o[i][j] = 0.f;

    for (int kc0 = 0; kc0 < K; kc0 += 128) {
        if (kc0 > 0) __syncthreads();
        const float4* W4 = (const float4*)(W + (size_t)kc0 * 128);
        for (int i = tid; i < 128 * 32; i += 256) {
            int k = i >> 5, c4 = (i & 31) << 2;
            float4 wv = W4[i];
            uint32_t h0, l0, h1, l1;
            split2(make_float2(wv.x, wv.y), h0, l0);
            split2(make_float2(wv.z, wv.w), h1, l1);
            uint32_t off = (uint32_t)(k * RS2 + c4) * 2;
            *(uint2*)(sm + off)         = make_uint2(h0, h1);
            *(uint2*)(sm + WLOFF + off) = make_uint2(l0, l1);
        }
        __syncthreads();

        uint32_t ah[8][4], al[8][4];
#pragma unroll
        for (int kc = 0; kc < 8; kc++) {
            int c0 = kc0 + kc * 16 + 2 * t4;
            split2(*(const float2*)(A + (size_t)rg * lda + c0),     ah[kc][0], al[kc][0]);
            split2(*(const float2*)(A + (size_t)rh * lda + c0),     ah[kc][1], al[kc][1]);
            split2(*(const float2*)(A + (size_t)rg * lda + c0 + 8), ah[kc][2], al[kc][2]);
            split2(*(const float2*)(A + (size_t)rh * lda + c0 + 8), ah[kc][3], al[kc][3]);
        }

#pragma unroll
        for (int nb2 = 0; nb2 < 8; nb2++) {
#pragma unroll
            for (int kc = 0; kc < 8; kc++) {
                uint32_t addr = sb + (uint32_t)(((kc * 16 + ((jj & 1) << 3) + rr) * RS2 +
                                                nb2 * 16 + ((jj >> 1) << 3)) * 2);
                uint32_t b0, b1, b2, b3, d0, d1, d2, d3;
                ldm_x4t(b0, b1, b2, b3, addr);
                ldm_x4t(d0, d1, d2, d3, addr + WLOFF);
                mma16816(o[2 * nb2],     ah[kc], b0, b1);
                mma16816(o[2 * nb2 + 1], ah[kc], b2, b3);
                mma16816(o[2 * nb2],     al[kc], b0, b1);
                mma16816(o[2 * nb2 + 1], al[kc], b2, b3);
                mma16816(o[2 * nb2],     ah[kc], d0, d1);
                mma16816(o[2 * nb2 + 1], ah[kc], d2, d3);
            }
        }
    }

#pragma unroll
    for (int nb = 0; nb < 16; nb++) {
        int col = nb * 8 + 2 * t4;
        float2 bz = bias ? *(const float2*)(bias + col) : make_float2(0.f, 0.f);
        float v0 = o[nb][0] + bz.x, v1 = o[nb][1] + bz.y;
        float v2 = o[nb][2] + bz.x, v3 = o[nb][3] + bz.y;
        if (MODE == 0) {
            if (doRelu) {
                v0 = fmaxf(v0, 0.f); v1 = fmaxf(v1, 0.f);
                v2 = fmaxf(v2, 0.f); v3 = fmaxf(v3, 0.f);
            }
            if (row_g < N) *(float2*)(out + (size_t)row_g * ldo + col) = make_float2(v0, v1);
            if (row_h < N) *(float2*)(out + (size_t)row_h * ldo + col) = make_float2(v2, v3);
        } else {
            v0 *= oscale; v1 *= oscale; v2 *= oscale; v3 *= oscale;
            if (row_g < N) {
                uint32_t hi, lo;
                split2h(make_float2(v0, v1), hi, lo);
                *(uint32_t*)((char*)oh + ((size_t)row_g * H + col) * 2) = hi;
                if (ol) *(uint32_t*)((char*)ol + ((size_t)row_g * H + col) * 2) = lo;
            }
            if (row_h < N) {
                uint32_t hi, lo;
                split2h(make_float2(v2, v3), hi, lo);
                *(uint32_t*)((char*)oh + ((size_t)row_h * H + col) * 2) = hi;
                if (ol) *(uint32_t*)((char*)ol + ((size_t)row_h * H + col) * 2) = lo;
            }
        }
    }
}

__global__ __launch_bounds__(256)
void k_tg_gcn(const float* __restrict__ Abase,
              const float* __restrict__ W0, const float* __restrict__ W1,
              float* __restrict__ outbase) {
    extern __shared__ char sm[];
    int ei = blockIdx.y;
    tgemm_body<0>(sm, Abase + (size_t)ei * N * H, H, ei ? W1 : W0, nullptr, 0,
                  blockIdx.x * 128, outbase + (size_t)ei * N * H, H, nullptr, nullptr, H, 1.f);
}
// Q: fp16 hi+lo, scaled by log2e. K: single fp16.
__global__ __launch_bounds__(256)
void k_tg_proj(const float* __restrict__ catb, const float* __restrict__ xg,
               const float* __restrict__ Wa, const float* __restrict__ ba,
               __half* qh, __half* ql, __half* kf) {
    extern __shared__ char sm[];
    int head = blockIdx.y & 3, isK = blockIdx.y >> 2;
    tgemm_body<1>(sm, isK ? xg : catb, isK ? H : CATW, Wa + head * H * H, ba + head * H, 0,
                  blockIdx.x * 128, nullptr, 0,
                  (isK ? kf : qh) + (size_t)head * NP * H,
                  isK ? nullptr : (ql + (size_t)head * NP * H), H,
                  isK ? 1.f : LOG2E);
}
__global__ __launch_bounds__(256)
void k_tg(const float* __restrict__ A, int lda,
          const float* __restrict__ W, const float* __restrict__ bias,
          float* __restrict__ out, int K, int doRelu) {
    extern __shared__ char sm[];
    tgemm_body<0>(sm, A, lda, W, bias, doRelu, blockIdx.x * 128, out, H, nullptr, nullptr, K, 1.f);
}

// ---------------- fp16 mma.sync flash attention (KV-split, KVT=128) ----------------
#define QT  128
#define KVT 128
#define RS  136                   // smem row stride (fp16 elements) = 272B
#define BUFB (256 * RS * 2)       // kf(128) + v(128) rows = 69632 B
#define SMEM_FA (2 * BUFB)        // 139264 B

__global__ void __launch_bounds__(256, 1)
k_flash_mma(const __half* __restrict__ Qhi, const __half* __restrict__ Qlo,
            const __half* __restrict__ Kf, const __half* __restrict__ Vf) {
    extern __shared__ __half smfa[];
    const uint32_t sbase = smem_u32(smfa);
    const int tid = threadIdx.x;
    const int w = tid >> 5, lane = tid & 31;
    const int g = lane >> 2, t4 = lane & 3;
    const int head = blockIdx.y;
    const int split = blockIdx.z;
    const int r0 = blockIdx.x * QT;

    const __half* qhi = Qhi + (size_t)head * NP * H;
    const __half* qlo = Qlo + (size_t)head * NP * H;
    const __half* kf  = Kf  + (size_t)head * NP * H;

    const int row_g = r0 + w * 16 + g;
    const int row_h = row_g + 8;

    uint32_t qh[8][4], ql[8][4];
#pragma unroll
    for (int kc = 0; kc < 8; kc++) {
        int c0 = kc * 16 + 2 * t4;
        qh[kc][0] = *(const uint32_t*)(qhi + (size_t)row_g * H + c0);
        qh[kc][1] = *(const uint32_t*)(qhi + (size_t)row_h * H + c0);
        qh[kc][2] = *(const uint32_t*)(qhi + (size_t)row_g * H + c0 + 8);
        qh[kc][3] = *(const uint32_t*)(qhi + (size_t)row_h * H + c0 + 8);
        ql[kc][0] = *(const uint32_t*)(qlo + (size_t)row_g * H + c0);
        ql[kc][1] = *(const uint32_t*)(qlo + (size_t)row_h * H + c0);
        ql[kc][2] = *(const uint32_t*)(qlo + (size_t)row_g * H + c0 + 8);
        ql[kc][3] = *(const uint32_t*)(qlo + (size_t)row_h * H + c0 + 8);
    }

    float o[16][4];
#pragma unroll
    for (int i = 0; i < 16; i++)
#pragma unroll
        for (int j = 0; j < 4; j++) o[i][j] = 0.f;
    float m0 = -1e30f, m1 = -1e30f, l0 = 0.f, l1 = 0.f;

    const int NT = (N + KVT - 1) / KVT;                       // 47
    const int t_lo = (split == 0) ? 0 : (split == 1 ? 16 : 32);
    const int t_hi = (split == 0) ? 16 : (split == 1 ? 32 : NT);

    auto issue_load = [&](int tile, int b) {
        int c0 = tile * KVT;
        uint32_t dbase = sbase + (uint32_t)b * BUFB;
#pragma unroll 4
        for (int i = tid; i < 128 * 16; i += 256) {
            int r = i >> 4, s = i & 15;
            int gr = c0 + r;
            uint32_t sz = (gr < N) ? 16u : 0u;
            int grc = (gr < N) ? gr : (N - 1);
            uint32_t d0 = dbase + (uint32_t)(r * RS * 2 + s * 16);
            cp16(d0,                kf + (size_t)grc * H + s * 8, sz);
            cp16(d0 + 128 * RS * 2, Vf + (size_t)grc * H + s * 8, sz);
        }
        asm volatile("cp.async.commit_group;" ::: "memory");
    };

    issue_load(t_lo, 0);

    for (int t = t_lo; t < t_hi; t++) {
        int b = (t - t_lo) & 1;
        if (t + 1 < t_hi) {
            issue_load(t + 1, b ^ 1);
            asm volatile("cp.async.wait_group 1;" ::: "memory");
        } else {
            asm volatile("cp.async.wait_group 0;" ::: "memory");
        }
        __syncthreads();

        uint32_t kb = sbase + (uint32_t)b * BUFB;
        float c[16][4];
#pragma unroll
        for (int i = 0; i < 16; i++)
#pragma unroll
            for (int j = 0; j < 4; j++) c[i][j] = 0.f;

        const int jj = lane >> 3, rr = lane & 7;
#pragma unroll
        for (int nb2 = 0; nb2 < 8; nb2++) {
#pragma unroll
            for (int kc = 0; kc < 8; kc++) {
                uint32_t addr = kb + (uint32_t)(((nb2 * 16 + ((jj >> 1) << 3) + rr) * RS +
                                                kc * 16 + ((jj & 1) << 3)) * 2);
                uint32_t h0, h1, h2, h3;
                ldm_x4(h0, h1, h2, h3, addr);
                mma16816h(c[2 * nb2],     qh[kc], h0, h1);
                mma16816h(c[2 * nb2 + 1], qh[kc], h2, h3);
                mma16816h(c[2 * nb2],     ql[kc], h0, h1);
                mma16816h(c[2 * nb2 + 1], ql[kc], h2, h3);
            }
        }

        // ---- online softmax (base-2 logits) ----
        float tm0 = -1e30f, tm1 = -1e30f;
#pragma unroll
        for (int nb = 0; nb < 16; nb++) {
            tm0 = fmaxf(tm0, fmaxf(c[nb][0], c[nb][1]));
            tm1 = fmaxf(tm1, fmaxf(c[nb][2], c[nb][3]));
        }
        tm0 = fmaxf(tm0, __shfl_xor_sync(0xffffffffu, tm0, 1));
        tm0 = fmaxf(tm0, __shfl_xor_sync(0xffffffffu, tm0, 2));
        tm1 = fmaxf(tm1, __shfl_xor_sync(0xffffffffu, tm1, 1));
        tm1 = fmaxf(tm1, __shfl_xor_sync(0xffffffffu, tm1, 2));
        float mn0 = fmaxf(m0, tm0), mn1 = fmaxf(m1, tm1);
        float sc0 = ex2(m0 - mn0), sc1 = ex2(m1 - mn1);
        m0 = mn0; m1 = mn1;

        uint32_t pa[8][4];
        float rs0 = 0.f, rs1 = 0.f;
        const bool tail = (t == NT - 1);
        const int cc0 = t * KVT;
#pragma unroll
        for (int kc2 = 0; kc2 < 8; kc2++) {
            int nA = 2 * kc2, nB = nA + 1;
            float pA0 = ex2(c[nA][0] - mn0), pA1 = ex2(c[nA][1] - mn0);
            float pA2 = ex2(c[nA][2] - mn1), pA3 = ex2(c[nA][3] - mn1);
            float pB0 = ex2(c[nB][0] - mn0), pB1 = ex2(c[nB][1] - mn0);
            float pB2 = ex2(c[nB][2] - mn1), pB3 = ex2(c[nB][3] - mn1);
            if (tail) {
                int jA = cc0 + nA * 8 + 2 * t4, jB = cc0 + nB * 8 + 2 * t4;
                if (jA     >= N) { pA0 = 0.f; pA2 = 0.f; }
                if (jA + 1 >= N) { pA1 = 0.f; pA3 = 0.f; }
                if (jB     >= N) { pB0 = 0.f; pB2 = 0.f; }
                if (jB + 1 >= N) { pB1 = 0.f; pB3 = 0.f; }
            }
            rs0 += pA0 + pA1 + pB0 + pB1;
            rs1 += pA2 + pA3 + pB2 + pB3;
            pa[kc2][0] = packh(pA0, pA1);
            pa[kc2][1] = packh(pA2, pA3);
            pa[kc2][2] = packh(pB0, pB1);
            pa[kc2][3] = packh(pB2, pB3);
        }
        l0 = l0 * sc0 + rs0;
        l1 = l1 * sc1 + rs1;
#pragma unroll
        for (int i = 0; i < 16; i++) {
            o[i][0] *= sc0; o[i][1] *= sc0;
            o[i][2] *= sc1; o[i][3] *= sc1;
        }

        // ---- O += P @ V ----
        uint32_t vbb = kb + 128 * RS * 2;
#pragma unroll
        for (int nb2 = 0; nb2 < 8; nb2++) {
#pragma unroll
            for (int kc2 = 0; kc2 < 8; kc2++) {
                uint32_t addr = vbb + (uint32_t)(((kc2 * 16 + ((jj & 1) << 3) + rr) * RS +
                                                 nb2 * 16 + ((jj >> 1) << 3)) * 2);
                uint32_t v0, v1, v2, v3;
                ldm_x4t(v0, v1, v2, v3, addr);
                mma16816h(o[2 * nb2],     pa[kc2], v0, v1);
                mma16816h(o[2 * nb2 + 1], pa[kc2], v2, v3);
            }
        }
        __syncthreads();
    }

    l0 += __shfl_xor_sync(0xffffffffu, l0, 1);
    l0 += __shfl_xor_sync(0xffffffffu, l0, 2);
    l1 += __shfl_xor_sync(0xffffffffu, l1, 1);
    l1 += __shfl_xor_sync(0xffffffffu, l1, 2);

    size_t pbase = (size_t)(split * NHEADS + head) * NP;
    if (row_g < N) {
        float* p = g_po + (pbase + row_g) * H;
#pragma unroll
        for (int nb = 0; nb < 16; nb++)
            *(float2*)(p + nb * 8 + 2 * t4) = make_float2(o[nb][0], o[nb][1]);
        if (t4 == 0) { g_pm[pbase + row_g] = m0; g_pl[pbase + row_g] = l0; }
    }
    if (row_h < N) {
        float* p = g_po + (pbase + row_h) * H;
#pragma unroll
        for (int nb = 0; nb < 16; nb++)
            *(float2*)(p + nb * 8 + 2 * t4) = make_float2(o[nb][2], o[nb][3]);
        if (t4 == 0) { g_pm[pbase + row_h] = m1; g_pl[pbase + row_h] = l1; }
    }
}

// merge KV-split partials into cat (base-2 m values)
__global__ void k_combine(float* __restrict__ catb) {
    int row = blockIdx.x, head = blockIdx.y, t = threadIdx.x;
    size_t i0 = (size_t)(0 * NHEADS + head) * NP + row;
    size_t i1 = (size_t)(1 * NHEADS + head) * NP + row;
    size_t i2 = (size_t)(2 * NHEADS + head) * NP + row;
    float m0 = g_pm[i0], m1 = g_pm[i1], m2 = g_pm[i2];
    float mm = fmaxf(m0, fmaxf(m1, m2));
    float w0 = ex2(m0 - mm), w1 = ex2(m1 - mm), w2 = ex2(m2 - mm);
    float L = g_pl[i0] * w0 + g_pl[i1] * w1 + g_pl[i2] * w2;
    float v = (g_po[i0 * H + t] * w0 + g_po[i1 * H + t] * w1 + g_po[i2 * H + t] * w2) / L;
    catb[(size_t)row * CATW + H + head * H + t] = v;
}

// ---------------- output projection (128 -> 3) ----------------
__global__ void k_out3(const float* __restrict__ h, const float* __restrict__ W,
                       const float* __restrict__ b, float* __restrict__ out) {
    __shared__ float red[3][128];
    int v = blockIdx.x, t = threadIdx.x;
    float hv = h[v * H + t];
    red[0][t] = hv * W[t * 3 + 0];
    red[1][t] = hv * W[t * 3 + 1];
    red[2][t] = hv * W[t * 3 + 2];
    __syncthreads();
    for (int ofs = 64; ofs > 0; ofs >>= 1) {
        if (t < ofs) {
            red[0][t] += red[0][t + ofs];
            red[1][t] += red[1][t + ofs];
            red[2][t] += red[2][t + ofs];
        }
        __syncthreads();
    }
    if (t < 3) out[v * 3 + t] = red[t][0] + b[t];
}

// ---------------- host ----------------
static void* symAddr(const void* s) {
    void* p = nullptr;
    cudaGetSymbolAddress(&p, s);
    return p;
}

extern "C" void kernel_launch(void* const* d_in, const int* in_sizes, int n_in,
                              void* d_out, int out_size) {
    const float* x_resting = (const float*)d_in[0];
    const float* x_rigid   = (const float*)d_in[1];
    const int*   e_rest    = (const int*)d_in[2];
    const int*   e_rig     = (const int*)d_in[3];
    const float* Wr0 = (const float*)d_in[4];
    const float* br0 = (const float*)d_in[5];
    const float* Wr  = (const float*)d_in[6];
    const float* br  = (const float*)d_in[7];
    const float* Wg0 = (const float*)d_in[8];
    const float* bg0 = (const float*)d_in[9];
    const float* Wg  = (const float*)d_in[10];
    const float* bg  = (const float*)d_in[11];
    const float* Wa  = (const float*)d_in[12];
    const float* ba  = (const float*)d_in[13];
    const float* Wd0 = (const float*)d_in[14];
    const float* bd0 = (const float*)d_in[15];
    const float* Wd  = (const float*)d_in[16];
    const float* bd  = (const float*)d_in[17];
    const float* Wout= (const float*)d_in[18];
    const float* bout= (const float*)d_in[19];
    float* out = (float*)d_out;

    int*   degB = (int*)symAddr(g_deg);
    int*   offB = (int*)symAddr(g_off);
    int*   cntB = (int*)symAddr(g_cnt);
    int*   srcB = (int*)symAddr(g_src);
    float* nrmB = (float*)symAddr(g_nrm);
    float* dinvB= (float*)symAddr(g_dinv);
    float* hw   = (float*)symAddr(g_hw);
    float* ha   = (float*)symAddr(g_ha);
    float* hb   = (float*)symAddr(g_hb);
    float* xg   = (float*)symAddr(g_xg);
    float* cat  = (float*)symAddr(g_cat);
    float* d1   = (float*)symAddr(g_d1);
    float* d2   = (float*)symAddr(g_d2);
    __half* qhi = (__half*)symAddr(g_qhi);
    __half* qlo = (__half*)symAddr(g_qlo);
    __half* khf = (__half*)symAddr(g_khf);
    __half* vhf = (__half*)symAddr(g_vhf);

    const int TB = 256;
    const int GN2 = (2 * N + TB - 1) / TB;
    const int GE  = (E + TB - 1) / TB;
    const int GEN = (EN + TB - 1) / TB;
    const int GT  = (N + 127) / 128;  // 47

    cudaFuncSetAttribute(k_tg_gcn,  cudaFuncAttributeMaxDynamicSharedMemorySize, SMEM_TG);
    cudaFuncSetAttribute(k_tg_proj, cudaFuncAttributeMaxDynamicSharedMemorySize, SMEM_TG);
    cudaFuncSetAttribute(k_tg,      cudaFuncAttributeMaxDynamicSharedMemorySize, SMEM_TG);
    cudaFuncSetAttribute(k_flash_mma, cudaFuncAttributeMaxDynamicSharedMemorySize, SMEM_FA);

    // ------- graph prep, both encoders merged -------
    k_deg_init<<<GN2, TB>>>(degB, cntB);
    k_deg_count2<<<dim3(GE, 2), TB>>>(e_rest + E, e_rig + E, degB);
    k_scan2<<<2, 1024>>>(degB, offB, dinvB);
    k_fill2<<<dim3(GEN, 2), TB>>>(e_rest, e_rig, offB, cntB, dinvB, srcB, nrmB);

    // ------- GCN encoders, merged -------
    k_in3_2<<<dim3(N, 2), H>>>(x_resting, x_rigid, Wr0, Wg0, hw);
    k_agg2v<<<dim3(N, 2), 128>>>(hw, offB, srcB, nrmB, br0, bg0, ha, H, ha + N * H, H, nullptr);
    k_tg_gcn<<<dim3(GT, 2), 256, SMEM_TG>>>(ha, Wr, Wg, hw);
    k_agg2v<<<dim3(N, 2), 128>>>(hw, offB, srcB, nrmB, br, bg, hb, H, hb + N * H, H, nullptr);
    k_tg_gcn<<<dim3(GT, 2), 256, SMEM_TG>>>(hb, Wr + H * H, Wg + H * H, hw);
    k_agg2v<<<dim3(N, 2), 128>>>(hw, offB, srcB, nrmB, br + H, bg + H, cat, CATW, xg, H, vhf);

    // ------- attention projections (8 tensor GEMMs, fp16 epilogue) -------
    k_tg_proj<<<dim3(GT, 8), 256, SMEM_TG>>>(cat, xg, Wa, ba, qhi, qlo, khf);

    // ------- flash attention, 3-way KV split + combine -------
    k_flash_mma<<<dim3((N + QT - 1) / QT, NHEADS, NSPLIT), 256, SMEM_FA>>>(qhi, qlo, khf, vhf);
    k_combine<<<dim3(N, NHEADS), H>>>(cat);

    // ------- decoder (tensor GEMMs) -------
    k_tg<<<GT, 256, SMEM_TG>>>(cat, CATW, Wd0, bd0, d1, CATW, 1);
    k_tg<<<GT, 256, SMEM_TG>>>(d1, H, Wd, bd, d2, H, 1);
    k_tg<<<GT, 256, SMEM_TG>>>(d2, H, Wd + H * H, bd + H, d1, H, 1);
    k_out3<<<N, H>>>(d1, Wout, bout, out);
}

// round 16
// speedup vs baseline: 5.9523x; 1.1313x over previous
#include <cuda_runtime.h>
#include <cuda_bf16.h>
#include <cuda_fp16.h>
#include <math.h>
#include <stdint.h>

#define N 6000
#define NP 6016
#define E 192000
#define H 128
#define NHEADS 4
#define EN (E + N)
#define CATW (H * (NHEADS + 1))   // 640
#define NSPLIT 3
#define LOG2E 1.4426950408889634f

// ---------------- device scratch ----------------
__device__ int   g_deg[2][N];
__device__ int   g_off[2][N + 1];
__device__ int   g_cnt[2][N];
__device__ int   g_src[2][EN];
__device__ float g_nrm[2][EN];
__device__ float g_dinv[2][N];
__device__ __align__(16) float g_hw[2][N * H];
__device__ __align__(16) float g_ha[2][N * H];
__device__ __align__(16) float g_hb[2][N * H];
__device__ __align__(16) float g_xg[N * H];
__device__ __align__(16) float g_cat[N * CATW];
__device__ __align__(16) float g_d1[N * H];
__device__ __align__(16) float g_d2[N * H];
// fp16 attention operands (padded to NP rows; pads stay zero)
__device__ __align__(16) __half g_qhf[NHEADS * NP * H];
__device__ __align__(16) __half g_khf[NHEADS * NP * H];
__device__ __align__(16) __half g_vhf[NP * H];
// flash partials (KV-split)
__device__ __align__(16) float g_po[NSPLIT * NHEADS * NP * H];
__device__ float g_pm[NSPLIT * NHEADS * NP];
__device__ float g_pl[NSPLIT * NHEADS * NP];

// ---------------- small helpers ----------------
__device__ __forceinline__ uint32_t smem_u32(const void* p) {
    uint32_t a;
    asm("{ .reg .u64 t; cvta.to.shared.u64 t, %1; cvt.u32.u64 %0, t; }" : "=r"(a) : "l"(p));
    return a;
}
__device__ __forceinline__ float ex2(float x) {
    float y;
    asm("ex2.approx.f32 %0, %1;" : "=f"(y) : "f"(x));
    return y;
}
// fp16 MMA: D(f32) += A(f16) B(f16)
__device__ __forceinline__ void mma16816h(float* c, const uint32_t* a, uint32_t b0, uint32_t b1) {
    asm volatile(
        "mma.sync.aligned.m16n8k16.row.col.f32.f16.f16.f32 "
        "{%0,%1,%2,%3}, {%4,%5,%6,%7}, {%8,%9}, {%0,%1,%2,%3};"
        : "+f"(c[0]), "+f"(c[1]), "+f"(c[2]), "+f"(c[3])
        : "r"(a[0]), "r"(a[1]), "r"(a[2]), "r"(a[3]), "r"(b0), "r"(b1));
}
// bf16 MMA (hi/lo GEMMs)
__device__ __forceinline__ void mma16816(float* c, const uint32_t* a, uint32_t b0, uint32_t b1) {
    asm volatile(
        "mma.sync.aligned.m16n8k16.row.col.f32.bf16.bf16.f32 "
        "{%0,%1,%2,%3}, {%4,%5,%6,%7}, {%8,%9}, {%0,%1,%2,%3};"
        : "+f"(c[0]), "+f"(c[1]), "+f"(c[2]), "+f"(c[3])
        : "r"(a[0]), "r"(a[1]), "r"(a[2]), "r"(a[3]), "r"(b0), "r"(b1));
}
__device__ __forceinline__ void ldm_x4(uint32_t& r0, uint32_t& r1, uint32_t& r2, uint32_t& r3,
                                       uint32_t addr) {
    asm volatile("ldmatrix.sync.aligned.m8n8.x4.shared.b16 {%0,%1,%2,%3}, [%4];"
                 : "=r"(r0), "=r"(r1), "=r"(r2), "=r"(r3) : "r"(addr));
}
__device__ __forceinline__ void ldm_x4t(uint32_t& r0, uint32_t& r1, uint32_t& r2, uint32_t& r3,
                                        uint32_t addr) {
    asm volatile("ldmatrix.sync.aligned.m8n8.x4.trans.shared.b16 {%0,%1,%2,%3}, [%4];"
                 : "=r"(r0), "=r"(r1), "=r"(r2), "=r"(r3) : "r"(addr));
}
__device__ __forceinline__ void cp16(uint32_t dst, const void* src, uint32_t sz) {
    asm volatile("cp.async.cg.shared.global [%0], [%1], 16, %2;"
                 :: "r"(dst), "l"(src), "r"(sz) : "memory");
}
__device__ __forceinline__ uint32_t packbf(float a, float b) {
    __nv_bfloat162 v = __floats2bfloat162_rn(a, b);
    return *reinterpret_cast<uint32_t*>(&v);
}
__device__ __forceinline__ uint32_t packh(float a, float b) {
    __half2 v = __floats2half2_rn(a, b);
    return *reinterpret_cast<uint32_t*>(&v);
}
// bf16 hi/lo split (GEMM weights/activations)
__device__ __forceinline__ void split2(float2 v, uint32_t& hi, uint32_t& lo) {
    __nv_bfloat16 hx = __float2bfloat16(v.x), hy = __float2bfloat16(v.y);
    __nv_bfloat162 h2 = __nv_bfloat162(hx, hy);
    hi = *reinterpret_cast<uint32_t*>(&h2);
    lo = packbf(v.x - __bfloat162float(hx), v.y - __bfloat162float(hy));
}

// ---------------- graph preprocessing (both encoders merged) ----------------
__global__ void k_deg_init(int* deg, int* cnt) {
    int i = blockIdx.x * blockDim.x + threadIdx.x;
    if (i < 2 * N) { deg[i] = 1; cnt[i] = 0; }
}
__global__ void k_deg_count2(const int* __restrict__ col0, const int* __restrict__ col1,
                             int* deg) {
    int e = blockIdx.x * blockDim.x + threadIdx.x;
    int ei = blockIdx.y;
    const int* col = ei ? col1 : col0;
    if (e < E) atomicAdd(&deg[ei * N + col[e]], 1);
}
// scan + dinv fused; one block per encoder
__global__ void k_scan2(const int* __restrict__ degAll, int* __restrict__ offAll,
                        float* __restrict__ dinvAll) {
    int ei = blockIdx.x;
    const int* deg = degAll + ei * N;
    int* off = offAll + ei * (N + 1);
    float* dinv = dinvAll + ei * N;
    __shared__ int wsum[32];
    int tid = threadIdx.x, lane = tid & 31, wid = tid >> 5;
    const int C = (N + 1023) / 1024;          // 6
    int base = tid * C;
    int loc[C];
    int s = 0;
#pragma unroll
    for (int i = 0; i < C; i++) {
        int idx = base + i;
        loc[i] = (idx < N) ? deg[idx] : 0;
        if (idx < N) dinv[idx] = rsqrtf((float)loc[i]);
        s += loc[i];
    }
    int inc = s;
#pragma unroll
    for (int d = 1; d < 32; d <<= 1) {
        int v = __shfl_up_sync(0xffffffffu, inc, d);
        if (lane >= d) inc += v;
    }
    if (lane == 31) wsum[wid] = inc;
    __syncthreads();
    if (wid == 0) {
        int v = wsum[lane];
#pragma unroll
        for (int d = 1; d < 32; d <<= 1) {
            int u = __shfl_up_sync(0xffffffffu, v, d);
            if (lane >= d) v += u;
        }
        wsum[lane] = v;
    }
    __syncthreads();
    int run = inc - s + (wid > 0 ? wsum[wid - 1] : 0);
#pragma unroll
    for (int i = 0; i < C; i++) {
        int idx = base + i;
        if (idx < N) { off[idx] = run; run += loc[i]; }
    }
    if (tid == 1023) off[N] = run;
}
__global__ void k_fill2(const int* __restrict__ ed0, const int* __restrict__ ed1,
                        const int* __restrict__ offB, int* cntB,
                        const float* __restrict__ dinvB,
                        int* __restrict__ srcB, float* __restrict__ nrmB) {
    int e = blockIdx.x * blockDim.x + threadIdx.x;
    if (e >= EN) return;
    int ei = blockIdx.y;
    const int* edges = ei ? ed1 : ed0;
    const int* off  = offB + ei * (N + 1);
    int* cnt        = cntB + ei * N;
    const float* dinv = dinvB + ei * N;
    int* src        = srcB + (size_t)ei * EN;
    float* nrm      = nrmB + (size_t)ei * EN;
    int r, c;
    if (e < E) { r = edges[e]; c = edges[E + e]; }
    else       { r = c = e - E; }
    int pos = off[c] + atomicAdd(&cnt[c], 1);
    src[pos] = r;
    nrm[pos] = dinv[r] * dinv[c];
}

// ---------------- GCN input + aggregation ----------------
__global__ void k_in3_2(const float* __restrict__ x0, const float* __restrict__ x1,
                        const float* __restrict__ W0, const float* __restrict__ W1,
                        float* __restrict__ hwB) {
    int ei = blockIdx.y;
    const float* x = ei ? x1 : x0;
    const float* W = ei ? W1 : W0;
    int v = blockIdx.x, t = threadIdx.x;
    float a0 = x[v * 3 + 0], a1 = x[v * 3 + 1], a2 = x[v * 3 + 2];
    hwB[(size_t)ei * N * H + v * H + t] = a0 * W[t] + a1 * W[H + t] + a2 * W[2 * H + t];
}
// vectorized aggregate: 4 warps over neighbors, float4 per thread, smem reduce
__global__ void k_agg2v(const float* __restrict__ hwB, const int* __restrict__ offB,
                        const int* __restrict__ srcB, const float* __restrict__ nrmB,
                        const float* __restrict__ bias0, const float* __restrict__ bias1,
                        float* out0, int ldo0, float* out1, int ldo1,
                        __half* vb1) {
    __shared__ float4 part[4][32];
    int ei = blockIdx.y;
    const float4* hw4 = (const float4*)(hwB + (size_t)ei * N * H);
    const int*   off = offB + ei * (N + 1);
    const int*   src = srcB + (size_t)ei * EN;
    const float* nrm = nrmB + (size_t)ei * EN;
    int v = blockIdx.x, tid = threadIdx.x, w = tid >> 5, lane = tid & 31;
    int s = off[v], e = off[v + 1];
    float4 acc = make_float4(0.f, 0.f, 0.f, 0.f);
    for (int j = s + w; j < e; j += 4) {
        int   sj = __ldg(&src[j]);
        float nj = __ldg(&nrm[j]);
        float4 x = hw4[(size_t)sj * 32 + lane];
        acc.x += x.x * nj; acc.y += x.y * nj; acc.z += x.z * nj; acc.w += x.w * nj;
    }
    part[w][lane] = acc;
    __syncthreads();
    if (w == 0) {
        float4 a = part[0][lane], b = part[1][lane], c = part[2][lane], d = part[3][lane];
        const float* bias = ei ? bias1 : bias0;
        float4 bb = *(const float4*)(bias + lane * 4);
        float r0 = fmaxf(a.x + b.x + c.x + d.x + bb.x, 0.f);
        float r1 = fmaxf(a.y + b.y + c.y + d.y + bb.y, 0.f);
        float r2 = fmaxf(a.z + b.z + c.z + d.z + bb.z, 0.f);
        float r3 = fmaxf(a.w + b.w + c.w + d.w + bb.w, 0.f);
        float* out = ei ? out1 : out0;
        int ldo = ei ? ldo1 : ldo0;
        *(float4*)(out + (size_t)v * ldo + lane * 4) = make_float4(r0, r1, r2, r3);
        if (ei == 1 && vb1) {
            uint2 p = make_uint2(packh(r0, r1), packh(r2, r3));
            *(uint2*)((char*)vb1 + ((size_t)v * H + lane * 4) * 2) = p;
        }
    }
}

// ---------------- tensor-core GEMM (bf16 hi/lo, fp32-accurate) ----------------
#define RS2 136
#define WLOFF (128 * RS2 * 2)     // byte offset of Wl within smem
#define SMEM_TG (2 * 128 * RS2 * 2)   // 69632 B

// MODE 0: fp32 store (+optional relu). MODE 1: single-fp16 store (ld H), scaled.
template<int MODE>
__device__ __forceinline__ void tgemm_body(
    char* sm, const float* __restrict__ A, int lda,
    const float* __restrict__ W, const float* __restrict__ bias,
    int doRelu, int r0, float* out, int ldo,
    __half* oh, int K, float oscale) {
    const uint32_t sb = smem_u32(sm);
    const int tid = threadIdx.x;
    const int w = tid >> 5, lane = tid & 31;
    const int g = lane >> 2, t4 = lane & 3;
    const int jj = lane >> 3, rr = lane & 7;
    const int row_g = r0 + w * 16 + g;
    const int row_h = row_g + 8;
    const int rg = (row_g < N) ? row_g : (N - 1);
    const int rh = (row_h < N) ? row_h : (N - 1);

    float o[16][4];
#pragma unroll
    for (int i = 0; i < 16; i++)
#pragma unroll
        for (int j = 0; j < 4; j++) o[i][j] = 0.f;

    for (int kc0 = 0; kc0 < K; kc0 += 128) {
        if (kc0 > 0) __syncthreads();
        const float4* W4 = (const float4*)(W + (size_t)kc0 * 128);
        for (int i = tid; i < 128 * 32; i += 256) {
            int k = i >> 5, c4 = (i & 31) << 2;
            float4 wv = W4[i];
            uint32_t h0, l0, h1, l1;
            split2(make_float2(wv.x, wv.y), h0, l0);
            split2(make_float2(wv.z, wv.w), h1, l1);
            uint32_t off = (uint32_t)(k * RS2 + c4) * 2;
            *(uint2*)(sm + off)         = make_uint2(h0, h1);
            *(uint2*)(sm + WLOFF + off) = make_uint2(l0, l1);
        }
        __syncthreads();

        uint32_t ah[8][4], al[8][4];
#pragma unroll
        for (int kc = 0; kc < 8; kc++) {
            int c0 = kc0 + kc * 16 + 2 * t4;
            split2(*(const float2*)(A + (size_t)rg * lda + c0),     ah[kc][0], al[kc][0]);
            split2(*(const float2*)(A + (size_t)rh * lda + c0),     ah[kc][1], al[kc][1]);
            split2(*(const float2*)(A + (size_t)rg * lda + c0 + 8), ah[kc][2], al[kc][2]);
            split2(*(const float2*)(A + (size_t)rh * lda + c0 + 8), ah[kc][3], al[kc][3]);
        }

#pragma unroll
        for (int nb2 = 0; nb2 < 8; nb2++) {
#pragma unroll
            for (int kc = 0; kc < 8; kc++) {
                uint32_t addr = sb + (uint32_t)(((kc * 16 + ((jj & 1) << 3) + rr) * RS2 +
                                                nb2 * 16 + ((jj >> 1) << 3)) * 2);
                uint32_t b0, b1, b2, b3, d0, d1, d2, d3;
                ldm_x4t(b0, b1, b2, b3, addr);
                ldm_x4t(d0, d1, d2, d3, addr + WLOFF);
                mma16816(o[2 * nb2],     ah[kc], b0, b1);
                mma16816(o[2 * nb2 + 1], ah[kc], b2, b3);
                mma16816(o[2 * nb2],     al[kc], b0, b1);
                mma16816(o[2 * nb2 + 1], al[kc], b2, b3);
                mma16816(o[2 * nb2],     ah[kc], d0, d1);
                mma16816(o[2 * nb2 + 1], ah[kc], d2, d3);
            }
        }
    }

#pragma unroll
    for (int nb = 0; nb < 16; nb++) {
        int col = nb * 8 + 2 * t4;
        float2 bz = bias ? *(const float2*)(bias + col) : make_float2(0.f, 0.f);
        float v0 = o[nb][0] + bz.x, v1 = o[nb][1] + bz.y;
        float v2 = o[nb][2] + bz.x, v3 = o[nb][3] + bz.y;
        if (MODE == 0) {
            if (doRelu) {
                v0 = fmaxf(v0, 0.f); v1 = fmaxf(v1, 0.f);
                v2 = fmaxf(v2, 0.f); v3 = fmaxf(v3, 0.f);
            }
            if (row_g < N) *(float2*)(out + (size_t)row_g * ldo + col) = make_float2(v0, v1);
            if (row_h < N) *(float2*)(out + (size_t)row_h * ldo + col) = make_float2(v2, v3);
        } else {
            if (row_g < N)
                *(uint32_t*)((char*)oh + ((size_t)row_g * H + col) * 2) =
                    packh(v0 * oscale, v1 * oscale);
            if (row_h < N)
                *(uint32_t*)((char*)oh + ((size_t)row_h * H + col) * 2) =
                    packh(v2 * oscale, v3 * oscale);
        }
    }
}

__global__ __launch_bounds__(256)
void k_tg_gcn(const float* __restrict__ Abase,
              const float* __restrict__ W0, const float* __restrict__ W1,
              float* __restrict__ outbase) {
    extern __shared__ char sm[];
    int ei = blockIdx.y;
    tgemm_body<0>(sm, Abase + (size_t)ei * N * H, H, ei ? W1 : W0, nullptr, 0,
                  blockIdx.x * 128, outbase + (size_t)ei * N * H, H, nullptr, H, 1.f);
}
// Q: single fp16 scaled by log2e. K: single fp16.
__global__ __launch_bounds__(256)
void k_tg_proj(const float* __restrict__ catb, const float* __restrict__ xg,
               const float* __restrict__ Wa, const float* __restrict__ ba,
               __half* qf, __half* kf) {
    extern __shared__ char sm[];
    int head = blockIdx.y & 3, isK = blockIdx.y >> 2;
    tgemm_body<1>(sm, isK ? xg : catb, isK ? H : CATW, Wa + head * H * H, ba + head * H, 0,
                  blockIdx.x * 128, nullptr, 0,
                  (isK ? kf : qf) + (size_t)head * NP * H, H,
                  isK ? 1.f : LOG2E);
}
__global__ __launch_bounds__(256)
void k_tg(const float* __restrict__ A, int lda,
          const float* __restrict__ W, const float* __restrict__ bias,
          float* __restrict__ out, int K, int doRelu) {
    extern __shared__ char sm[];
    tgemm_body<0>(sm, A, lda, W, bias, doRelu, blockIdx.x * 128, out, H, nullptr, K, 1.f);
}

// ---------------- fp16 mma.sync flash attention (KV-split, KVT=128) ----------------
#define QT  128
#define KVT 128
#define RS  136                   // smem row stride (fp16 elements) = 272B
#define BUFB (256 * RS * 2)       // kf(128) + v(128) rows = 69632 B
#define SMEM_FA (2 * BUFB)        // 139264 B

__global__ void __launch_bounds__(256, 1)
k_flash_mma(const __half* __restrict__ Qf, const __half* __restrict__ Kf,
            const __half* __restrict__ Vf) {
    extern __shared__ __half smfa[];
    const uint32_t sbase = smem_u32(smfa);
    const int tid = threadIdx.x;
    const int w = tid >> 5, lane = tid & 31;
    const int g = lane >> 2, t4 = lane & 3;
    const int head = blockIdx.y;
    const int split = blockIdx.z;
    const int r0 = blockIdx.x * QT;

    const __half* qf = Qf + (size_t)head * NP * H;
    const __half* kf = Kf + (size_t)head * NP * H;

    const int row_g = r0 + w * 16 + g;
    const int row_h = row_g + 8;

    uint32_t qh[8][4];
#pragma unroll
    for (int kc = 0; kc < 8; kc++) {
        int c0 = kc * 16 + 2 * t4;
        qh[kc][0] = *(const uint32_t*)(qf + (size_t)row_g * H + c0);
        qh[kc][1] = *(const uint32_t*)(qf + (size_t)row_h * H + c0);
        qh[kc][2] = *(const uint32_t*)(qf + (size_t)row_g * H + c0 + 8);
        qh[kc][3] = *(const uint32_t*)(qf + (size_t)row_h * H + c0 + 8);
    }

    float o[16][4];
#pragma unroll
    for (int i = 0; i < 16; i++)
#pragma unroll
        for (int j = 0; j < 4; j++) o[i][j] = 0.f;
    float m0 = -1e30f, m1 = -1e30f, l0 = 0.f, l1 = 0.f;

    const int NT = (N + KVT - 1) / KVT;                       // 47
    const int t_lo = (split == 0) ? 0 : (split == 1 ? 16 : 32);
    const int t_hi = (split == 0) ? 16 : (split == 1 ? 32 : NT);

    auto issue_load = [&](int tile, int b) {
        int c0 = tile * KVT;
        uint32_t dbase = sbase + (uint32_t)b * BUFB;
#pragma unroll 4
        for (int i = tid; i < 128 * 16; i += 256) {
            int r = i >> 4, s = i & 15;
            int gr = c0 + r;
            uint32_t sz = (gr < N) ? 16u : 0u;
            int grc = (gr < N) ? gr : (N - 1);
            uint32_t d0 = dbase + (uint32_t)(r * RS * 2 + s * 16);
            cp16(d0,                kf + (size_t)grc * H + s * 8, sz);
            cp16(d0 + 128 * RS * 2, Vf + (size_t)grc * H + s * 8, sz);
        }
        asm volatile("cp.async.commit_group;" ::: "memory");
    };

    issue_load(t_lo, 0);

    for (int t = t_lo; t < t_hi; t++) {
        int b = (t - t_lo) & 1;
        if (t + 1 < t_hi) {
            issue_load(t + 1, b ^ 1);
            asm volatile("cp.async.wait_group 1;" ::: "memory");
        } else {
            asm volatile("cp.async.wait_group 0;" ::: "memory");
        }
        __syncthreads();

        uint32_t kb = sbase + (uint32_t)b * BUFB;
        float c[16][4];
#pragma unroll
        for (int i = 0; i < 16; i++)
#pragma unroll
            for (int j = 0; j < 4; j++) c[i][j] = 0.f;

        const int jj = lane >> 3, rr = lane & 7;
#pragma unroll
        for (int nb2 = 0; nb2 < 8; nb2++) {
#pragma unroll
            for (int kc = 0; kc < 8; kc++) {
                uint32_t addr = kb + (uint32_t)(((nb2 * 16 + ((jj >> 1) << 3) + rr) * RS +
                                                kc * 16 + ((jj & 1) << 3)) * 2);
                uint32_t h0, h1, h2, h3;
                ldm_x4(h0, h1, h2, h3, addr);
                mma16816h(c[2 * nb2],     qh[kc], h0, h1);
                mma16816h(c[2 * nb2 + 1], qh[kc], h2, h3);
            }
        }

        // ---- online softmax (base-2 logits) ----
        float tm0 = -1e30f, tm1 = -1e30f;
#pragma unroll
        for (int nb = 0; nb < 16; nb++) {
            tm0 = fmaxf(tm0, fmaxf(c[nb][0], c[nb][1]));
            tm1 = fmaxf(tm1, fmaxf(c[nb][2], c[nb][3]));
        }
        tm0 = fmaxf(tm0, __shfl_xor_sync(0xffffffffu, tm0, 1));
        tm0 = fmaxf(tm0, __shfl_xor_sync(0xffffffffu, tm0, 2));
        tm1 = fmaxf(tm1, __shfl_xor_sync(0xffffffffu, tm1, 1));
        tm1 = fmaxf(tm1, __shfl_xor_sync(0xffffffffu, tm1, 2));
        float mn0 = fmaxf(m0, tm0), mn1 = fmaxf(m1, tm1);
        float sc0 = ex2(m0 - mn0), sc1 = ex2(m1 - mn1);
        m0 = mn0; m1 = mn1;

        uint32_t pa[8][4];
        float rs0 = 0.f, rs1 = 0.f;
        const bool tail = (t == NT - 1);
        const int cc0 = t * KVT;
#pragma unroll
        for (int kc2 = 0; kc2 < 8; kc2++) {
            int nA = 2 * kc2, nB = nA + 1;
            float pA0 = ex2(c[nA][0] - mn0), pA1 = ex2(c[nA][1] - mn0);
            float pA2 = ex2(c[nA][2] - mn1), pA3 = ex2(c[nA][3] - mn1);
            float pB0 = ex2(c[nB][0] - mn0), pB1 = ex2(c[nB][1] - mn0);
            float pB2 = ex2(c[nB][2] - mn1), pB3 = ex2(c[nB][3] - mn1);
            if (tail) {
                int jA = cc0 + nA * 8 + 2 * t4, jB = cc0 + nB * 8 + 2 * t4;
                if (jA     >= N) { pA0 = 0.f; pA2 = 0.f; }
                if (jA + 1 >= N) { pA1 = 0.f; pA3 = 0.f; }
                if (jB     >= N) { pB0 = 0.f; pB2 = 0.f; }
                if (jB + 1 >= N) { pB1 = 0.f; pB3 = 0.f; }
            }
            rs0 += pA0 + pA1 + pB0 + pB1;
            rs1 += pA2 + pA3 + pB2 + pB3;
            pa[kc2][0] = packh(pA0, pA1);
            pa[kc2][1] = packh(pA2, pA3);
            pa[kc2][2] = packh(pB0, pB1);
            pa[kc2][3] = packh(pB2, pB3);
        }
        l0 = l0 * sc0 + rs0;
        l1 = l1 * sc1 + rs1;
#pragma unroll
        for (int i = 0; i < 16; i++) {
            o[i][0] *= sc0; o[i][1] *= sc0;
            o[i][2] *= sc1; o[i][3] *= sc1;
        }

        // ---- O += P @ V ----
        uint32_t vbb = kb + 128 * RS * 2;
#pragma unroll
        for (int nb2 = 0; nb2 < 8; nb2++) {
#pragma unroll
            for (int kc2 = 0; kc2 < 8; kc2++) {
                uint32_t addr = vbb + (uint32_t)(((kc2 * 16 + ((jj & 1) << 3) + rr) * RS +
                                                 nb2 * 16 + ((jj >> 1) << 3)) * 2);
                uint32_t v0, v1, v2, v3;
                ldm_x4t(v0, v1, v2, v3, addr);
                mma16816h(o[2 * nb2],     pa[kc2], v0, v1);
                mma16816h(o[2 * nb2 + 1], pa[kc2], v2, v3);
            }
        }
        __syncthreads();
    }

    l0 += __shfl_xor_sync(0xffffffffu, l0, 1);
    l0 += __shfl_xor_sync(0xffffffffu, l0, 2);
    l1 += __shfl_xor_sync(0xffffffffu, l1, 1);
    l1 += __shfl_xor_sync(0xffffffffu, l1, 2);

    size_t pbase = (size_t)(split * NHEADS + head) * NP;
    if (row_g < N) {
        float* p = g_po + (pbase + row_g) * H;
#pragma unroll
        for (int nb = 0; nb < 16; nb++)
            *(float2*)(p + nb * 8 + 2 * t4) = make_float2(o[nb][0], o[nb][1]);
        if (t4 == 0) { g_pm[pbase + row_g] = m0; g_pl[pbase + row_g] = l0; }
    }
    if (row_h < N) {
        float* p = g_po + (pbase + row_h) * H;
#pragma unroll
        for (int nb = 0; nb < 16; nb++)
            *(float2*)(p + nb * 8 + 2 * t4) = make_float2(o[nb][2], o[nb][3]);
        if (t4 == 0) { g_pm[pbase + row_h] = m1; g_pl[pbase + row_h] = l1; }
    }
}

// merge KV-split partials into cat (base-2 m values)
__global__ void k_combine(float* __restrict__ catb) {
    int row = blockIdx.x, head = blockIdx.y, t = threadIdx.x;
    size_t i0 = (size_t)(0 * NHEADS + head) * NP + row;
    size_t i1 = (size_t)(1 * NHEADS + head) * NP + row;
    size_t i2 = (size_t)(2 * NHEADS + head) * NP + row;
    float m0 = g_pm[i0], m1 = g_pm[i1], m2 = g_pm[i2];
    float mm = fmaxf(m0, fmaxf(m1, m2));
    float w0 = ex2(m0 - mm), w1 = ex2(m1 - mm), w2 = ex2(m2 - mm);
    float L = g_pl[i0] * w0 + g_pl[i1] * w1 + g_pl[i2] * w2;
    float v = (g_po[i0 * H + t] * w0 + g_po[i1 * H + t] * w1 + g_po[i2 * H + t] * w2) / L;
    catb[(size_t)row * CATW + H + head * H + t] = v;
}

// ---------------- output projection (128 -> 3) ----------------
__global__ void k_out3(const float* __restrict__ h, const float* __restrict__ W,
                       const float* __restrict__ b, float* __restrict__ out) {
    __shared__ float red[3][128];
    int v = blockIdx.x, t = threadIdx.x;
    float hv = h[v * H + t];
    red[0][t] = hv * W[t * 3 + 0];
    red[1][t] = hv * W[t * 3 + 1];
    red[2][t] = hv * W[t * 3 + 2];
    __syncthreads();
    for (int ofs = 64; ofs > 0; ofs >>= 1) {
        if (t < ofs) {
            red[0][t] += red[0][t + ofs];
            red[1][t] += red[1][t + ofs];
            red[2][t] += red[2][t + ofs];
        }
        __syncthreads();
    }
    if (t < 3) out[v * 3 + t] = red[t][0] + b[t];
}

// ---------------- host ----------------
static void* symAddr(const void* s) {
    void* p = nullptr;
    cudaGetSymbolAddress(&p, s);
    return p;
}

extern "C" void kernel_launch(void* const* d_in, const int* in_sizes, int n_in,
                              void* d_out, int out_size) {
    const float* x_resting = (const float*)d_in[0];
    const float* x_rigid   = (const float*)d_in[1];
    const int*   e_rest    = (const int*)d_in[2];
    const int*   e_rig     = (const int*)d_in[3];
    const float* Wr0 = (const float*)d_in[4];
    const float* br0 = (const float*)d_in[5];
    const float* Wr  = (const float*)d_in[6];
    const float* br  = (const float*)d_in[7];
    const float* Wg0 = (const float*)d_in[8];
    const float* bg0 = (const float*)d_in[9];
    const float* Wg  = (const float*)d_in[10];
    const float* bg  = (const float*)d_in[11];
    const float* Wa  = (const float*)d_in[12];
    const float* ba  = (const float*)d_in[13];
    const float* Wd0 = (const float*)d_in[14];
    const float* bd0 = (const float*)d_in[15];
    const float* Wd  = (const float*)d_in[16];
    const float* bd  = (const float*)d_in[17];
    const float* Wout= (const float*)d_in[18];
    const float* bout= (const float*)d_in[19];
    float* out = (float*)d_out;

    int*   degB = (int*)symAddr(g_deg);
    int*   offB = (int*)symAddr(g_off);
    int*   cntB = (int*)symAddr(g_cnt);
    int*   srcB = (int*)symAddr(g_src);
    float* nrmB = (float*)symAddr(g_nrm);
    float* dinvB= (float*)symAddr(g_dinv);
    float* hw   = (float*)symAddr(g_hw);
    float* ha   = (float*)symAddr(g_ha);
    float* hb   = (float*)symAddr(g_hb);
    float* xg   = (float*)symAddr(g_xg);
    float* cat  = (float*)symAddr(g_cat);
    float* d1   = (float*)symAddr(g_d1);
    float* d2   = (float*)symAddr(g_d2);
    __half* qhf = (__half*)symAddr(g_qhf);
    __half* khf = (__half*)symAddr(g_khf);
    __half* vhf = (__half*)symAddr(g_vhf);

    const int TB = 256;
    const int GN2 = (2 * N + TB - 1) / TB;
    const int GE  = (E + TB - 1) / TB;
    const int GEN = (EN + TB - 1) / TB;
    const int GT  = (N + 127) / 128;  // 47

    cudaFuncSetAttribute(k_tg_gcn,  cudaFuncAttributeMaxDynamicSharedMemorySize, SMEM_TG);
    cudaFuncSetAttribute(k_tg_proj, cudaFuncAttributeMaxDynamicSharedMemorySize, SMEM_TG);
    cudaFuncSetAttribute(k_tg,      cudaFuncAttributeMaxDynamicSharedMemorySize, SMEM_TG);
    cudaFuncSetAttribute(k_flash_mma, cudaFuncAttributeMaxDynamicSharedMemorySize, SMEM_FA);

    // ------- graph prep, both encoders merged -------
    k_deg_init<<<GN2, TB>>>(degB, cntB);
    k_deg_count2<<<dim3(GE, 2), TB>>>(e_rest + E, e_rig + E, degB);
    k_scan2<<<2, 1024>>>(degB, offB, dinvB);
    k_fill2<<<dim3(GEN, 2), TB>>>(e_rest, e_rig, offB, cntB, dinvB, srcB, nrmB);

    // ------- GCN encoders, merged -------
    k_in3_2<<<dim3(N, 2), H>>>(x_resting, x_rigid, Wr0, Wg0, hw);
    k_agg2v<<<dim3(N, 2), 128>>>(hw, offB, srcB, nrmB, br0, bg0, ha, H, ha + N * H, H, nullptr);
    k_tg_gcn<<<dim3(GT, 2), 256, SMEM_TG>>>(ha, Wr, Wg, hw);
    k_agg2v<<<dim3(N, 2), 128>>>(hw, offB, srcB, nrmB, br, bg, hb, H, hb + N * H, H, nullptr);
    k_tg_gcn<<<dim3(GT, 2), 256, SMEM_TG>>>(hb, Wr + H * H, Wg + H * H, hw);
    k_agg2v<<<dim3(N, 2), 128>>>(hw, offB, srcB, nrmB, br + H, bg + H, cat, CATW, xg, H, vhf);

    // ------- attention projections (8 tensor GEMMs, fp16 epilogue) -------
    k_tg_proj<<<dim3(GT, 8), 256, SMEM_TG>>>(cat, xg, Wa, ba, qhf, khf);

    // ------- flash attention, 3-way KV split + combine -------
    k_flash_mma<<<dim3((N + QT - 1) / QT, NHEADS, NSPLIT), 256, SMEM_FA>>>(qhf, khf, vhf);
    k_combine<<<dim3(N, NHEADS), H>>>(cat);

    // ------- decoder (tensor GEMMs) -------
    k_tg<<<GT, 256, SMEM_TG>>>(cat, CATW, Wd0, bd0, d1, CATW, 1);
    k_tg<<<GT, 256, SMEM_TG>>>(d1, H, Wd, bd, d2, H, 1);
    k_tg<<<GT, 256, SMEM_TG>>>(d2, H, Wd + H * H, bd + H, d1, H, 1);
    k_out3<<<N, H>>>(d1, Wout, bout, out);
}